// round 11
// baseline (speedup 1.0000x reference)
#include <cuda_runtime.h>
#include <cuda_bf16.h>
#include <math.h>
#include <stdint.h>

// Problem constants
#define BB 2
#define EE 160000
#define NN 10000
#define DD 128
#define TE 16

typedef unsigned long long u64;
typedef unsigned int u32;

// ---------------- scratch (device globals) ----------------
__device__ float g_edge_emb[(size_t)BB * EE * DD];
__device__ float g_nodeA[(size_t)BB * NN * DD];
__device__ float g_nodeB[(size_t)BB * NN * DD];
__device__ float g_s[(size_t)BB * 2 * EE];
__device__ float g_d[(size_t)BB * 2 * EE];   // per-edge attention dots, [b][round][e]
__device__ int   g_deg[NN];
__device__ int   g_off[NN + 1];
__device__ int   g_cursor[NN];
__device__ int   g_csr[2 * EE];
// decoder weights, transposed to [N,K] row-major, bf16 hi/mid split
__device__ __align__(16) __nv_bfloat16 g_w1t_hi[256 * 384];
__device__ __align__(16) __nv_bfloat16 g_w1t_mid[256 * 384];
__device__ __align__(16) __nv_bfloat16 g_w2t_hi[128 * 256];
__device__ __align__(16) __nv_bfloat16 g_w2t_mid[128 * 256];
// z1 activations, pre-split bf16 hi/mid: [B*E][256]
__device__ __align__(16) __nv_bfloat16 g_z1_hi[(size_t)BB * EE * 256];
__device__ __align__(16) __nv_bfloat16 g_z1_mid[(size_t)BB * EE * 256];

// ---------------- generic helpers ----------------
__device__ __forceinline__ float geluf(float x) { return x * normcdff(x); }

__device__ __forceinline__ u64 pack2(float lo, float hi) {
    u64 r; asm("mov.b64 %0, {%1, %2};" : "=l"(r) : "f"(lo), "f"(hi)); return r;
}
__device__ __forceinline__ u64 fma2(u64 a, u64 b, u64 c) {
    u64 d; asm("fma.rn.f32x2 %0, %1, %2, %3;" : "=l"(d) : "l"(a), "l"(b), "l"(c)); return d;
}
__device__ __forceinline__ float sum2(u64 v) {
    float lo, hi; asm("mov.b64 {%0, %1}, %2;" : "=f"(lo), "=f"(hi) : "l"(v)); return lo + hi;
}

__device__ __forceinline__ float brsum128(float v, float* red) {
    int lane = threadIdx.x & 31, w = threadIdx.x >> 5;
    #pragma unroll
    for (int o = 16; o; o >>= 1) v += __shfl_down_sync(0xffffffffu, v, o);
    if (lane == 0) red[w] = v;
    __syncthreads();
    float s = red[0] + red[1] + red[2] + red[3];
    __syncthreads();
    return s;
}
__device__ __forceinline__ float brmax128(float v, float* red) {
    int lane = threadIdx.x & 31, w = threadIdx.x >> 5;
    #pragma unroll
    for (int o = 16; o; o >>= 1) v = fmaxf(v, __shfl_down_sync(0xffffffffu, v, o));
    if (lane == 0) red[w] = v;
    __syncthreads();
    float s = fmaxf(fmaxf(red[0], red[1]), fmaxf(red[2], red[3]));
    __syncthreads();
    return s;
}

// ---------------- mma.sync / ldmatrix helpers ----------------
__device__ __forceinline__ u32 smem_u32(const void* p) {
    u32 a; asm("{ .reg .u64 t; cvta.to.shared.u64 t, %1; cvt.u32.u64 %0, t; }" : "=r"(a) : "l"(p));
    return a;
}
__device__ __forceinline__ void ldsm4(u32& r0, u32& r1, u32& r2, u32& r3, u32 addr) {
    asm volatile("ldmatrix.sync.aligned.m8n8.x4.shared.b16 {%0,%1,%2,%3}, [%4];"
        : "=r"(r0), "=r"(r1), "=r"(r2), "=r"(r3) : "r"(addr));
}
__device__ __forceinline__ void mma_bf16(float* d, u32 a0, u32 a1, u32 a2, u32 a3, u32 b0, u32 b1) {
    asm volatile("mma.sync.aligned.m16n8k16.row.col.f32.bf16.bf16.f32 "
        "{%0,%1,%2,%3}, {%4,%5,%6,%7}, {%8,%9}, {%0,%1,%2,%3};"
        : "+f"(d[0]), "+f"(d[1]), "+f"(d[2]), "+f"(d[3])
        : "r"(a0), "r"(a1), "r"(a2), "r"(a3), "r"(b0), "r"(b1));
}
#define STS64P(a, x, y) asm volatile("st.shared.v2.b32 [%0], {%1, %2};" :: "r"(a), "r"(x), "r"(y) : "memory")
#define STS128P(a, v)   asm volatile("st.shared.v4.b32 [%0], {%1, %2, %3, %4};" \
                            :: "r"(a), "r"((v).x), "r"((v).y), "r"((v).z), "r"((v).w) : "memory")
__device__ __forceinline__ u32 sw128(u32 off) { return off ^ ((off >> 3) & 0x70); }
__device__ __forceinline__ u32 packbf(__nv_bfloat16 a, __nv_bfloat16 b) {
    return ((u32)__bfloat16_as_ushort(b) << 16) | (u32)__bfloat16_as_ushort(a);
}

// ---------------- init ----------------
__global__ void k_zero_node_and_counts() {
    long i = (long)blockIdx.x * blockDim.x + threadIdx.x;
    long nNode = (long)BB * NN * DD;
    if (i < nNode) g_nodeA[i] = 0.0f;
    if (i < NN) { g_deg[i] = 0; g_cursor[i] = 0; }
}

// ---------------- CSR build ----------------
__global__ void k_count_deg(const int* __restrict__ src, const int* __restrict__ dst) {
    int i = blockIdx.x * blockDim.x + threadIdx.x;
    if (i < EE) {
        atomicAdd(&g_deg[src[i]], 1);
        atomicAdd(&g_deg[dst[i]], 1);
    }
}

__global__ void k_scan() {
    __shared__ int sums[1024];
    int t = threadIdx.x;
    const int chunk = (NN + 1023) / 1024;
    int start = t * chunk;
    int end = min(start + chunk, NN);
    int s = 0;
    for (int i = start; i < end; i++) s += g_deg[i];
    sums[t] = s;
    __syncthreads();
    for (int d = 1; d < 1024; d <<= 1) {
        int v = (t >= d) ? sums[t - d] : 0;
        __syncthreads();
        sums[t] += v;
        __syncthreads();
    }
    int run = (t > 0) ? sums[t - 1] : 0;
    for (int i = start; i < end; i++) { g_off[i] = run; run += g_deg[i]; }
    if (t == 1023) g_off[NN] = sums[1023];
}

__global__ void k_scatter(const int* __restrict__ src, const int* __restrict__ dst) {
    int p = blockIdx.x * blockDim.x + threadIdx.x;
    if (p < 2 * EE) {
        int node = (p < EE) ? src[p] : dst[p - EE];
        int pos = g_off[node] + atomicAdd(&g_cursor[node], 1);
        g_csr[pos] = p;
    }
}

// ---------------- decoder weight prep ----------------
__global__ void k_prep(const float* __restrict__ w1, const float* __restrict__ w2) {
    int i = blockIdx.x * blockDim.x + threadIdx.x;
    if (i < 256 * 384) {
        int n = i / 384, k = i - n * 384;
        float v = w1[(size_t)k * 256 + n];
        __nv_bfloat16 h = __float2bfloat16(v);
        g_w1t_hi[i] = h;
        g_w1t_mid[i] = __float2bfloat16(v - __bfloat162float(h));
    }
    if (i < 128 * 256) {
        int n = i / 256, k = i - n * 256;
        float v = w2[(size_t)k * 128 + n];
        __nv_bfloat16 h = __float2bfloat16(v);
        g_w2t_hi[i] = h;
        g_w2t_mid[i] = __float2bfloat16(v - __bfloat162float(h));
    }
}

// ---------------- encoder (f32x2, unchanged) ----------------
__global__ void __launch_bounds__(128) k_encoder(
    const float* __restrict__ feat,
    const float* __restrict__ w1, const float* __restrict__ b1,
    const float* __restrict__ g1, const float* __restrict__ be1,
    const float* __restrict__ w2, const float* __restrict__ b2,
    const float* __restrict__ g2, const float* __restrict__ be2) {
    __shared__ __align__(16) float xs[TE][24];
    __shared__ __align__(16) float hs[TE][DD];
    __shared__ __align__(16) float gs[TE][DD];

    long base = (long)blockIdx.x * TE;
    int tid = threadIdx.x, lane = tid & 31, w = tid >> 5;
    int d = tid;

    for (int i = tid; i < TE * 6; i += 128) {
        int t = i / 6, j = i % 6;
        ((float4*)xs[t])[j] = ((const float4*)(feat + (base + t) * 24))[j];
    }
    __syncthreads();

    {
        u64 wp[12];
        #pragma unroll
        for (int k = 0; k < 12; k++)
            wp[k] = pack2(w1[(2 * k) * DD + d], w1[(2 * k + 1) * DD + d]);
        float b1v = b1[d];
        #pragma unroll
        for (int t = 0; t < TE; t++) {
            u64 acc = pack2(b1v, 0.0f);
            #pragma unroll
            for (int j = 0; j < 6; j++) {
                ulonglong2 xv = ((const ulonglong2*)xs[t])[j];
                acc = fma2(xv.x, wp[2 * j], acc);
                acc = fma2(xv.y, wp[2 * j + 1], acc);
            }
            hs[t][d] = sum2(acc);
        }
    }
    __syncthreads();

    {
        float ga[4], bb[4];
        #pragma unroll
        for (int r = 0; r < 4; r++) { ga[r] = g1[lane + 32 * r]; bb[r] = be1[lane + 32 * r]; }
        #pragma unroll
        for (int tt = 0; tt < 4; tt++) {
            int t = w * 4 + tt;
            float v[4];
            #pragma unroll
            for (int r = 0; r < 4; r++) v[r] = hs[t][lane + 32 * r];
            float s = v[0] + v[1] + v[2] + v[3];
            #pragma unroll
            for (int o = 16; o; o >>= 1) s += __shfl_xor_sync(0xffffffffu, s, o);
            float mu = s * (1.0f / DD);
            float q = 0.0f;
            #pragma unroll
            for (int r = 0; r < 4; r++) { v[r] -= mu; q += v[r] * v[r]; }
            #pragma unroll
            for (int o = 16; o; o >>= 1) q += __shfl_xor_sync(0xffffffffu, q, o);
            float inv = rsqrtf(q * (1.0f / DD) + 1e-5f);
            #pragma unroll
            for (int r = 0; r < 4; r++)
                gs[t][lane + 32 * r] = geluf(v[r] * inv * ga[r] + bb[r]);
        }
    }
    __syncthreads();

    {
        float b2v = b2[d];
        u64 acc2[TE];
        #pragma unroll
        for (int t = 0; t < TE; t++) acc2[t] = pack2(b2v, 0.0f);
        for (int k = 0; k < DD; k += 4) {
            const float* wr = w2 + (size_t)k * DD;
            u64 w0 = pack2(wr[d], wr[DD + d]);
            u64 w1p = pack2(wr[2 * DD + d], wr[3 * DD + d]);
            #pragma unroll
            for (int t = 0; t < TE; t++) {
                ulonglong2 gv = *(const ulonglong2*)&gs[t][k];
                acc2[t] = fma2(gv.x, w0, acc2[t]);
                acc2[t] = fma2(gv.y, w1p, acc2[t]);
            }
        }
        __syncthreads();
        #pragma unroll
        for (int t = 0; t < TE; t++) hs[t][d] = sum2(acc2[t]);
    }
    __syncthreads();

    {
        float ga[4], bb[4];
        #pragma unroll
        for (int r = 0; r < 4; r++) { ga[r] = g2[lane + 32 * r]; bb[r] = be2[lane + 32 * r]; }
        #pragma unroll
        for (int tt = 0; tt < 4; tt++) {
            int t = w * 4 + tt;
            float v[4];
            #pragma unroll
            for (int r = 0; r < 4; r++) v[r] = hs[t][lane + 32 * r];
            float s = v[0] + v[1] + v[2] + v[3];
            #pragma unroll
            for (int o = 16; o; o >>= 1) s += __shfl_xor_sync(0xffffffffu, s, o);
            float mu = s * (1.0f / DD);
            float q = 0.0f;
            #pragma unroll
            for (int r = 0; r < 4; r++) { v[r] -= mu; q += v[r] * v[r]; }
            #pragma unroll
            for (int o = 16; o; o >>= 1) q += __shfl_xor_sync(0xffffffffu, q, o);
            float inv = rsqrtf(q * (1.0f / DD) + 1e-5f);
            float* orow = g_edge_emb + (base + t) * DD;
            #pragma unroll
            for (int r = 0; r < 4; r++)
                orow[lane + 32 * r] = v[r] * inv * ga[r] + bb[r];
        }
    }
}

// ---------------- per-edge attention dots for both rounds ----------------
__global__ void __launch_bounds__(256) k_edot(const float* __restrict__ watt1,
                                              const float* __restrict__ watt2) {
    int lane = threadIdx.x & 31;
    long gw = (long)blockIdx.x * 8 + (threadIdx.x >> 5);
    long nwarps = (long)gridDim.x * 8;
    float w1r[4], w2r[4];
    #pragma unroll
    for (int r = 0; r < 4; r++) {
        w1r[r] = watt1[128 + lane + 32 * r];
        w2r[r] = watt2[128 + lane + 32 * r];
    }
    for (long idx = gw; idx < (long)BB * EE; idx += nwarps) {
        const float* row = g_edge_emb + idx * DD;
        float v0 = row[lane], v1 = row[lane + 32], v2 = row[lane + 64], v3 = row[lane + 96];
        float d1 = fmaf(v0, w1r[0], fmaf(v1, w1r[1], fmaf(v2, w1r[2], v3 * w1r[3])));
        float d2 = fmaf(v0, w2r[0], fmaf(v1, w2r[1], fmaf(v2, w2r[2], v3 * w2r[3])));
        #pragma unroll
        for (int o = 16; o; o >>= 1) {
            d1 += __shfl_down_sync(0xffffffffu, d1, o);
            d2 += __shfl_down_sync(0xffffffffu, d2, o);
        }
        if (lane == 0) {
            long b = idx / EE, e = idx - b * EE;
            g_d[(b * 2 + 0) * EE + e] = d1;
            g_d[(b * 2 + 1) * EE + e] = d2;
        }
    }
}

// ---------------- message passing: exp-cached softmax, unrolled aggregation ----------------
__global__ void k_mp(const float* __restrict__ watt, const float* __restrict__ batt, int dir) {
    int n = blockIdx.x;
    int b = blockIdx.y;
    int tid = threadIdx.x;
    const float* nin  = (dir ? g_nodeB : g_nodeA) + (size_t)b * NN * DD;
    float*       nout = (dir ? g_nodeA : g_nodeB) + (size_t)b * NN * DD;
    const float* eemb = g_edge_emb + (size_t)b * EE * DD;
    const float* dvec = g_d + ((size_t)b * 2 + dir) * EE;
    float*       sb   = g_s + (size_t)b * 2 * EE;

    int cnt = g_deg[n];
    int start = g_off[n];
    float hval = nin[n * DD + tid];
    if (cnt == 0) { nout[n * DD + tid] = hval; return; }

    __shared__ float red[4];

    float c = brsum128(hval * watt[tid], red);
    float battv = batt[0];

    // pass 1: s per pair
    float lmax = -INFINITY;
    for (int i = tid; i < cnt; i += 128) {
        int p = g_csr[start + i];
        int e = (p < EE) ? p : p - EE;
        float s = c + dvec[e] + battv;
        s = (s > 0.0f) ? s : 0.2f * s;
        sb[start + i] = s;
        lmax = fmaxf(lmax, s);
    }
    float m = brmax128(lmax, red);   // barrier => sb visible

    // pass 2: denominator; overwrite sb with exp(s-m)
    float den = 0.0f;
    for (int i = tid; i < cnt; i += 128) {
        float ex = __expf(sb[start + i] - m);
        sb[start + i] = ex;
        den += ex;
    }
    den = brsum128(den, red);        // barrier => ex values visible
    float inv = 1.0f / den;

    // pass 3: weighted aggregation, unrolled x2 with dual accumulators
    float acc0 = 0.0f, acc1 = 0.0f;
    int i = 0;
    for (; i + 1 < cnt; i += 2) {
        int p0 = g_csr[start + i];
        int p1 = g_csr[start + i + 1];
        int ea = (p0 < EE) ? p0 : p0 - EE;
        int eb = (p1 < EE) ? p1 : p1 - EE;
        float wg0 = sb[start + i];
        float wg1 = sb[start + i + 1];
        acc0 = fmaf(wg0, eemb[(size_t)ea * DD + tid], acc0);
        acc1 = fmaf(wg1, eemb[(size_t)eb * DD + tid], acc1);
    }
    if (i < cnt) {
        int p = g_csr[start + i];
        int e = (p < EE) ? p : p - EE;
        acc0 = fmaf(sb[start + i], eemb[(size_t)e * DD + tid], acc0);
    }
    nout[n * DD + tid] = geluf((acc0 + acc1) * inv);
}

// ---------------- decoder stage 1 (EXACT R8 structure): z1 = gelu(cat @ W1 + b1) ----------------
__global__ void __launch_bounds__(256, 1) k_dec1(
    const int* __restrict__ src, const int* __restrict__ dst,
    const float* __restrict__ b1) {
    __shared__ __align__(16) __nv_bfloat16 sAh[8192];
    __shared__ __align__(16) __nv_bfloat16 sAm[8192];
    __shared__ __align__(16) __nv_bfloat16 sBh[2048];
    __shared__ __align__(16) __nv_bfloat16 sBm[2048];
    __shared__ float b1s[256];
    __shared__ int sidx[128], didx[128];

    const u32 Ah = smem_u32(sAh), Am = smem_u32(sAm);
    const u32 Bh = smem_u32(sBh), Bm = smem_u32(sBm);

    int tid = threadIdx.x, lane = tid & 31, warp = tid >> 5;
    int g = lane >> 2, tig = lane & 3;
    int wbase = warp * 16;

    long base = (long)blockIdx.x * 128;
    int b = (int)(base / EE);
    int e0 = (int)(base - (long)b * EE);
    size_t bNN = (size_t)b * NN;

    b1s[tid] = b1[tid];
    if (tid < 128) {
        sidx[tid] = src[e0 + tid];
        didx[tid] = dst[e0 + tid];
    }
    __syncthreads();

    const u32 aRow = (u32)(wbase + (lane & 15));
    const u32 aKH  = (u32)((lane >> 4) & 1) * 16;
    const u32 bRowInPair = (u32)(((lane >> 4) & 1) * 8 + (lane & 7));
    const u32 bKH  = (u32)((lane >> 3) & 1) * 16;
    const int bn = tid >> 3, bu = tid & 7;
    const u32 bSts = sw128((u32)(bn * 128 + bu * 16));

    float d1[128];
    #pragma unroll
    for (int i = 0; i < 128; i++) d1[i] = 0.0f;

    uint4 pvh, pvm;
    {
        size_t gidx = (size_t)bn * 384 + bu * 8;
        pvh = *(const uint4*)(g_w1t_hi + gidx);
        pvm = *(const uint4*)(g_w1t_mid + gidx);
    }

    for (int kc = 0; kc < 6; kc++) {
        for (int j = tid; j < 2048; j += 256) {
            int r = j >> 4, q = j & 15;
            const float* rp;
            int f4;
            if (kc < 2)      { rp = g_nodeA + (bNN + sidx[r]) * DD;              f4 = kc * 16 + q; }
            else if (kc < 4) { rp = g_nodeA + (bNN + didx[r]) * DD;              f4 = (kc - 2) * 16 + q; }
            else             { rp = g_edge_emb + ((size_t)b * EE + e0 + r) * DD; f4 = (kc - 4) * 16 + q; }
            float4 v = ((const float4*)rp)[f4];
            __nv_bfloat16 h0 = __float2bfloat16(v.x), h1 = __float2bfloat16(v.y);
            __nv_bfloat16 h2 = __float2bfloat16(v.z), h3 = __float2bfloat16(v.w);
            __nv_bfloat16 m0 = __float2bfloat16(v.x - __bfloat162float(h0));
            __nv_bfloat16 m1 = __float2bfloat16(v.y - __bfloat162float(h1));
            __nv_bfloat16 m2 = __float2bfloat16(v.z - __bfloat162float(h2));
            __nv_bfloat16 m3 = __float2bfloat16(v.w - __bfloat162float(h3));
            u32 off = sw128((u32)(r * 128 + q * 8));
            STS64P(Ah + off, packbf(h0, h1), packbf(h2, h3));
            STS64P(Am + off, packbf(m0, m1), packbf(m2, m3));
        }
        __syncthreads();   // A visible

        u32 af[4][8];
        #pragma unroll
        for (int kk = 0; kk < 4; kk++) {
            u32 aAddr = sw128((u32)(aRow * 128 + kk * 32) + aKH);
            ldsm4(af[kk][0], af[kk][1], af[kk][2], af[kk][3], Ah + aAddr);
            ldsm4(af[kk][4], af[kk][5], af[kk][6], af[kk][7], Am + aAddr);
        }

        #pragma unroll
        for (int ng = 0; ng < 8; ng++) {
            STS128P(Bh + bSts, pvh);
            STS128P(Bm + bSts, pvm);
            {
                int np = kc * 8 + ng + 1;
                if (np > 47) np = 47;
                int nkc = np >> 3, nng = np & 7;
                size_t gidx = (size_t)(nng * 32 + bn) * 384 + nkc * 64 + bu * 8;
                pvh = *(const uint4*)(g_w1t_hi + gidx);
                pvm = *(const uint4*)(g_w1t_mid + gidx);
            }
            __syncthreads();   // B visible
            #pragma unroll
            for (int kk = 0; kk < 4; kk++) {
                #pragma unroll
                for (int nt = 0; nt < 2; nt++) {
                    u32 bAddr = sw128((u32)((nt * 16 + bRowInPair) * 128 + kk * 32) + bKH);
                    u32 bh0, bh1, bh2, bh3, bm0, bm1, bm2, bm3;
                    ldsm4(bh0, bh1, bh2, bh3, Bh + bAddr);
                    ldsm4(bm0, bm1, bm2, bm3, Bm + bAddr);
                    float* dA = d1 + (ng * 4 + nt * 2) * 4;
                    float* dB = dA + 4;
                    mma_bf16(dA, af[kk][0], af[kk][1], af[kk][2], af[kk][3], bh0, bh1);
                    mma_bf16(dA, af[kk][4], af[kk][5], af[kk][6], af[kk][7], bh0, bh1);
                    mma_bf16(dA, af[kk][0], af[kk][1], af[kk][2], af[kk][3], bm0, bm1);
                    mma_bf16(dB, af[kk][0], af[kk][1], af[kk][2], af[kk][3], bh2, bh3);
                    mma_bf16(dB, af[kk][4], af[kk][5], af[kk][6], af[kk][7], bh2, bh3);
                    mma_bf16(dB, af[kk][0], af[kk][1], af[kk][2], af[kk][3], bm2, bm3);
                }
            }
            __syncthreads();   // readers done before next stores
        }
    }

    // epilogue: gelu(d1 + b1) -> g_z1 hi/mid
    long r0 = base + wbase + g;
    long r1 = r0 + 8;
    #pragma unroll
    for (int ti = 0; ti < 32; ti++) {
        int c0 = ti * 8 + tig * 2;
        float v0 = geluf(d1[ti * 4 + 0] + b1s[c0]);
        float v1 = geluf(d1[ti * 4 + 1] + b1s[c0 + 1]);
        float v2 = geluf(d1[ti * 4 + 2] + b1s[c0]);
        float v3 = geluf(d1[ti * 4 + 3] + b1s[c0 + 1]);
        __nv_bfloat16 h0 = __float2bfloat16(v0), h1 = __float2bfloat16(v1);
        __nv_bfloat16 h2 = __float2bfloat16(v2), h3 = __float2bfloat16(v3);
        __nv_bfloat16 m0 = __float2bfloat16(v0 - __bfloat162float(h0));
        __nv_bfloat16 m1 = __float2bfloat16(v1 - __bfloat162float(h1));
        __nv_bfloat16 m2 = __float2bfloat16(v2 - __bfloat162float(h2));
        __nv_bfloat16 m3 = __float2bfloat16(v3 - __bfloat162float(h3));
        *(u32*)(g_z1_hi  + r0 * 256 + c0) = packbf(h0, h1);
        *(u32*)(g_z1_mid + r0 * 256 + c0) = packbf(m0, m1);
        *(u32*)(g_z1_hi  + r1 * 256 + c0) = packbf(h2, h3);
        *(u32*)(g_z1_mid + r1 * 256 + c0) = packbf(m2, m3);
    }
}

// ---------------- decoder stage 2 (EXACT R8 structure) ----------------
__global__ void __launch_bounds__(256, 1) k_dec2(
    const float* __restrict__ b2, const float* __restrict__ w3,
    const float* __restrict__ b3, float* __restrict__ out) {
    __shared__ __align__(16) __nv_bfloat16 sAh[8192];
    __shared__ __align__(16) __nv_bfloat16 sAm[8192];
    __shared__ __align__(16) __nv_bfloat16 sBh[2048];
    __shared__ __align__(16) __nv_bfloat16 sBm[2048];
    __shared__ float b2s[128], w3s[128];

    const u32 Ah = smem_u32(sAh), Am = smem_u32(sAm);
    const u32 Bh = smem_u32(sBh), Bm = smem_u32(sBm);

    int tid = threadIdx.x, lane = tid & 31, warp = tid >> 5;
    int g = lane >> 2, tig = lane & 3;
    int wbase = warp * 16;
    long base = (long)blockIdx.x * 128;

    if (tid < 128) { b2s[tid] = b2[tid]; w3s[tid] = w3[tid]; }

    const u32 aRow = (u32)(wbase + (lane & 15));
    const u32 aKH  = (u32)((lane >> 4) & 1) * 16;
    const u32 bRowInPair = (u32)(((lane >> 4) & 1) * 8 + (lane & 7));
    const u32 bKH  = (u32)((lane >> 3) & 1) * 16;
    const int bn = tid >> 3, bu = tid & 7;
    const u32 bSts = sw128((u32)(bn * 128 + bu * 16));

    float d2[64];
    #pragma unroll
    for (int i = 0; i < 64; i++) d2[i] = 0.0f;

    uint4 pvh, pvm;
    {
        size_t gidx = (size_t)bn * 256 + bu * 8;
        pvh = *(const uint4*)(g_w2t_hi + gidx);
        pvm = *(const uint4*)(g_w2t_mid + gidx);
    }

    for (int kc = 0; kc < 4; kc++) {
        __syncthreads();
        for (int j = tid; j < 1024; j += 256) {
            int r = j >> 3, u = j & 7;
            size_t gidx = (size_t)(base + r) * 256 + kc * 64 + u * 8;
            uint4 vh = *(const uint4*)(g_z1_hi + gidx);
            uint4 vm = *(const uint4*)(g_z1_mid + gidx);
            u32 off = sw128((u32)(r * 128 + u * 16));
            STS128P(Ah + off, vh);
            STS128P(Am + off, vm);
        }
        __syncthreads();

        u32 af[4][8];
        #pragma unroll
        for (int kk = 0; kk < 4; kk++) {
            u32 aAddr = sw128((u32)(aRow * 128 + kk * 32) + aKH);
            ldsm4(af[kk][0], af[kk][1], af[kk][2], af[kk][3], Ah + aAddr);
            ldsm4(af[kk][4], af[kk][5], af[kk][6], af[kk][7], Am + aAddr);
        }

        #pragma unroll
        for (int ng = 0; ng < 4; ng++) {
            STS128P(Bh + bSts, pvh);
            STS128P(Bm + bSts, pvm);
            {
                int np = kc * 4 + ng + 1;
                if (np > 15) np = 15;
                int nkc = np >> 2, nng = np & 3;
                size_t gidx = (size_t)(nng * 32 + bn) * 256 + nkc * 64 + bu * 8;
                pvh = *(const uint4*)(g_w2t_hi + gidx);
                pvm = *(const uint4*)(g_w2t_mid + gidx);
            }
            __syncthreads();
            #pragma unroll
            for (int kk = 0; kk < 4; kk++) {
                #pragma unroll
                for (int nt = 0; nt < 2; nt++) {
                    u32 bAddr = sw128((u32)((nt * 16 + bRowInPair) * 128 + kk * 32) + bKH);
                    u32 bh0, bh1, bh2, bh3, bm0, bm1, bm2, bm3;
                    ldsm4(bh0, bh1, bh2, bh3, Bh + bAddr);
                    ldsm4(bm0, bm1, bm2, bm3, Bm + bAddr);
                    float* dA = d2 + (ng * 4 + nt * 2) * 4;
                    float* dB = dA + 4;
                    mma_bf16(dA, af[kk][0], af[kk][1], af[kk][2], af[kk][3], bh0, bh1);
                    mma_bf16(dA, af[kk][4], af[kk][5], af[kk][6], af[kk][7], bh0, bh1);
                    mma_bf16(dA, af[kk][0], af[kk][1], af[kk][2], af[kk][3], bm0, bm1);
                    mma_bf16(dB, af[kk][0], af[kk][1], af[kk][2], af[kk][3], bh2, bh3);
                    mma_bf16(dB, af[kk][4], af[kk][5], af[kk][6], af[kk][7], bh2, bh3);
                    mma_bf16(dB, af[kk][0], af[kk][1], af[kk][2], af[kk][3], bm2, bm3);
                }
            }
            __syncthreads();
        }
    }

    // z3
    float acc0 = 0.0f, acc1 = 0.0f;
    #pragma unroll
    for (int ti = 0; ti < 16; ti++) {
        int c0 = ti * 8 + tig * 2;
        float w0 = w3s[c0], w1v = w3s[c0 + 1];
        float bb0 = b2s[c0], bb1 = b2s[c0 + 1];
        acc0 = fmaf(geluf(d2[ti * 4 + 0] + bb0), w0, acc0);
        acc0 = fmaf(geluf(d2[ti * 4 + 1] + bb1), w1v, acc0);
        acc1 = fmaf(geluf(d2[ti * 4 + 2] + bb0), w0, acc1);
        acc1 = fmaf(geluf(d2[ti * 4 + 3] + bb1), w1v, acc1);
    }
    acc0 += __shfl_down_sync(0xffffffffu, acc0, 2, 4);
    acc0 += __shfl_down_sync(0xffffffffu, acc0, 1, 4);
    acc1 += __shfl_down_sync(0xffffffffu, acc1, 2, 4);
    acc1 += __shfl_down_sync(0xffffffffu, acc1, 1, 4);
    if (tig == 0) {
        float b3v = b3[0];
        out[base + wbase + g] = acc0 + b3v;
        out[base + wbase + g + 8] = acc1 + b3v;
    }
}

// ---------------- launch ----------------
extern "C" void kernel_launch(void* const* d_in, const int* in_sizes, int n_in,
                              void* d_out, int out_size) {
    const float* feat   = (const float*)d_in[0];
    const float* enc_w1 = (const float*)d_in[1];
    const float* enc_b1 = (const float*)d_in[2];
    const float* enc_g1 = (const float*)d_in[3];
    const float* enc_be1= (const float*)d_in[4];
    const float* enc_w2 = (const float*)d_in[5];
    const float* enc_b2 = (const float*)d_in[6];
    const float* enc_g2 = (const float*)d_in[7];
    const float* enc_be2= (const float*)d_in[8];
    const float* watt1  = (const float*)d_in[9];
    const float* batt1  = (const float*)d_in[10];
    const float* watt2  = (const float*)d_in[11];
    const float* batt2  = (const float*)d_in[12];
    const float* dec_w1 = (const float*)d_in[13];
    const float* dec_b1 = (const float*)d_in[14];
    const float* dec_w2 = (const float*)d_in[15];
    const float* dec_b2 = (const float*)d_in[16];
    const float* dec_w3 = (const float*)d_in[17];
    const float* dec_b3 = (const float*)d_in[18];
    const int*   src    = (const int*)d_in[19];
    const int*   dst    = (const int*)d_in[20];
    float* out = (float*)d_out;

    {
        long n = (long)BB * NN * DD;
        int blocks = (int)((n + 255) / 256);
        k_zero_node_and_counts<<<blocks, 256>>>();
    }

    k_prep<<<(256 * 384 + 255) / 256, 256>>>(dec_w1, dec_w2);

    // 3rd launch: CSR count (independent of encoder) so encoder is the
    // launch ncu profiles with -s 5.
    k_count_deg<<<(EE + 255) / 256, 256>>>(src, dst);

    k_encoder<<<(BB * EE) / TE, 128>>>(feat, enc_w1, enc_b1, enc_g1, enc_be1,
                                       enc_w2, enc_b2, enc_g2, enc_be2);

    k_scan<<<1, 1024>>>();
    k_scatter<<<(2 * EE + 255) / 256, 256>>>(src, dst);

    k_edot<<<1480, 256>>>(watt1, watt2);

    k_mp<<<dim3(NN, BB), DD>>>(watt1, batt1, 0);
    k_mp<<<dim3(NN, BB), DD>>>(watt2, batt2, 1);

    k_dec1<<<(BB * EE) / 128, 256>>>(src, dst, dec_b1);
    k_dec2<<<(BB * EE) / 128, 256>>>(dec_b2, dec_w3, dec_b3, out);
}

// round 12
// speedup vs baseline: 1.0163x; 1.0163x over previous
#include <cuda_runtime.h>
#include <cuda_bf16.h>
#include <math.h>
#include <stdint.h>

// Problem constants
#define BB 2
#define EE 160000
#define NN 10000
#define DD 128
#define TE 16

typedef unsigned long long u64;
typedef unsigned int u32;

// ---------------- scratch (device globals) ----------------
__device__ float g_edge_emb[(size_t)BB * EE * DD];
__device__ float g_nodeA[(size_t)BB * NN * DD];
__device__ float g_nodeB[(size_t)BB * NN * DD];
__device__ float g_s[(size_t)BB * 2 * EE];
__device__ float g_d[(size_t)BB * 2 * EE];
__device__ int   g_deg[NN];
__device__ int   g_off[NN + 1];
__device__ int   g_cursor[NN];
__device__ int   g_csr[2 * EE];
// decoder weights, transposed to [N,K] row-major, bf16 hi/mid split
__device__ __align__(16) __nv_bfloat16 g_w1t_hi[256 * 384];
__device__ __align__(16) __nv_bfloat16 g_w1t_mid[256 * 384];
__device__ __align__(16) __nv_bfloat16 g_w2t_hi[128 * 256];
__device__ __align__(16) __nv_bfloat16 g_w2t_mid[128 * 256];
// encoder layer-2 weights, transposed [N=128][K=128], bf16 hi/mid split
__device__ __align__(16) __nv_bfloat16 g_we2t_hi[128 * 128];
__device__ __align__(16) __nv_bfloat16 g_we2t_mid[128 * 128];
// z1 activations, pre-split bf16 hi/mid: [B*E][256]
__device__ __align__(16) __nv_bfloat16 g_z1_hi[(size_t)BB * EE * 256];
__device__ __align__(16) __nv_bfloat16 g_z1_mid[(size_t)BB * EE * 256];

// ---------------- generic helpers ----------------
__device__ __forceinline__ float geluf(float x) { return x * normcdff(x); }

__device__ __forceinline__ u64 pack2(float lo, float hi) {
    u64 r; asm("mov.b64 %0, {%1, %2};" : "=l"(r) : "f"(lo), "f"(hi)); return r;
}
__device__ __forceinline__ u64 fma2(u64 a, u64 b, u64 c) {
    u64 d; asm("fma.rn.f32x2 %0, %1, %2, %3;" : "=l"(d) : "l"(a), "l"(b), "l"(c)); return d;
}
__device__ __forceinline__ float sum2(u64 v) {
    float lo, hi; asm("mov.b64 {%0, %1}, %2;" : "=f"(lo), "=f"(hi) : "l"(v)); return lo + hi;
}

__device__ __forceinline__ float brsum128(float v, float* red) {
    int lane = threadIdx.x & 31, w = threadIdx.x >> 5;
    #pragma unroll
    for (int o = 16; o; o >>= 1) v += __shfl_down_sync(0xffffffffu, v, o);
    if (lane == 0) red[w] = v;
    __syncthreads();
    float s = red[0] + red[1] + red[2] + red[3];
    __syncthreads();
    return s;
}
__device__ __forceinline__ float brmax128(float v, float* red) {
    int lane = threadIdx.x & 31, w = threadIdx.x >> 5;
    #pragma unroll
    for (int o = 16; o; o >>= 1) v = fmaxf(v, __shfl_down_sync(0xffffffffu, v, o));
    if (lane == 0) red[w] = v;
    __syncthreads();
    float s = fmaxf(fmaxf(red[0], red[1]), fmaxf(red[2], red[3]));
    __syncthreads();
    return s;
}

// ---------------- mma.sync / ldmatrix helpers ----------------
__device__ __forceinline__ u32 smem_u32(const void* p) {
    u32 a; asm("{ .reg .u64 t; cvta.to.shared.u64 t, %1; cvt.u32.u64 %0, t; }" : "=r"(a) : "l"(p));
    return a;
}
__device__ __forceinline__ void ldsm4(u32& r0, u32& r1, u32& r2, u32& r3, u32 addr) {
    asm volatile("ldmatrix.sync.aligned.m8n8.x4.shared.b16 {%0,%1,%2,%3}, [%4];"
        : "=r"(r0), "=r"(r1), "=r"(r2), "=r"(r3) : "r"(addr));
}
__device__ __forceinline__ void mma_bf16(float* d, u32 a0, u32 a1, u32 a2, u32 a3, u32 b0, u32 b1) {
    asm volatile("mma.sync.aligned.m16n8k16.row.col.f32.bf16.bf16.f32 "
        "{%0,%1,%2,%3}, {%4,%5,%6,%7}, {%8,%9}, {%0,%1,%2,%3};"
        : "+f"(d[0]), "+f"(d[1]), "+f"(d[2]), "+f"(d[3])
        : "r"(a0), "r"(a1), "r"(a2), "r"(a3), "r"(b0), "r"(b1));
}
#define STS16(a, v)     asm volatile("st.shared.u16 [%0], %1;" :: "r"(a), "h"(v) : "memory")
#define STS64P(a, x, y) asm volatile("st.shared.v2.b32 [%0], {%1, %2};" :: "r"(a), "r"(x), "r"(y) : "memory")
#define STS128P(a, v)   asm volatile("st.shared.v4.b32 [%0], {%1, %2, %3, %4};" \
                            :: "r"(a), "r"((v).x), "r"((v).y), "r"((v).z), "r"((v).w) : "memory")
__device__ __forceinline__ u32 sw128(u32 off) { return off ^ ((off >> 3) & 0x70); }
__device__ __forceinline__ u32 packbf(__nv_bfloat16 a, __nv_bfloat16 b) {
    return ((u32)__bfloat16_as_ushort(b) << 16) | (u32)__bfloat16_as_ushort(a);
}

// ---------------- init ----------------
__global__ void k_zero_node_and_counts() {
    long i = (long)blockIdx.x * blockDim.x + threadIdx.x;
    long nNode = (long)BB * NN * DD;
    if (i < nNode) g_nodeA[i] = 0.0f;
    if (i < NN) { g_deg[i] = 0; g_cursor[i] = 0; }
}

// ---------------- CSR build ----------------
__global__ void k_count_deg(const int* __restrict__ src, const int* __restrict__ dst) {
    int i = blockIdx.x * blockDim.x + threadIdx.x;
    if (i < EE) {
        atomicAdd(&g_deg[src[i]], 1);
        atomicAdd(&g_deg[dst[i]], 1);
    }
}

__global__ void k_scan() {
    __shared__ int sums[1024];
    int t = threadIdx.x;
    const int chunk = (NN + 1023) / 1024;
    int start = t * chunk;
    int end = min(start + chunk, NN);
    int s = 0;
    for (int i = start; i < end; i++) s += g_deg[i];
    sums[t] = s;
    __syncthreads();
    for (int d = 1; d < 1024; d <<= 1) {
        int v = (t >= d) ? sums[t - d] : 0;
        __syncthreads();
        sums[t] += v;
        __syncthreads();
    }
    int run = (t > 0) ? sums[t - 1] : 0;
    for (int i = start; i < end; i++) { g_off[i] = run; run += g_deg[i]; }
    if (t == 1023) g_off[NN] = sums[1023];
}

__global__ void k_scatter(const int* __restrict__ src, const int* __restrict__ dst) {
    int p = blockIdx.x * blockDim.x + threadIdx.x;
    if (p < 2 * EE) {
        int node = (p < EE) ? src[p] : dst[p - EE];
        int pos = g_off[node] + atomicAdd(&g_cursor[node], 1);
        g_csr[pos] = p;
    }
}

// ---------------- weight prep: transpose + bf16 hi/mid split ----------------
__global__ void k_prep(const float* __restrict__ w1, const float* __restrict__ w2,
                       const float* __restrict__ we2) {
    int i = blockIdx.x * blockDim.x + threadIdx.x;
    if (i < 256 * 384) {
        int n = i / 384, k = i - n * 384;
        float v = w1[(size_t)k * 256 + n];
        __nv_bfloat16 h = __float2bfloat16(v);
        g_w1t_hi[i] = h;
        g_w1t_mid[i] = __float2bfloat16(v - __bfloat162float(h));
    }
    if (i < 128 * 256) {
        int n = i / 256, k = i - n * 256;
        float v = w2[(size_t)k * 128 + n];
        __nv_bfloat16 h = __float2bfloat16(v);
        g_w2t_hi[i] = h;
        g_w2t_mid[i] = __float2bfloat16(v - __bfloat162float(h));
    }
    if (i < 128 * 128) {
        int n = i / 128, k = i - n * 128;
        float v = we2[(size_t)k * 128 + n];
        __nv_bfloat16 h = __float2bfloat16(v);
        g_we2t_hi[i] = h;
        g_we2t_mid[i] = __float2bfloat16(v - __bfloat162float(h));
    }
}

// ---------------- encoder: layer1 scalar fp32 + layer2 on mma.sync bf16x3 ----------------
// 64 edges / CTA, 128 threads (4 warps). Clones k_dec2's mma skeleton.
// sA subtile kc (kc=0,1) holds cols [kc*64, kc*64+64) of gelu(LN1(...)), SW128.
__global__ void __launch_bounds__(128, 1) k_enc(
    const float* __restrict__ feat,
    const float* __restrict__ w1, const float* __restrict__ b1,
    const float* __restrict__ g1, const float* __restrict__ be1,
    const float* __restrict__ b2, const float* __restrict__ g2,
    const float* __restrict__ be2) {
    __shared__ __align__(16) __nv_bfloat16 sAh[8192];  // 2 subtiles x (64 rows x 64 cols)
    __shared__ __align__(16) __nv_bfloat16 sAm[8192];
    __shared__ __align__(16) __nv_bfloat16 sBh[2048];  // 32 n x 64 k
    __shared__ __align__(16) __nv_bfloat16 sBm[2048];
    __shared__ __align__(16) float xs[16][24];
    __shared__ float red[16][4][2];
    __shared__ float b2s[128], g2s[128], be2s[128];

    const u32 Ah = smem_u32(sAh), Am = smem_u32(sAm);
    const u32 Bh = smem_u32(sBh), Bm = smem_u32(sBm);

    int tid = threadIdx.x, lane = tid & 31, warp = tid >> 5;
    long base = (long)blockIdx.x * 64;   // global edge base (64 | EE)

    b2s[tid] = b2[tid];
    g2s[tid] = g2[tid];
    be2s[tid] = be2[tid];

    // layer1 column cache (thread owns col d = tid)
    int d = tid;
    u64 wp[12];
    #pragma unroll
    for (int k = 0; k < 12; k++)
        wp[k] = pack2(w1[(2 * k) * DD + d], w1[(2 * k + 1) * DD + d]);
    float b1v = b1[d], g1v = g1[d], be1v = be1[d];
    const u32 aSub = (u32)(d >> 6) * 8192;
    const u32 aCol2 = (u32)(d & 63) * 2;

    // ---------- phase 1: layer1 + LN1 + gelu -> sA planes ----------
    for (int it = 0; it < 4; it++) {
        __syncthreads();    // xs/red free
        for (int i = tid; i < 16 * 6; i += 128) {
            int t = i / 6, j = i % 6;
            ((float4*)xs[t])[j] = ((const float4*)(feat + (base + it * 16 + t) * 24))[j];
        }
        __syncthreads();

        float acc[16];
        #pragma unroll
        for (int t = 0; t < 16; t++) {
            u64 a = pack2(b1v, 0.0f);
            #pragma unroll
            for (int j = 0; j < 6; j++) {
                ulonglong2 xv = ((const ulonglong2*)xs[t])[j];
                a = fma2(xv.x, wp[2 * j], a);
                a = fma2(xv.y, wp[2 * j + 1], a);
            }
            acc[t] = sum2(a);
        }

        // per-edge sum & sumsq over 128 cols: warp partials -> red
        #pragma unroll
        for (int t = 0; t < 16; t++) {
            float s = acc[t], q = acc[t] * acc[t];
            #pragma unroll
            for (int o = 16; o; o >>= 1) {
                s += __shfl_down_sync(0xffffffffu, s, o);
                q += __shfl_down_sync(0xffffffffu, q, o);
            }
            if (lane == 0) { red[t][warp][0] = s; red[t][warp][1] = q; }
        }
        __syncthreads();

        #pragma unroll
        for (int t = 0; t < 16; t++) {
            float s = red[t][0][0] + red[t][1][0] + red[t][2][0] + red[t][3][0];
            float q = red[t][0][1] + red[t][1][1] + red[t][2][1] + red[t][3][1];
            float mu = s * (1.0f / DD);
            float var = q * (1.0f / DD) - mu * mu;
            float rstd = rsqrtf(var + 1e-5f);
            float v = geluf((acc[t] - mu) * rstd * g1v + be1v);
            __nv_bfloat16 h = __float2bfloat16(v);
            __nv_bfloat16 m = __float2bfloat16(v - __bfloat162float(h));
            u32 row = (u32)(it * 16 + t);
            u32 off = aSub + sw128(row * 128 + aCol2);
            STS16(Ah + off, __bfloat16_as_ushort(h));
            STS16(Am + off, __bfloat16_as_ushort(m));
        }
    }
    __syncthreads();   // sA complete

    // ---------- phase 2: mma (k_dec2 skeleton, 4 warps) ----------
    int g = lane >> 2, tig = lane & 3;
    int wbase = warp * 16;
    const u32 aRow = (u32)(wbase + (lane & 15));
    const u32 aKH  = (u32)((lane >> 4) & 1) * 16;
    const u32 bRowInPair = (u32)(((lane >> 4) & 1) * 8 + (lane & 7));
    const u32 bKH  = (u32)((lane >> 3) & 1) * 16;
    // B staging with 128 threads: thread covers n=tid>>2, u=(tid&3)*2 and u+1
    const int bn = tid >> 2, bu = (tid & 3) * 2;
    const u32 bSts0 = sw128((u32)(bn * 128 + bu * 16));
    const u32 bSts1 = sw128((u32)(bn * 128 + (bu + 1) * 16));

    float dd[64];
    #pragma unroll
    for (int i = 0; i < 64; i++) dd[i] = 0.0f;

    uint4 ph0, ph1, pm0, pm1;
    {
        size_t gi = (size_t)bn * 128 + bu * 8;
        ph0 = *(const uint4*)(g_we2t_hi + gi);
        ph1 = *(const uint4*)(g_we2t_hi + gi + 8);
        pm0 = *(const uint4*)(g_we2t_mid + gi);
        pm1 = *(const uint4*)(g_we2t_mid + gi + 8);
    }

    for (int kc = 0; kc < 2; kc++) {
        u32 af[4][8];
        #pragma unroll
        for (int kk = 0; kk < 4; kk++) {
            u32 aAddr = (u32)kc * 8192 + sw128((u32)(aRow * 128 + kk * 32) + aKH);
            ldsm4(af[kk][0], af[kk][1], af[kk][2], af[kk][3], Ah + aAddr);
            ldsm4(af[kk][4], af[kk][5], af[kk][6], af[kk][7], Am + aAddr);
        }

        #pragma unroll
        for (int ng = 0; ng < 4; ng++) {
            STS128P(Bh + bSts0, ph0);
            STS128P(Bh + bSts1, ph1);
            STS128P(Bm + bSts0, pm0);
            STS128P(Bm + bSts1, pm1);
            {
                int np = kc * 4 + ng + 1;
                if (np > 7) np = 7;
                int nkc = np >> 2, nng = np & 3;
                size_t gi = (size_t)(nng * 32 + bn) * 128 + nkc * 64 + bu * 8;
                ph0 = *(const uint4*)(g_we2t_hi + gi);
                ph1 = *(const uint4*)(g_we2t_hi + gi + 8);
                pm0 = *(const uint4*)(g_we2t_mid + gi);
                pm1 = *(const uint4*)(g_we2t_mid + gi + 8);
            }
            __syncthreads();   // B visible
            #pragma unroll
            for (int kk = 0; kk < 4; kk++) {
                #pragma unroll
                for (int nt = 0; nt < 2; nt++) {
                    u32 bAddr = sw128((u32)((nt * 16 + bRowInPair) * 128 + kk * 32) + bKH);
                    u32 bh0, bh1, bh2, bh3, bm0, bm1, bm2, bm3;
                    ldsm4(bh0, bh1, bh2, bh3, Bh + bAddr);
                    ldsm4(bm0, bm1, bm2, bm3, Bm + bAddr);
                    float* dA = dd + (ng * 4 + nt * 2) * 4;
                    float* dB = dA + 4;
                    mma_bf16(dA, af[kk][0], af[kk][1], af[kk][2], af[kk][3], bh0, bh1);
                    mma_bf16(dA, af[kk][4], af[kk][5], af[kk][6], af[kk][7], bh0, bh1);
                    mma_bf16(dA, af[kk][0], af[kk][1], af[kk][2], af[kk][3], bm0, bm1);
                    mma_bf16(dB, af[kk][0], af[kk][1], af[kk][2], af[kk][3], bh2, bh3);
                    mma_bf16(dB, af[kk][4], af[kk][5], af[kk][6], af[kk][7], bh2, bh3);
                    mma_bf16(dB, af[kk][0], af[kk][1], af[kk][2], af[kk][3], bm2, bm3);
                }
            }
            __syncthreads();   // B reads done before next stores
        }
    }

    // ---------- phase 3: + b2, LN2, store to g_edge_emb ----------
    float s0 = 0.0f, q0 = 0.0f, s1 = 0.0f, q1 = 0.0f;
    #pragma unroll
    for (int ti = 0; ti < 16; ti++) {
        int c0 = ti * 8 + tig * 2;
        float v0 = dd[ti * 4 + 0] + b2s[c0];
        float v1 = dd[ti * 4 + 1] + b2s[c0 + 1];
        float v2 = dd[ti * 4 + 2] + b2s[c0];
        float v3 = dd[ti * 4 + 3] + b2s[c0 + 1];
        dd[ti * 4 + 0] = v0; dd[ti * 4 + 1] = v1;
        dd[ti * 4 + 2] = v2; dd[ti * 4 + 3] = v3;
        s0 += v0 + v1; q0 += v0 * v0 + v1 * v1;
        s1 += v2 + v3; q1 += v2 * v2 + v3 * v3;
    }
    // reduce across the 4 lanes of the tig group (all end with total)
    #pragma unroll
    for (int o = 1; o < 4; o <<= 1) {
        s0 += __shfl_xor_sync(0xffffffffu, s0, o, 4);
        q0 += __shfl_xor_sync(0xffffffffu, q0, o, 4);
        s1 += __shfl_xor_sync(0xffffffffu, s1, o, 4);
        q1 += __shfl_xor_sync(0xffffffffu, q1, o, 4);
    }
    float mu0 = s0 * (1.0f / DD), mu1 = s1 * (1.0f / DD);
    float rs0 = rsqrtf(q0 * (1.0f / DD) - mu0 * mu0 + 1e-5f);
    float rs1 = rsqrtf(q1 * (1.0f / DD) - mu1 * mu1 + 1e-5f);
    float* o0 = g_edge_emb + (base + wbase + g) * DD;
    float* o1 = g_edge_emb + (base + wbase + g + 8) * DD;
    #pragma unroll
    for (int ti = 0; ti < 16; ti++) {
        int c0 = ti * 8 + tig * 2;
        float2 a, c;
        a.x = (dd[ti * 4 + 0] - mu0) * rs0 * g2s[c0]     + be2s[c0];
        a.y = (dd[ti * 4 + 1] - mu0) * rs0 * g2s[c0 + 1] + be2s[c0 + 1];
        c.x = (dd[ti * 4 + 2] - mu1) * rs1 * g2s[c0]     + be2s[c0];
        c.y = (dd[ti * 4 + 3] - mu1) * rs1 * g2s[c0 + 1] + be2s[c0 + 1];
        *(float2*)(o0 + c0) = a;
        *(float2*)(o1 + c0) = c;
    }
}

// ---------------- per-edge attention dots for both rounds ----------------
__global__ void __launch_bounds__(256) k_edot(const float* __restrict__ watt1,
                                              const float* __restrict__ watt2) {
    int lane = threadIdx.x & 31;
    long gw = (long)blockIdx.x * 8 + (threadIdx.x >> 5);
    long nwarps = (long)gridDim.x * 8;
    float w1r[4], w2r[4];
    #pragma unroll
    for (int r = 0; r < 4; r++) {
        w1r[r] = watt1[128 + lane + 32 * r];
        w2r[r] = watt2[128 + lane + 32 * r];
    }
    for (long idx = gw; idx < (long)BB * EE; idx += nwarps) {
        const float* row = g_edge_emb + idx * DD;
        float v0 = row[lane], v1 = row[lane + 32], v2 = row[lane + 64], v3 = row[lane + 96];
        float d1 = fmaf(v0, w1r[0], fmaf(v1, w1r[1], fmaf(v2, w1r[2], v3 * w1r[3])));
        float d2 = fmaf(v0, w2r[0], fmaf(v1, w2r[1], fmaf(v2, w2r[2], v3 * w2r[3])));
        #pragma unroll
        for (int o = 16; o; o >>= 1) {
            d1 += __shfl_down_sync(0xffffffffu, d1, o);
            d2 += __shfl_down_sync(0xffffffffu, d2, o);
        }
        if (lane == 0) {
            long b = idx / EE, e = idx - b * EE;
            g_d[(b * 2 + 0) * EE + e] = d1;
            g_d[(b * 2 + 1) * EE + e] = d2;
        }
    }
}

// ---------------- message passing ----------------
__global__ void k_mp(const float* __restrict__ watt, const float* __restrict__ batt, int dir) {
    int n = blockIdx.x;
    int b = blockIdx.y;
    int tid = threadIdx.x;
    const float* nin  = (dir ? g_nodeB : g_nodeA) + (size_t)b * NN * DD;
    float*       nout = (dir ? g_nodeA : g_nodeB) + (size_t)b * NN * DD;
    const float* eemb = g_edge_emb + (size_t)b * EE * DD;
    const float* dvec = g_d + ((size_t)b * 2 + dir) * EE;
    float*       sb   = g_s + (size_t)b * 2 * EE;

    int cnt = g_deg[n];
    int start = g_off[n];
    float hval = nin[n * DD + tid];
    if (cnt == 0) { nout[n * DD + tid] = hval; return; }

    __shared__ float red[4];

    float c = brsum128(hval * watt[tid], red);
    float battv = batt[0];

    float lmax = -INFINITY;
    for (int i = tid; i < cnt; i += 128) {
        int p = g_csr[start + i];
        int e = (p < EE) ? p : p - EE;
        float s = c + dvec[e] + battv;
        s = (s > 0.0f) ? s : 0.2f * s;
        sb[start + i] = s;
        lmax = fmaxf(lmax, s);
    }
    float m = brmax128(lmax, red);

    float den = 0.0f;
    for (int i = tid; i < cnt; i += 128) {
        float ex = __expf(sb[start + i] - m);
        sb[start + i] = ex;
        den += ex;
    }
    den = brsum128(den, red);
    float inv = 1.0f / den;

    float acc0 = 0.0f, acc1 = 0.0f;
    int i = 0;
    for (; i + 1 < cnt; i += 2) {
        int p0 = g_csr[start + i];
        int p1 = g_csr[start + i + 1];
        int ea = (p0 < EE) ? p0 : p0 - EE;
        int eb = (p1 < EE) ? p1 : p1 - EE;
        float wg0 = sb[start + i];
        float wg1 = sb[start + i + 1];
        acc0 = fmaf(wg0, eemb[(size_t)ea * DD + tid], acc0);
        acc1 = fmaf(wg1, eemb[(size_t)eb * DD + tid], acc1);
    }
    if (i < cnt) {
        int p = g_csr[start + i];
        int e = (p < EE) ? p : p - EE;
        acc0 = fmaf(sb[start + i], eemb[(size_t)e * DD + tid], acc0);
    }
    nout[n * DD + tid] = geluf((acc0 + acc1) * inv);
}

// ---------------- decoder stage 1 (EXACT R8 structure) ----------------
__global__ void __launch_bounds__(256, 1) k_dec1(
    const int* __restrict__ src, const int* __restrict__ dst,
    const float* __restrict__ b1) {
    __shared__ __align__(16) __nv_bfloat16 sAh[8192];
    __shared__ __align__(16) __nv_bfloat16 sAm[8192];
    __shared__ __align__(16) __nv_bfloat16 sBh[2048];
    __shared__ __align__(16) __nv_bfloat16 sBm[2048];
    __shared__ float b1s[256];
    __shared__ int sidx[128], didx[128];

    const u32 Ah = smem_u32(sAh), Am = smem_u32(sAm);
    const u32 Bh = smem_u32(sBh), Bm = smem_u32(sBm);

    int tid = threadIdx.x, lane = tid & 31, warp = tid >> 5;
    int g = lane >> 2, tig = lane & 3;
    int wbase = warp * 16;

    long base = (long)blockIdx.x * 128;
    int b = (int)(base / EE);
    int e0 = (int)(base - (long)b * EE);
    size_t bNN = (size_t)b * NN;

    b1s[tid] = b1[tid];
    if (tid < 128) {
        sidx[tid] = src[e0 + tid];
        didx[tid] = dst[e0 + tid];
    }
    __syncthreads();

    const u32 aRow = (u32)(wbase + (lane & 15));
    const u32 aKH  = (u32)((lane >> 4) & 1) * 16;
    const u32 bRowInPair = (u32)(((lane >> 4) & 1) * 8 + (lane & 7));
    const u32 bKH  = (u32)((lane >> 3) & 1) * 16;
    const int bn = tid >> 3, bu = tid & 7;
    const u32 bSts = sw128((u32)(bn * 128 + bu * 16));

    float d1[128];
    #pragma unroll
    for (int i = 0; i < 128; i++) d1[i] = 0.0f;

    uint4 pvh, pvm;
    {
        size_t gidx = (size_t)bn * 384 + bu * 8;
        pvh = *(const uint4*)(g_w1t_hi + gidx);
        pvm = *(const uint4*)(g_w1t_mid + gidx);
    }

    for (int kc = 0; kc < 6; kc++) {
        for (int j = tid; j < 2048; j += 256) {
            int r = j >> 4, q = j & 15;
            const float* rp;
            int f4;
            if (kc < 2)      { rp = g_nodeA + (bNN + sidx[r]) * DD;              f4 = kc * 16 + q; }
            else if (kc < 4) { rp = g_nodeA + (bNN + didx[r]) * DD;              f4 = (kc - 2) * 16 + q; }
            else             { rp = g_edge_emb + ((size_t)b * EE + e0 + r) * DD; f4 = (kc - 4) * 16 + q; }
            float4 v = ((const float4*)rp)[f4];
            __nv_bfloat16 h0 = __float2bfloat16(v.x), h1 = __float2bfloat16(v.y);
            __nv_bfloat16 h2 = __float2bfloat16(v.z), h3 = __float2bfloat16(v.w);
            __nv_bfloat16 m0 = __float2bfloat16(v.x - __bfloat162float(h0));
            __nv_bfloat16 m1 = __float2bfloat16(v.y - __bfloat162float(h1));
            __nv_bfloat16 m2 = __float2bfloat16(v.z - __bfloat162float(h2));
            __nv_bfloat16 m3 = __float2bfloat16(v.w - __bfloat162float(h3));
            u32 off = sw128((u32)(r * 128 + q * 8));
            STS64P(Ah + off, packbf(h0, h1), packbf(h2, h3));
            STS64P(Am + off, packbf(m0, m1), packbf(m2, m3));
        }
        __syncthreads();

        u32 af[4][8];
        #pragma unroll
        for (int kk = 0; kk < 4; kk++) {
            u32 aAddr = sw128((u32)(aRow * 128 + kk * 32) + aKH);
            ldsm4(af[kk][0], af[kk][1], af[kk][2], af[kk][3], Ah + aAddr);
            ldsm4(af[kk][4], af[kk][5], af[kk][6], af[kk][7], Am + aAddr);
        }

        #pragma unroll
        for (int ng = 0; ng < 8; ng++) {
            STS128P(Bh + bSts, pvh);
            STS128P(Bm + bSts, pvm);
            {
                int np = kc * 8 + ng + 1;
                if (np > 47) np = 47;
                int nkc = np >> 3, nng = np & 7;
                size_t gidx = (size_t)(nng * 32 + bn) * 384 + nkc * 64 + bu * 8;
                pvh = *(const uint4*)(g_w1t_hi + gidx);
                pvm = *(const uint4*)(g_w1t_mid + gidx);
            }
            __syncthreads();
            #pragma unroll
            for (int kk = 0; kk < 4; kk++) {
                #pragma unroll
                for (int nt = 0; nt < 2; nt++) {
                    u32 bAddr = sw128((u32)((nt * 16 + bRowInPair) * 128 + kk * 32) + bKH);
                    u32 bh0, bh1, bh2, bh3, bm0, bm1, bm2, bm3;
                    ldsm4(bh0, bh1, bh2, bh3, Bh + bAddr);
                    ldsm4(bm0, bm1, bm2, bm3, Bm + bAddr);
                    float* dA = d1 + (ng * 4 + nt * 2) * 4;
                    float* dB = dA + 4;
                    mma_bf16(dA, af[kk][0], af[kk][1], af[kk][2], af[kk][3], bh0, bh1);
                    mma_bf16(dA, af[kk][4], af[kk][5], af[kk][6], af[kk][7], bh0, bh1);
                    mma_bf16(dA, af[kk][0], af[kk][1], af[kk][2], af[kk][3], bm0, bm1);
                    mma_bf16(dB, af[kk][0], af[kk][1], af[kk][2], af[kk][3], bh2, bh3);
                    mma_bf16(dB, af[kk][4], af[kk][5], af[kk][6], af[kk][7], bh2, bh3);
                    mma_bf16(dB, af[kk][0], af[kk][1], af[kk][2], af[kk][3], bm2, bm3);
                }
            }
            __syncthreads();
        }
    }

    long r0 = base + wbase + g;
    long r1 = r0 + 8;
    #pragma unroll
    for (int ti = 0; ti < 32; ti++) {
        int c0 = ti * 8 + tig * 2;
        float v0 = geluf(d1[ti * 4 + 0] + b1s[c0]);
        float v1 = geluf(d1[ti * 4 + 1] + b1s[c0 + 1]);
        float v2 = geluf(d1[ti * 4 + 2] + b1s[c0]);
        float v3 = geluf(d1[ti * 4 + 3] + b1s[c0 + 1]);
        __nv_bfloat16 h0 = __float2bfloat16(v0), h1 = __float2bfloat16(v1);
        __nv_bfloat16 h2 = __float2bfloat16(v2), h3 = __float2bfloat16(v3);
        __nv_bfloat16 m0 = __float2bfloat16(v0 - __bfloat162float(h0));
        __nv_bfloat16 m1 = __float2bfloat16(v1 - __bfloat162float(h1));
        __nv_bfloat16 m2 = __float2bfloat16(v2 - __bfloat162float(h2));
        __nv_bfloat16 m3 = __float2bfloat16(v3 - __bfloat162float(h3));
        *(u32*)(g_z1_hi  + r0 * 256 + c0) = packbf(h0, h1);
        *(u32*)(g_z1_mid + r0 * 256 + c0) = packbf(m0, m1);
        *(u32*)(g_z1_hi  + r1 * 256 + c0) = packbf(h2, h3);
        *(u32*)(g_z1_mid + r1 * 256 + c0) = packbf(m2, m3);
    }
}

// ---------------- decoder stage 2 (EXACT R8 structure) ----------------
__global__ void __launch_bounds__(256, 1) k_dec2(
    const float* __restrict__ b2, const float* __restrict__ w3,
    const float* __restrict__ b3, float* __restrict__ out) {
    __shared__ __align__(16) __nv_bfloat16 sAh[8192];
    __shared__ __align__(16) __nv_bfloat16 sAm[8192];
    __shared__ __align__(16) __nv_bfloat16 sBh[2048];
    __shared__ __align__(16) __nv_bfloat16 sBm[2048];
    __shared__ float b2s[128], w3s[128];

    const u32 Ah = smem_u32(sAh), Am = smem_u32(sAm);
    const u32 Bh = smem_u32(sBh), Bm = smem_u32(sBm);

    int tid = threadIdx.x, lane = tid & 31, warp = tid >> 5;
    int g = lane >> 2, tig = lane & 3;
    int wbase = warp * 16;
    long base = (long)blockIdx.x * 128;

    if (tid < 128) { b2s[tid] = b2[tid]; w3s[tid] = w3[tid]; }

    const u32 aRow = (u32)(wbase + (lane & 15));
    const u32 aKH  = (u32)((lane >> 4) & 1) * 16;
    const u32 bRowInPair = (u32)(((lane >> 4) & 1) * 8 + (lane & 7));
    const u32 bKH  = (u32)((lane >> 3) & 1) * 16;
    const int bn = tid >> 3, bu = tid & 7;
    const u32 bSts = sw128((u32)(bn * 128 + bu * 16));

    float d2[64];
    #pragma unroll
    for (int i = 0; i < 64; i++) d2[i] = 0.0f;

    uint4 pvh, pvm;
    {
        size_t gidx = (size_t)bn * 256 + bu * 8;
        pvh = *(const uint4*)(g_w2t_hi + gidx);
        pvm = *(const uint4*)(g_w2t_mid + gidx);
    }

    for (int kc = 0; kc < 4; kc++) {
        __syncthreads();
        for (int j = tid; j < 1024; j += 256) {
            int r = j >> 3, u = j & 7;
            size_t gidx = (size_t)(base + r) * 256 + kc * 64 + u * 8;
            uint4 vh = *(const uint4*)(g_z1_hi + gidx);
            uint4 vm = *(const uint4*)(g_z1_mid + gidx);
            u32 off = sw128((u32)(r * 128 + u * 16));
            STS128P(Ah + off, vh);
            STS128P(Am + off, vm);
        }
        __syncthreads();

        u32 af[4][8];
        #pragma unroll
        for (int kk = 0; kk < 4; kk++) {
            u32 aAddr = sw128((u32)(aRow * 128 + kk * 32) + aKH);
            ldsm4(af[kk][0], af[kk][1], af[kk][2], af[kk][3], Ah + aAddr);
            ldsm4(af[kk][4], af[kk][5], af[kk][6], af[kk][7], Am + aAddr);
        }

        #pragma unroll
        for (int ng = 0; ng < 4; ng++) {
            STS128P(Bh + bSts, pvh);
            STS128P(Bm + bSts, pvm);
            {
                int np = kc * 4 + ng + 1;
                if (np > 15) np = 15;
                int nkc = np >> 2, nng = np & 3;
                size_t gidx = (size_t)(nng * 32 + bn) * 256 + nkc * 64 + bu * 8;
                pvh = *(const uint4*)(g_w2t_hi + gidx);
                pvm = *(const uint4*)(g_w2t_mid + gidx);
            }
            __syncthreads();
            #pragma unroll
            for (int kk = 0; kk < 4; kk++) {
                #pragma unroll
                for (int nt = 0; nt < 2; nt++) {
                    u32 bAddr = sw128((u32)((nt * 16 + bRowInPair) * 128 + kk * 32) + bKH);
                    u32 bh0, bh1, bh2, bh3, bm0, bm1, bm2, bm3;
                    ldsm4(bh0, bh1, bh2, bh3, Bh + bAddr);
                    ldsm4(bm0, bm1, bm2, bm3, Bm + bAddr);
                    float* dA = d2 + (ng * 4 + nt * 2) * 4;
                    float* dB = dA + 4;
                    mma_bf16(dA, af[kk][0], af[kk][1], af[kk][2], af[kk][3], bh0, bh1);
                    mma_bf16(dA, af[kk][4], af[kk][5], af[kk][6], af[kk][7], bh0, bh1);
                    mma_bf16(dA, af[kk][0], af[kk][1], af[kk][2], af[kk][3], bm0, bm1);
                    mma_bf16(dB, af[kk][0], af[kk][1], af[kk][2], af[kk][3], bh2, bh3);
                    mma_bf16(dB, af[kk][4], af[kk][5], af[kk][6], af[kk][7], bh2, bh3);
                    mma_bf16(dB, af[kk][0], af[kk][1], af[kk][2], af[kk][3], bm2, bm3);
                }
            }
            __syncthreads();
        }
    }

    float acc0 = 0.0f, acc1 = 0.0f;
    #pragma unroll
    for (int ti = 0; ti < 16; ti++) {
        int c0 = ti * 8 + tig * 2;
        float w0 = w3s[c0], w1v = w3s[c0 + 1];
        float bb0 = b2s[c0], bb1 = b2s[c0 + 1];
        acc0 = fmaf(geluf(d2[ti * 4 + 0] + bb0), w0, acc0);
        acc0 = fmaf(geluf(d2[ti * 4 + 1] + bb1), w1v, acc0);
        acc1 = fmaf(geluf(d2[ti * 4 + 2] + bb0), w0, acc1);
        acc1 = fmaf(geluf(d2[ti * 4 + 3] + bb1), w1v, acc1);
    }
    acc0 += __shfl_down_sync(0xffffffffu, acc0, 2, 4);
    acc0 += __shfl_down_sync(0xffffffffu, acc0, 1, 4);
    acc1 += __shfl_down_sync(0xffffffffu, acc1, 2, 4);
    acc1 += __shfl_down_sync(0xffffffffu, acc1, 1, 4);
    if (tig == 0) {
        float b3v = b3[0];
        out[base + wbase + g] = acc0 + b3v;
        out[base + wbase + g + 8] = acc1 + b3v;
    }
}

// ---------------- launch ----------------
extern "C" void kernel_launch(void* const* d_in, const int* in_sizes, int n_in,
                              void* d_out, int out_size) {
    const float* feat   = (const float*)d_in[0];
    const float* enc_w1 = (const float*)d_in[1];
    const float* enc_b1 = (const float*)d_in[2];
    const float* enc_g1 = (const float*)d_in[3];
    const float* enc_be1= (const float*)d_in[4];
    const float* enc_w2 = (const float*)d_in[5];
    const float* enc_b2 = (const float*)d_in[6];
    const float* enc_g2 = (const float*)d_in[7];
    const float* enc_be2= (const float*)d_in[8];
    const float* watt1  = (const float*)d_in[9];
    const float* batt1  = (const float*)d_in[10];
    const float* watt2  = (const float*)d_in[11];
    const float* batt2  = (const float*)d_in[12];
    const float* dec_w1 = (const float*)d_in[13];
    const float* dec_b1 = (const float*)d_in[14];
    const float* dec_w2 = (const float*)d_in[15];
    const float* dec_b2 = (const float*)d_in[16];
    const float* dec_w3 = (const float*)d_in[17];
    const float* dec_b3 = (const float*)d_in[18];
    const int*   src    = (const int*)d_in[19];
    const int*   dst    = (const int*)d_in[20];
    float* out = (float*)d_out;

    {
        long n = (long)BB * NN * DD;
        int blocks = (int)((n + 255) / 256);
        k_zero_node_and_counts<<<blocks, 256>>>();
    }

    k_prep<<<(256 * 384 + 255) / 256, 256>>>(dec_w1, dec_w2, enc_w2);

    k_count_deg<<<(EE + 255) / 256, 256>>>(src, dst);

    // 4th launch (ncu-profiled): the new tensor-core encoder
    k_enc<<<(BB * EE) / 64, 128>>>(feat, enc_w1, enc_b1, enc_g1, enc_be1,
                                   enc_b2, enc_g2, enc_be2);

    k_scan<<<1, 1024>>>();
    k_scatter<<<(2 * EE + 255) / 256, 256>>>(src, dst);

    k_edot<<<1480, 256>>>(watt1, watt2);

    k_mp<<<dim3(NN, BB), DD>>>(watt1, batt1, 0);
    k_mp<<<dim3(NN, BB), DD>>>(watt2, batt2, 1);

    k_dec1<<<(BB * EE) / 128, 256>>>(src, dst, dec_b1);
    k_dec2<<<(BB * EE) / 128, 256>>>(dec_b2, dec_w3, dec_b3, out);
}

// round 13
// speedup vs baseline: 1.0255x; 1.0090x over previous
#include <cuda_runtime.h>
#include <cuda_bf16.h>
#include <math.h>
#include <stdint.h>

// Problem constants
#define BB 2
#define EE 160000
#define NN 10000
#define DD 128
#define TE 16

typedef unsigned long long u64;
typedef unsigned int u32;

// ---------------- scratch (device globals) ----------------
__device__ float g_edge_emb[(size_t)BB * EE * DD];
__device__ float g_nodeA[(size_t)BB * NN * DD];
__device__ float g_nodeB[(size_t)BB * NN * DD];
__device__ float g_s[(size_t)BB * 2 * EE];
__device__ float g_d[(size_t)BB * 2 * EE];
__device__ int   g_deg[NN];
__device__ int   g_off[NN + 1];
__device__ int   g_cursor[NN];
__device__ int   g_csr[2 * EE];
// decoder weights, transposed to [N,K] row-major, bf16 hi/mid split
__device__ __align__(16) __nv_bfloat16 g_w1t_hi[256 * 384];
__device__ __align__(16) __nv_bfloat16 g_w1t_mid[256 * 384];
__device__ __align__(16) __nv_bfloat16 g_w2t_hi[128 * 256];
__device__ __align__(16) __nv_bfloat16 g_w2t_mid[128 * 256];
// encoder layer-2 weights, transposed [N=128][K=128], bf16 hi/mid split
__device__ __align__(16) __nv_bfloat16 g_we2t_hi[128 * 128];
__device__ __align__(16) __nv_bfloat16 g_we2t_mid[128 * 128];
// z1 activations, pre-split bf16 hi/mid: [B*E][256]
__device__ __align__(16) __nv_bfloat16 g_z1_hi[(size_t)BB * EE * 256];
__device__ __align__(16) __nv_bfloat16 g_z1_mid[(size_t)BB * EE * 256];

// ---------------- generic helpers ----------------
__device__ __forceinline__ float geluf(float x) { return x * normcdff(x); }

__device__ __forceinline__ u64 pack2(float lo, float hi) {
    u64 r; asm("mov.b64 %0, {%1, %2};" : "=l"(r) : "f"(lo), "f"(hi)); return r;
}
__device__ __forceinline__ u64 fma2(u64 a, u64 b, u64 c) {
    u64 d; asm("fma.rn.f32x2 %0, %1, %2, %3;" : "=l"(d) : "l"(a), "l"(b), "l"(c)); return d;
}
__device__ __forceinline__ float sum2(u64 v) {
    float lo, hi; asm("mov.b64 {%0, %1}, %2;" : "=f"(lo), "=f"(hi) : "l"(v)); return lo + hi;
}

__device__ __forceinline__ float brsum128(float v, float* red) {
    int lane = threadIdx.x & 31, w = threadIdx.x >> 5;
    #pragma unroll
    for (int o = 16; o; o >>= 1) v += __shfl_down_sync(0xffffffffu, v, o);
    if (lane == 0) red[w] = v;
    __syncthreads();
    float s = red[0] + red[1] + red[2] + red[3];
    __syncthreads();
    return s;
}
__device__ __forceinline__ float brmax128(float v, float* red) {
    int lane = threadIdx.x & 31, w = threadIdx.x >> 5;
    #pragma unroll
    for (int o = 16; o; o >>= 1) v = fmaxf(v, __shfl_down_sync(0xffffffffu, v, o));
    if (lane == 0) red[w] = v;
    __syncthreads();
    float s = fmaxf(fmaxf(red[0], red[1]), fmaxf(red[2], red[3]));
    __syncthreads();
    return s;
}

// ---------------- mma.sync / ldmatrix helpers ----------------
__device__ __forceinline__ u32 smem_u32(const void* p) {
    u32 a; asm("{ .reg .u64 t; cvta.to.shared.u64 t, %1; cvt.u32.u64 %0, t; }" : "=r"(a) : "l"(p));
    return a;
}
__device__ __forceinline__ void ldsm4(u32& r0, u32& r1, u32& r2, u32& r3, u32 addr) {
    asm volatile("ldmatrix.sync.aligned.m8n8.x4.shared.b16 {%0,%1,%2,%3}, [%4];"
        : "=r"(r0), "=r"(r1), "=r"(r2), "=r"(r3) : "r"(addr));
}
__device__ __forceinline__ void mma_bf16(float* d, u32 a0, u32 a1, u32 a2, u32 a3, u32 b0, u32 b1) {
    asm volatile("mma.sync.aligned.m16n8k16.row.col.f32.bf16.bf16.f32 "
        "{%0,%1,%2,%3}, {%4,%5,%6,%7}, {%8,%9}, {%0,%1,%2,%3};"
        : "+f"(d[0]), "+f"(d[1]), "+f"(d[2]), "+f"(d[3])
        : "r"(a0), "r"(a1), "r"(a2), "r"(a3), "r"(b0), "r"(b1));
}
#define STS16(a, v)     asm volatile("st.shared.u16 [%0], %1;" :: "r"(a), "h"(v) : "memory")
#define STS64P(a, x, y) asm volatile("st.shared.v2.b32 [%0], {%1, %2};" :: "r"(a), "r"(x), "r"(y) : "memory")
#define STS128P(a, v)   asm volatile("st.shared.v4.b32 [%0], {%1, %2, %3, %4};" \
                            :: "r"(a), "r"((v).x), "r"((v).y), "r"((v).z), "r"((v).w) : "memory")
__device__ __forceinline__ u32 sw128(u32 off) { return off ^ ((off >> 3) & 0x70); }
__device__ __forceinline__ u32 packbf(__nv_bfloat16 a, __nv_bfloat16 b) {
    return ((u32)__bfloat16_as_ushort(b) << 16) | (u32)__bfloat16_as_ushort(a);
}

// ---------------- init ----------------
__global__ void k_zero_node_and_counts() {
    long i = (long)blockIdx.x * blockDim.x + threadIdx.x;
    long nNode = (long)BB * NN * DD;
    if (i < nNode) g_nodeA[i] = 0.0f;
    if (i < NN) { g_deg[i] = 0; g_cursor[i] = 0; }
}

// ---------------- CSR build ----------------
__global__ void k_count_deg(const int* __restrict__ src, const int* __restrict__ dst) {
    int i = blockIdx.x * blockDim.x + threadIdx.x;
    if (i < EE) {
        atomicAdd(&g_deg[src[i]], 1);
        atomicAdd(&g_deg[dst[i]], 1);
    }
}

__global__ void k_scan() {
    __shared__ int sums[1024];
    int t = threadIdx.x;
    const int chunk = (NN + 1023) / 1024;
    int start = t * chunk;
    int end = min(start + chunk, NN);
    int s = 0;
    for (int i = start; i < end; i++) s += g_deg[i];
    sums[t] = s;
    __syncthreads();
    for (int d = 1; d < 1024; d <<= 1) {
        int v = (t >= d) ? sums[t - d] : 0;
        __syncthreads();
        sums[t] += v;
        __syncthreads();
    }
    int run = (t > 0) ? sums[t - 1] : 0;
    for (int i = start; i < end; i++) { g_off[i] = run; run += g_deg[i]; }
    if (t == 1023) g_off[NN] = sums[1023];
}

__global__ void k_scatter(const int* __restrict__ src, const int* __restrict__ dst) {
    int p = blockIdx.x * blockDim.x + threadIdx.x;
    if (p < 2 * EE) {
        int node = (p < EE) ? src[p] : dst[p - EE];
        int pos = g_off[node] + atomicAdd(&g_cursor[node], 1);
        g_csr[pos] = p;
    }
}

// ---------------- weight prep: transpose + bf16 hi/mid split ----------------
__global__ void k_prep(const float* __restrict__ w1, const float* __restrict__ w2,
                       const float* __restrict__ we2) {
    int i = blockIdx.x * blockDim.x + threadIdx.x;
    if (i < 256 * 384) {
        int n = i / 384, k = i - n * 384;
        float v = w1[(size_t)k * 256 + n];
        __nv_bfloat16 h = __float2bfloat16(v);
        g_w1t_hi[i] = h;
        g_w1t_mid[i] = __float2bfloat16(v - __bfloat162float(h));
    }
    if (i < 128 * 256) {
        int n = i / 256, k = i - n * 256;
        float v = w2[(size_t)k * 128 + n];
        __nv_bfloat16 h = __float2bfloat16(v);
        g_w2t_hi[i] = h;
        g_w2t_mid[i] = __float2bfloat16(v - __bfloat162float(h));
    }
    if (i < 128 * 128) {
        int n = i / 128, k = i - n * 128;
        float v = we2[(size_t)k * 128 + n];
        __nv_bfloat16 h = __float2bfloat16(v);
        g_we2t_hi[i] = h;
        g_we2t_mid[i] = __float2bfloat16(v - __bfloat162float(h));
    }
}

// ---------------- encoder: layer1 scalar fp32 + layer2 on mma.sync bf16x3 ----------------
// 64 edges / CTA, 128 threads. Phase 1 stages layer1 outputs through the idle
// B-staging smem and distributes LN across warps (2 edges/warp/iter).
__global__ void __launch_bounds__(128, 1) k_enc(
    const float* __restrict__ feat,
    const float* __restrict__ w1, const float* __restrict__ b1,
    const float* __restrict__ g1, const float* __restrict__ be1,
    const float* __restrict__ b2, const float* __restrict__ g2,
    const float* __restrict__ be2) {
    __shared__ __align__(16) __nv_bfloat16 sAh[8192];  // 2 subtiles x (64 rows x 64 cols)
    __shared__ __align__(16) __nv_bfloat16 sAm[8192];
    __shared__ __align__(16) __nv_bfloat16 sBh[2048];  // phase2 B staging; phase1 fs
    __shared__ __align__(16) __nv_bfloat16 sBm[2048];
    __shared__ __align__(16) float xs[8][24];
    __shared__ float b2s[128], g2s[128], be2s[128];
    __shared__ float g1s[128], be1s[128];

    const u32 Ah = smem_u32(sAh), Am = smem_u32(sAm);
    const u32 Bh = smem_u32(sBh), Bm = smem_u32(sBm);

    int tid = threadIdx.x, lane = tid & 31, warp = tid >> 5;
    long base = (long)blockIdx.x * 64;

    b2s[tid] = b2[tid];
    g2s[tid] = g2[tid];
    be2s[tid] = be2[tid];
    g1s[tid] = g1[tid];
    be1s[tid] = be1[tid];

    // layer1 column cache (thread owns col d = tid)
    int d = tid;
    u64 wp[12];
    #pragma unroll
    for (int k = 0; k < 12; k++)
        wp[k] = pack2(w1[(2 * k) * DD + d], w1[(2 * k + 1) * DD + d]);
    float b1v = b1[d];

    // ---------- phase 1: layer1 + LN1 + gelu -> sA planes (8 edges/iter) ----------
    float* fs = (float*)sBh;   // 4 KB = 1024 floats = 8 edges x 128 cols
    for (int it = 0; it < 8; it++) {
        __syncthreads();   // fs / xs free (covers initial smem fills too)
        for (int i = tid; i < 48; i += 128) {
            int t = i / 6, j = i % 6;
            ((float4*)xs[t])[j] = ((const float4*)(feat + (base + it * 8 + t) * 24))[j];
        }
        __syncthreads();

        float acc[8];
        #pragma unroll
        for (int t = 0; t < 8; t++) {
            u64 a = pack2(b1v, 0.0f);
            #pragma unroll
            for (int j = 0; j < 6; j++) {
                ulonglong2 xv = ((const ulonglong2*)xs[t])[j];
                a = fma2(xv.x, wp[2 * j], a);
                a = fma2(xv.y, wp[2 * j + 1], a);
            }
            acc[t] = sum2(a);
        }
        #pragma unroll
        for (int t = 0; t < 8; t++) fs[t * 128 + d] = acc[t];
        __syncthreads();

        // warp w normalizes edges w*2, w*2+1
        #pragma unroll
        for (int tt = 0; tt < 2; tt++) {
            int t = warp * 2 + tt;
            float v[4];
            #pragma unroll
            for (int r = 0; r < 4; r++) v[r] = fs[t * 128 + lane + 32 * r];
            float s = v[0] + v[1] + v[2] + v[3];
            float q = v[0] * v[0] + v[1] * v[1] + v[2] * v[2] + v[3] * v[3];
            #pragma unroll
            for (int o = 16; o; o >>= 1) {
                s += __shfl_xor_sync(0xffffffffu, s, o);
                q += __shfl_xor_sync(0xffffffffu, q, o);
            }
            float mu = s * (1.0f / DD);
            float rstd = rsqrtf(q * (1.0f / DD) - mu * mu + 1e-5f);
            u32 row = (u32)(it * 8 + t);
            #pragma unroll
            for (int r = 0; r < 4; r++) {
                int c = lane + 32 * r;
                float vv = geluf((v[r] - mu) * rstd * g1s[c] + be1s[c]);
                __nv_bfloat16 h = __float2bfloat16(vv);
                __nv_bfloat16 m = __float2bfloat16(vv - __bfloat162float(h));
                u32 off = ((u32)(c >> 6)) * 8192 + sw128(row * 128 + (u32)(c & 63) * 2);
                STS16(Ah + off, __bfloat16_as_ushort(h));
                STS16(Am + off, __bfloat16_as_ushort(m));
            }
        }
    }
    __syncthreads();   // sA complete; fs reads done before B staging overwrites

    // ---------- phase 2: mma (unchanged from R12) ----------
    int g = lane >> 2, tig = lane & 3;
    int wbase = warp * 16;
    const u32 aRow = (u32)(wbase + (lane & 15));
    const u32 aKH  = (u32)((lane >> 4) & 1) * 16;
    const u32 bRowInPair = (u32)(((lane >> 4) & 1) * 8 + (lane & 7));
    const u32 bKH  = (u32)((lane >> 3) & 1) * 16;
    const int bn = tid >> 2, bu = (tid & 3) * 2;
    const u32 bSts0 = sw128((u32)(bn * 128 + bu * 16));
    const u32 bSts1 = sw128((u32)(bn * 128 + (bu + 1) * 16));

    float dd[64];
    #pragma unroll
    for (int i = 0; i < 64; i++) dd[i] = 0.0f;

    uint4 ph0, ph1, pm0, pm1;
    {
        size_t gi = (size_t)bn * 128 + bu * 8;
        ph0 = *(const uint4*)(g_we2t_hi + gi);
        ph1 = *(const uint4*)(g_we2t_hi + gi + 8);
        pm0 = *(const uint4*)(g_we2t_mid + gi);
        pm1 = *(const uint4*)(g_we2t_mid + gi + 8);
    }

    for (int kc = 0; kc < 2; kc++) {
        u32 af[4][8];
        #pragma unroll
        for (int kk = 0; kk < 4; kk++) {
            u32 aAddr = (u32)kc * 8192 + sw128((u32)(aRow * 128 + kk * 32) + aKH);
            ldsm4(af[kk][0], af[kk][1], af[kk][2], af[kk][3], Ah + aAddr);
            ldsm4(af[kk][4], af[kk][5], af[kk][6], af[kk][7], Am + aAddr);
        }

        #pragma unroll
        for (int ng = 0; ng < 4; ng++) {
            STS128P(Bh + bSts0, ph0);
            STS128P(Bh + bSts1, ph1);
            STS128P(Bm + bSts0, pm0);
            STS128P(Bm + bSts1, pm1);
            {
                int np = kc * 4 + ng + 1;
                if (np > 7) np = 7;
                int nkc = np >> 2, nng = np & 3;
                size_t gi = (size_t)(nng * 32 + bn) * 128 + nkc * 64 + bu * 8;
                ph0 = *(const uint4*)(g_we2t_hi + gi);
                ph1 = *(const uint4*)(g_we2t_hi + gi + 8);
                pm0 = *(const uint4*)(g_we2t_mid + gi);
                pm1 = *(const uint4*)(g_we2t_mid + gi + 8);
            }
            __syncthreads();   // B visible
            #pragma unroll
            for (int kk = 0; kk < 4; kk++) {
                #pragma unroll
                for (int nt = 0; nt < 2; nt++) {
                    u32 bAddr = sw128((u32)((nt * 16 + bRowInPair) * 128 + kk * 32) + bKH);
                    u32 bh0, bh1, bh2, bh3, bm0, bm1, bm2, bm3;
                    ldsm4(bh0, bh1, bh2, bh3, Bh + bAddr);
                    ldsm4(bm0, bm1, bm2, bm3, Bm + bAddr);
                    float* dA = dd + (ng * 4 + nt * 2) * 4;
                    float* dB = dA + 4;
                    mma_bf16(dA, af[kk][0], af[kk][1], af[kk][2], af[kk][3], bh0, bh1);
                    mma_bf16(dA, af[kk][4], af[kk][5], af[kk][6], af[kk][7], bh0, bh1);
                    mma_bf16(dA, af[kk][0], af[kk][1], af[kk][2], af[kk][3], bm0, bm1);
                    mma_bf16(dB, af[kk][0], af[kk][1], af[kk][2], af[kk][3], bh2, bh3);
                    mma_bf16(dB, af[kk][4], af[kk][5], af[kk][6], af[kk][7], bh2, bh3);
                    mma_bf16(dB, af[kk][0], af[kk][1], af[kk][2], af[kk][3], bm2, bm3);
                }
            }
            __syncthreads();   // B reads done before next stores
        }
    }

    // ---------- phase 3: + b2, LN2, store to g_edge_emb ----------
    float s0 = 0.0f, q0 = 0.0f, s1 = 0.0f, q1 = 0.0f;
    #pragma unroll
    for (int ti = 0; ti < 16; ti++) {
        int c0 = ti * 8 + tig * 2;
        float v0 = dd[ti * 4 + 0] + b2s[c0];
        float v1 = dd[ti * 4 + 1] + b2s[c0 + 1];
        float v2 = dd[ti * 4 + 2] + b2s[c0];
        float v3 = dd[ti * 4 + 3] + b2s[c0 + 1];
        dd[ti * 4 + 0] = v0; dd[ti * 4 + 1] = v1;
        dd[ti * 4 + 2] = v2; dd[ti * 4 + 3] = v3;
        s0 += v0 + v1; q0 += v0 * v0 + v1 * v1;
        s1 += v2 + v3; q1 += v2 * v2 + v3 * v3;
    }
    #pragma unroll
    for (int o = 1; o < 4; o <<= 1) {
        s0 += __shfl_xor_sync(0xffffffffu, s0, o, 4);
        q0 += __shfl_xor_sync(0xffffffffu, q0, o, 4);
        s1 += __shfl_xor_sync(0xffffffffu, s1, o, 4);
        q1 += __shfl_xor_sync(0xffffffffu, q1, o, 4);
    }
    float mu0 = s0 * (1.0f / DD), mu1 = s1 * (1.0f / DD);
    float rs0 = rsqrtf(q0 * (1.0f / DD) - mu0 * mu0 + 1e-5f);
    float rs1 = rsqrtf(q1 * (1.0f / DD) - mu1 * mu1 + 1e-5f);
    float* o0 = g_edge_emb + (base + wbase + g) * DD;
    float* o1 = g_edge_emb + (base + wbase + g + 8) * DD;
    #pragma unroll
    for (int ti = 0; ti < 16; ti++) {
        int c0 = ti * 8 + tig * 2;
        float2 a, c;
        a.x = (dd[ti * 4 + 0] - mu0) * rs0 * g2s[c0]     + be2s[c0];
        a.y = (dd[ti * 4 + 1] - mu0) * rs0 * g2s[c0 + 1] + be2s[c0 + 1];
        c.x = (dd[ti * 4 + 2] - mu1) * rs1 * g2s[c0]     + be2s[c0];
        c.y = (dd[ti * 4 + 3] - mu1) * rs1 * g2s[c0 + 1] + be2s[c0 + 1];
        *(float2*)(o0 + c0) = a;
        *(float2*)(o1 + c0) = c;
    }
}

// ---------------- per-edge attention dots for both rounds ----------------
__global__ void __launch_bounds__(256) k_edot(const float* __restrict__ watt1,
                                              const float* __restrict__ watt2) {
    int lane = threadIdx.x & 31;
    long gw = (long)blockIdx.x * 8 + (threadIdx.x >> 5);
    long nwarps = (long)gridDim.x * 8;
    float w1r[4], w2r[4];
    #pragma unroll
    for (int r = 0; r < 4; r++) {
        w1r[r] = watt1[128 + lane + 32 * r];
        w2r[r] = watt2[128 + lane + 32 * r];
    }
    for (long idx = gw; idx < (long)BB * EE; idx += nwarps) {
        const float* row = g_edge_emb + idx * DD;
        float v0 = row[lane], v1 = row[lane + 32], v2 = row[lane + 64], v3 = row[lane + 96];
        float d1 = fmaf(v0, w1r[0], fmaf(v1, w1r[1], fmaf(v2, w1r[2], v3 * w1r[3])));
        float d2 = fmaf(v0, w2r[0], fmaf(v1, w2r[1], fmaf(v2, w2r[2], v3 * w2r[3])));
        #pragma unroll
        for (int o = 16; o; o >>= 1) {
            d1 += __shfl_down_sync(0xffffffffu, d1, o);
            d2 += __shfl_down_sync(0xffffffffu, d2, o);
        }
        if (lane == 0) {
            long b = idx / EE, e = idx - b * EE;
            g_d[(b * 2 + 0) * EE + e] = d1;
            g_d[(b * 2 + 1) * EE + e] = d2;
        }
    }
}

// ---------------- message passing (unchanged from R12) ----------------
__global__ void k_mp(const float* __restrict__ watt, const float* __restrict__ batt, int dir) {
    int n = blockIdx.x;
    int b = blockIdx.y;
    int tid = threadIdx.x;
    const float* nin  = (dir ? g_nodeB : g_nodeA) + (size_t)b * NN * DD;
    float*       nout = (dir ? g_nodeA : g_nodeB) + (size_t)b * NN * DD;
    const float* eemb = g_edge_emb + (size_t)b * EE * DD;
    const float* dvec = g_d + ((size_t)b * 2 + dir) * EE;
    float*       sb   = g_s + (size_t)b * 2 * EE;

    int cnt = g_deg[n];
    int start = g_off[n];
    float hval = nin[n * DD + tid];
    if (cnt == 0) { nout[n * DD + tid] = hval; return; }

    __shared__ float red[4];

    float c = brsum128(hval * watt[tid], red);
    float battv = batt[0];

    float lmax = -INFINITY;
    for (int i = tid; i < cnt; i += 128) {
        int p = g_csr[start + i];
        int e = (p < EE) ? p : p - EE;
        float s = c + dvec[e] + battv;
        s = (s > 0.0f) ? s : 0.2f * s;
        sb[start + i] = s;
        lmax = fmaxf(lmax, s);
    }
    float m = brmax128(lmax, red);

    float den = 0.0f;
    for (int i = tid; i < cnt; i += 128) {
        float ex = __expf(sb[start + i] - m);
        sb[start + i] = ex;
        den += ex;
    }
    den = brsum128(den, red);
    float inv = 1.0f / den;

    float acc0 = 0.0f, acc1 = 0.0f;
    int i = 0;
    for (; i + 1 < cnt; i += 2) {
        int p0 = g_csr[start + i];
        int p1 = g_csr[start + i + 1];
        int ea = (p0 < EE) ? p0 : p0 - EE;
        int eb = (p1 < EE) ? p1 : p1 - EE;
        float wg0 = sb[start + i];
        float wg1 = sb[start + i + 1];
        acc0 = fmaf(wg0, eemb[(size_t)ea * DD + tid], acc0);
        acc1 = fmaf(wg1, eemb[(size_t)eb * DD + tid], acc1);
    }
    if (i < cnt) {
        int p = g_csr[start + i];
        int e = (p < EE) ? p : p - EE;
        acc0 = fmaf(sb[start + i], eemb[(size_t)e * DD + tid], acc0);
    }
    nout[n * DD + tid] = geluf((acc0 + acc1) * inv);
}

// ---------------- decoder stage 1 (EXACT R8 structure) ----------------
__global__ void __launch_bounds__(256, 1) k_dec1(
    const int* __restrict__ src, const int* __restrict__ dst,
    const float* __restrict__ b1) {
    __shared__ __align__(16) __nv_bfloat16 sAh[8192];
    __shared__ __align__(16) __nv_bfloat16 sAm[8192];
    __shared__ __align__(16) __nv_bfloat16 sBh[2048];
    __shared__ __align__(16) __nv_bfloat16 sBm[2048];
    __shared__ float b1s[256];
    __shared__ int sidx[128], didx[128];

    const u32 Ah = smem_u32(sAh), Am = smem_u32(sAm);
    const u32 Bh = smem_u32(sBh), Bm = smem_u32(sBm);

    int tid = threadIdx.x, lane = tid & 31, warp = tid >> 5;
    int g = lane >> 2, tig = lane & 3;
    int wbase = warp * 16;

    long base = (long)blockIdx.x * 128;
    int b = (int)(base / EE);
    int e0 = (int)(base - (long)b * EE);
    size_t bNN = (size_t)b * NN;

    b1s[tid] = b1[tid];
    if (tid < 128) {
        sidx[tid] = src[e0 + tid];
        didx[tid] = dst[e0 + tid];
    }
    __syncthreads();

    const u32 aRow = (u32)(wbase + (lane & 15));
    const u32 aKH  = (u32)((lane >> 4) & 1) * 16;
    const u32 bRowInPair = (u32)(((lane >> 4) & 1) * 8 + (lane & 7));
    const u32 bKH  = (u32)((lane >> 3) & 1) * 16;
    const int bn = tid >> 3, bu = tid & 7;
    const u32 bSts = sw128((u32)(bn * 128 + bu * 16));

    float d1[128];
    #pragma unroll
    for (int i = 0; i < 128; i++) d1[i] = 0.0f;

    uint4 pvh, pvm;
    {
        size_t gidx = (size_t)bn * 384 + bu * 8;
        pvh = *(const uint4*)(g_w1t_hi + gidx);
        pvm = *(const uint4*)(g_w1t_mid + gidx);
    }

    for (int kc = 0; kc < 6; kc++) {
        for (int j = tid; j < 2048; j += 256) {
            int r = j >> 4, q = j & 15;
            const float* rp;
            int f4;
            if (kc < 2)      { rp = g_nodeA + (bNN + sidx[r]) * DD;              f4 = kc * 16 + q; }
            else if (kc < 4) { rp = g_nodeA + (bNN + didx[r]) * DD;              f4 = (kc - 2) * 16 + q; }
            else             { rp = g_edge_emb + ((size_t)b * EE + e0 + r) * DD; f4 = (kc - 4) * 16 + q; }
            float4 v = ((const float4*)rp)[f4];
            __nv_bfloat16 h0 = __float2bfloat16(v.x), h1 = __float2bfloat16(v.y);
            __nv_bfloat16 h2 = __float2bfloat16(v.z), h3 = __float2bfloat16(v.w);
            __nv_bfloat16 m0 = __float2bfloat16(v.x - __bfloat162float(h0));
            __nv_bfloat16 m1 = __float2bfloat16(v.y - __bfloat162float(h1));
            __nv_bfloat16 m2 = __float2bfloat16(v.z - __bfloat162float(h2));
            __nv_bfloat16 m3 = __float2bfloat16(v.w - __bfloat162float(h3));
            u32 off = sw128((u32)(r * 128 + q * 8));
            STS64P(Ah + off, packbf(h0, h1), packbf(h2, h3));
            STS64P(Am + off, packbf(m0, m1), packbf(m2, m3));
        }
        __syncthreads();

        u32 af[4][8];
        #pragma unroll
        for (int kk = 0; kk < 4; kk++) {
            u32 aAddr = sw128((u32)(aRow * 128 + kk * 32) + aKH);
            ldsm4(af[kk][0], af[kk][1], af[kk][2], af[kk][3], Ah + aAddr);
            ldsm4(af[kk][4], af[kk][5], af[kk][6], af[kk][7], Am + aAddr);
        }

        #pragma unroll
        for (int ng = 0; ng < 8; ng++) {
            STS128P(Bh + bSts, pvh);
            STS128P(Bm + bSts, pvm);
            {
                int np = kc * 8 + ng + 1;
                if (np > 47) np = 47;
                int nkc = np >> 3, nng = np & 7;
                size_t gidx = (size_t)(nng * 32 + bn) * 384 + nkc * 64 + bu * 8;
                pvh = *(const uint4*)(g_w1t_hi + gidx);
                pvm = *(const uint4*)(g_w1t_mid + gidx);
            }
            __syncthreads();
            #pragma unroll
            for (int kk = 0; kk < 4; kk++) {
                #pragma unroll
                for (int nt = 0; nt < 2; nt++) {
                    u32 bAddr = sw128((u32)((nt * 16 + bRowInPair) * 128 + kk * 32) + bKH);
                    u32 bh0, bh1, bh2, bh3, bm0, bm1, bm2, bm3;
                    ldsm4(bh0, bh1, bh2, bh3, Bh + bAddr);
                    ldsm4(bm0, bm1, bm2, bm3, Bm + bAddr);
                    float* dA = d1 + (ng * 4 + nt * 2) * 4;
                    float* dB = dA + 4;
                    mma_bf16(dA, af[kk][0], af[kk][1], af[kk][2], af[kk][3], bh0, bh1);
                    mma_bf16(dA, af[kk][4], af[kk][5], af[kk][6], af[kk][7], bh0, bh1);
                    mma_bf16(dA, af[kk][0], af[kk][1], af[kk][2], af[kk][3], bm0, bm1);
                    mma_bf16(dB, af[kk][0], af[kk][1], af[kk][2], af[kk][3], bh2, bh3);
                    mma_bf16(dB, af[kk][4], af[kk][5], af[kk][6], af[kk][7], bh2, bh3);
                    mma_bf16(dB, af[kk][0], af[kk][1], af[kk][2], af[kk][3], bm2, bm3);
                }
            }
            __syncthreads();
        }
    }

    long r0 = base + wbase + g;
    long r1 = r0 + 8;
    #pragma unroll
    for (int ti = 0; ti < 32; ti++) {
        int c0 = ti * 8 + tig * 2;
        float v0 = geluf(d1[ti * 4 + 0] + b1s[c0]);
        float v1 = geluf(d1[ti * 4 + 1] + b1s[c0 + 1]);
        float v2 = geluf(d1[ti * 4 + 2] + b1s[c0]);
        float v3 = geluf(d1[ti * 4 + 3] + b1s[c0 + 1]);
        __nv_bfloat16 h0 = __float2bfloat16(v0), h1 = __float2bfloat16(v1);
        __nv_bfloat16 h2 = __float2bfloat16(v2), h3 = __float2bfloat16(v3);
        __nv_bfloat16 m0 = __float2bfloat16(v0 - __bfloat162float(h0));
        __nv_bfloat16 m1 = __float2bfloat16(v1 - __bfloat162float(h1));
        __nv_bfloat16 m2 = __float2bfloat16(v2 - __bfloat162float(h2));
        __nv_bfloat16 m3 = __float2bfloat16(v3 - __bfloat162float(h3));
        *(u32*)(g_z1_hi  + r0 * 256 + c0) = packbf(h0, h1);
        *(u32*)(g_z1_mid + r0 * 256 + c0) = packbf(m0, m1);
        *(u32*)(g_z1_hi  + r1 * 256 + c0) = packbf(h2, h3);
        *(u32*)(g_z1_mid + r1 * 256 + c0) = packbf(m2, m3);
    }
}

// ---------------- decoder stage 2 (EXACT R8 structure) ----------------
__global__ void __launch_bounds__(256, 1) k_dec2(
    const float* __restrict__ b2, const float* __restrict__ w3,
    const float* __restrict__ b3, float* __restrict__ out) {
    __shared__ __align__(16) __nv_bfloat16 sAh[8192];
    __shared__ __align__(16) __nv_bfloat16 sAm[8192];
    __shared__ __align__(16) __nv_bfloat16 sBh[2048];
    __shared__ __align__(16) __nv_bfloat16 sBm[2048];
    __shared__ float b2s[128], w3s[128];

    const u32 Ah = smem_u32(sAh), Am = smem_u32(sAm);
    const u32 Bh = smem_u32(sBh), Bm = smem_u32(sBm);

    int tid = threadIdx.x, lane = tid & 31, warp = tid >> 5;
    int g = lane >> 2, tig = lane & 3;
    int wbase = warp * 16;
    long base = (long)blockIdx.x * 128;

    if (tid < 128) { b2s[tid] = b2[tid]; w3s[tid] = w3[tid]; }

    const u32 aRow = (u32)(wbase + (lane & 15));
    const u32 aKH  = (u32)((lane >> 4) & 1) * 16;
    const u32 bRowInPair = (u32)(((lane >> 4) & 1) * 8 + (lane & 7));
    const u32 bKH  = (u32)((lane >> 3) & 1) * 16;
    const int bn = tid >> 3, bu = tid & 7;
    const u32 bSts = sw128((u32)(bn * 128 + bu * 16));

    float d2[64];
    #pragma unroll
    for (int i = 0; i < 64; i++) d2[i] = 0.0f;

    uint4 pvh, pvm;
    {
        size_t gidx = (size_t)bn * 256 + bu * 8;
        pvh = *(const uint4*)(g_w2t_hi + gidx);
        pvm = *(const uint4*)(g_w2t_mid + gidx);
    }

    for (int kc = 0; kc < 4; kc++) {
        __syncthreads();
        for (int j = tid; j < 1024; j += 256) {
            int r = j >> 3, u = j & 7;
            size_t gidx = (size_t)(base + r) * 256 + kc * 64 + u * 8;
            uint4 vh = *(const uint4*)(g_z1_hi + gidx);
            uint4 vm = *(const uint4*)(g_z1_mid + gidx);
            u32 off = sw128((u32)(r * 128 + u * 16));
            STS128P(Ah + off, vh);
            STS128P(Am + off, vm);
        }
        __syncthreads();

        u32 af[4][8];
        #pragma unroll
        for (int kk = 0; kk < 4; kk++) {
            u32 aAddr = sw128((u32)(aRow * 128 + kk * 32) + aKH);
            ldsm4(af[kk][0], af[kk][1], af[kk][2], af[kk][3], Ah + aAddr);
            ldsm4(af[kk][4], af[kk][5], af[kk][6], af[kk][7], Am + aAddr);
        }

        #pragma unroll
        for (int ng = 0; ng < 4; ng++) {
            STS128P(Bh + bSts, pvh);
            STS128P(Bm + bSts, pvm);
            {
                int np = kc * 4 + ng + 1;
                if (np > 15) np = 15;
                int nkc = np >> 2, nng = np & 3;
                size_t gidx = (size_t)(nng * 32 + bn) * 256 + nkc * 64 + bu * 8;
                pvh = *(const uint4*)(g_w2t_hi + gidx);
                pvm = *(const uint4*)(g_w2t_mid + gidx);
            }
            __syncthreads();
            #pragma unroll
            for (int kk = 0; kk < 4; kk++) {
                #pragma unroll
                for (int nt = 0; nt < 2; nt++) {
                    u32 bAddr = sw128((u32)((nt * 16 + bRowInPair) * 128 + kk * 32) + bKH);
                    u32 bh0, bh1, bh2, bh3, bm0, bm1, bm2, bm3;
                    ldsm4(bh0, bh1, bh2, bh3, Bh + bAddr);
                    ldsm4(bm0, bm1, bm2, bm3, Bm + bAddr);
                    float* dA = d2 + (ng * 4 + nt * 2) * 4;
                    float* dB = dA + 4;
                    mma_bf16(dA, af[kk][0], af[kk][1], af[kk][2], af[kk][3], bh0, bh1);
                    mma_bf16(dA, af[kk][4], af[kk][5], af[kk][6], af[kk][7], bh0, bh1);
                    mma_bf16(dA, af[kk][0], af[kk][1], af[kk][2], af[kk][3], bm0, bm1);
                    mma_bf16(dB, af[kk][0], af[kk][1], af[kk][2], af[kk][3], bh2, bh3);
                    mma_bf16(dB, af[kk][4], af[kk][5], af[kk][6], af[kk][7], bh2, bh3);
                    mma_bf16(dB, af[kk][0], af[kk][1], af[kk][2], af[kk][3], bm2, bm3);
                }
            }
            __syncthreads();
        }
    }

    float acc0 = 0.0f, acc1 = 0.0f;
    #pragma unroll
    for (int ti = 0; ti < 16; ti++) {
        int c0 = ti * 8 + tig * 2;
        float w0 = w3s[c0], w1v = w3s[c0 + 1];
        float bb0 = b2s[c0], bb1 = b2s[c0 + 1];
        acc0 = fmaf(geluf(d2[ti * 4 + 0] + bb0), w0, acc0);
        acc0 = fmaf(geluf(d2[ti * 4 + 1] + bb1), w1v, acc0);
        acc1 = fmaf(geluf(d2[ti * 4 + 2] + bb0), w0, acc1);
        acc1 = fmaf(geluf(d2[ti * 4 + 3] + bb1), w1v, acc1);
    }
    acc0 += __shfl_down_sync(0xffffffffu, acc0, 2, 4);
    acc0 += __shfl_down_sync(0xffffffffu, acc0, 1, 4);
    acc1 += __shfl_down_sync(0xffffffffu, acc1, 2, 4);
    acc1 += __shfl_down_sync(0xffffffffu, acc1, 1, 4);
    if (tig == 0) {
        float b3v = b3[0];
        out[base + wbase + g] = acc0 + b3v;
        out[base + wbase + g + 8] = acc1 + b3v;
    }
}

// ---------------- launch ----------------
extern "C" void kernel_launch(void* const* d_in, const int* in_sizes, int n_in,
                              void* d_out, int out_size) {
    const float* feat   = (const float*)d_in[0];
    const float* enc_w1 = (const float*)d_in[1];
    const float* enc_b1 = (const float*)d_in[2];
    const float* enc_g1 = (const float*)d_in[3];
    const float* enc_be1= (const float*)d_in[4];
    const float* enc_w2 = (const float*)d_in[5];
    const float* enc_b2 = (const float*)d_in[6];
    const float* enc_g2 = (const float*)d_in[7];
    const float* enc_be2= (const float*)d_in[8];
    const float* watt1  = (const float*)d_in[9];
    const float* batt1  = (const float*)d_in[10];
    const float* watt2  = (const float*)d_in[11];
    const float* batt2  = (const float*)d_in[12];
    const float* dec_w1 = (const float*)d_in[13];
    const float* dec_b1 = (const float*)d_in[14];
    const float* dec_w2 = (const float*)d_in[15];
    const float* dec_b2 = (const float*)d_in[16];
    const float* dec_w3 = (const float*)d_in[17];
    const float* dec_b3 = (const float*)d_in[18];
    const int*   src    = (const int*)d_in[19];
    const int*   dst    = (const int*)d_in[20];
    float* out = (float*)d_out;

    {
        long n = (long)BB * NN * DD;
        int blocks = (int)((n + 255) / 256);
        k_zero_node_and_counts<<<blocks, 256>>>();
    }

    k_prep<<<(256 * 384 + 255) / 256, 256>>>(dec_w1, dec_w2, enc_w2);

    k_count_deg<<<(EE + 255) / 256, 256>>>(src, dst);

    // 4th launch (ncu-profiled): the encoder
    k_enc<<<(BB * EE) / 64, 128>>>(feat, enc_w1, enc_b1, enc_g1, enc_be1,
                                   enc_b2, enc_g2, enc_be2);

    k_scan<<<1, 1024>>>();
    k_scatter<<<(2 * EE + 255) / 256, 256>>>(src, dst);

    k_edot<<<1480, 256>>>(watt1, watt2);

    k_mp<<<dim3(NN, BB), DD>>>(watt1, batt1, 0);
    k_mp<<<dim3(NN, BB), DD>>>(watt2, batt2, 1);

    k_dec1<<<(BB * EE) / 128, 256>>>(src, dst, dec_b1);
    k_dec2<<<(BB * EE) / 128, 256>>>(dec_b2, dec_w3, dec_b3, out);
}

// round 14
// speedup vs baseline: 1.0630x; 1.0366x over previous
#include <cuda_runtime.h>
#include <cuda_bf16.h>
#include <math.h>
#include <stdint.h>

// Problem constants
#define BB 2
#define EE 160000
#define NN 10000
#define DD 128
#define TE 16

typedef unsigned long long u64;
typedef unsigned int u32;

// ---------------- scratch (device globals) ----------------
__device__ float g_edge_emb[(size_t)BB * EE * DD];
__device__ float g_nodeA[(size_t)BB * NN * DD];
__device__ float g_nodeB[(size_t)BB * NN * DD];
__device__ float g_s[(size_t)BB * 2 * EE];
__device__ float g_d[(size_t)BB * 2 * EE];
__device__ int   g_deg[NN];
__device__ int   g_off[NN + 1];
__device__ int   g_cursor[NN];
__device__ int   g_csr[2 * EE];
// decoder weights, transposed to [N,K] row-major, bf16 hi/mid split
__device__ __align__(16) __nv_bfloat16 g_w1t_hi[256 * 384];
__device__ __align__(16) __nv_bfloat16 g_w1t_mid[256 * 384];
__device__ __align__(16) __nv_bfloat16 g_w2t_hi[128 * 256];
__device__ __align__(16) __nv_bfloat16 g_w2t_mid[128 * 256];
// encoder layer-2 weights, transposed [N=128][K=128], bf16 hi/mid split
__device__ __align__(16) __nv_bfloat16 g_we2t_hi[128 * 128];
__device__ __align__(16) __nv_bfloat16 g_we2t_mid[128 * 128];
// z1 activations, pre-split bf16 hi/mid: [B*E][256]
__device__ __align__(16) __nv_bfloat16 g_z1_hi[(size_t)BB * EE * 256];
__device__ __align__(16) __nv_bfloat16 g_z1_mid[(size_t)BB * EE * 256];

// ---------------- generic helpers ----------------
__device__ __forceinline__ float geluf(float x) { return x * normcdff(x); }

__device__ __forceinline__ u64 pack2(float lo, float hi) {
    u64 r; asm("mov.b64 %0, {%1, %2};" : "=l"(r) : "f"(lo), "f"(hi)); return r;
}
__device__ __forceinline__ u64 fma2(u64 a, u64 b, u64 c) {
    u64 d; asm("fma.rn.f32x2 %0, %1, %2, %3;" : "=l"(d) : "l"(a), "l"(b), "l"(c)); return d;
}
__device__ __forceinline__ float sum2(u64 v) {
    float lo, hi; asm("mov.b64 {%0, %1}, %2;" : "=f"(lo), "=f"(hi) : "l"(v)); return lo + hi;
}

__device__ __forceinline__ float brsum128(float v, float* red) {
    int lane = threadIdx.x & 31, w = threadIdx.x >> 5;
    #pragma unroll
    for (int o = 16; o; o >>= 1) v += __shfl_down_sync(0xffffffffu, v, o);
    if (lane == 0) red[w] = v;
    __syncthreads();
    float s = red[0] + red[1] + red[2] + red[3];
    __syncthreads();
    return s;
}
__device__ __forceinline__ float brmax128(float v, float* red) {
    int lane = threadIdx.x & 31, w = threadIdx.x >> 5;
    #pragma unroll
    for (int o = 16; o; o >>= 1) v = fmaxf(v, __shfl_down_sync(0xffffffffu, v, o));
    if (lane == 0) red[w] = v;
    __syncthreads();
    float s = fmaxf(fmaxf(red[0], red[1]), fmaxf(red[2], red[3]));
    __syncthreads();
    return s;
}

// ---------------- mma.sync / ldmatrix helpers ----------------
__device__ __forceinline__ u32 smem_u32(const void* p) {
    u32 a; asm("{ .reg .u64 t; cvta.to.shared.u64 t, %1; cvt.u32.u64 %0, t; }" : "=r"(a) : "l"(p));
    return a;
}
__device__ __forceinline__ void ldsm4(u32& r0, u32& r1, u32& r2, u32& r3, u32 addr) {
    asm volatile("ldmatrix.sync.aligned.m8n8.x4.shared.b16 {%0,%1,%2,%3}, [%4];"
        : "=r"(r0), "=r"(r1), "=r"(r2), "=r"(r3) : "r"(addr));
}
__device__ __forceinline__ void mma_bf16(float* d, u32 a0, u32 a1, u32 a2, u32 a3, u32 b0, u32 b1) {
    asm volatile("mma.sync.aligned.m16n8k16.row.col.f32.bf16.bf16.f32 "
        "{%0,%1,%2,%3}, {%4,%5,%6,%7}, {%8,%9}, {%0,%1,%2,%3};"
        : "+f"(d[0]), "+f"(d[1]), "+f"(d[2]), "+f"(d[3])
        : "r"(a0), "r"(a1), "r"(a2), "r"(a3), "r"(b0), "r"(b1));
}
#define STS16(a, v)     asm volatile("st.shared.u16 [%0], %1;" :: "r"(a), "h"(v) : "memory")
#define STS64P(a, x, y) asm volatile("st.shared.v2.b32 [%0], {%1, %2};" :: "r"(a), "r"(x), "r"(y) : "memory")
#define STS128P(a, v)   asm volatile("st.shared.v4.b32 [%0], {%1, %2, %3, %4};" \
                            :: "r"(a), "r"((v).x), "r"((v).y), "r"((v).z), "r"((v).w) : "memory")
__device__ __forceinline__ u32 sw128(u32 off) { return off ^ ((off >> 3) & 0x70); }
__device__ __forceinline__ u32 packbf(__nv_bfloat16 a, __nv_bfloat16 b) {
    return ((u32)__bfloat16_as_ushort(b) << 16) | (u32)__bfloat16_as_ushort(a);
}

// ---------------- init ----------------
__global__ void k_zero_node_and_counts() {
    long i = (long)blockIdx.x * blockDim.x + threadIdx.x;
    long nNode = (long)BB * NN * DD;
    if (i < nNode) g_nodeA[i] = 0.0f;
    if (i < NN) { g_deg[i] = 0; g_cursor[i] = 0; }
}

// ---------------- CSR build ----------------
__global__ void k_count_deg(const int* __restrict__ src, const int* __restrict__ dst) {
    int i = blockIdx.x * blockDim.x + threadIdx.x;
    if (i < EE) {
        atomicAdd(&g_deg[src[i]], 1);
        atomicAdd(&g_deg[dst[i]], 1);
    }
}

__global__ void k_scan() {
    __shared__ int sums[1024];
    int t = threadIdx.x;
    const int chunk = (NN + 1023) / 1024;
    int start = t * chunk;
    int end = min(start + chunk, NN);
    int s = 0;
    for (int i = start; i < end; i++) s += g_deg[i];
    sums[t] = s;
    __syncthreads();
    for (int d = 1; d < 1024; d <<= 1) {
        int v = (t >= d) ? sums[t - d] : 0;
        __syncthreads();
        sums[t] += v;
        __syncthreads();
    }
    int run = (t > 0) ? sums[t - 1] : 0;
    for (int i = start; i < end; i++) { g_off[i] = run; run += g_deg[i]; }
    if (t == 1023) g_off[NN] = sums[1023];
}

__global__ void k_scatter(const int* __restrict__ src, const int* __restrict__ dst) {
    int p = blockIdx.x * blockDim.x + threadIdx.x;
    if (p < 2 * EE) {
        int node = (p < EE) ? src[p] : dst[p - EE];
        int pos = g_off[node] + atomicAdd(&g_cursor[node], 1);
        g_csr[pos] = p;
    }
}

// ---------------- weight prep: transpose + bf16 hi/mid split ----------------
__global__ void k_prep(const float* __restrict__ w1, const float* __restrict__ w2,
                       const float* __restrict__ we2) {
    int i = blockIdx.x * blockDim.x + threadIdx.x;
    if (i < 256 * 384) {
        int n = i / 384, k = i - n * 384;
        float v = w1[(size_t)k * 256 + n];
        __nv_bfloat16 h = __float2bfloat16(v);
        g_w1t_hi[i] = h;
        g_w1t_mid[i] = __float2bfloat16(v - __bfloat162float(h));
    }
    if (i < 128 * 256) {
        int n = i / 256, k = i - n * 256;
        float v = w2[(size_t)k * 128 + n];
        __nv_bfloat16 h = __float2bfloat16(v);
        g_w2t_hi[i] = h;
        g_w2t_mid[i] = __float2bfloat16(v - __bfloat162float(h));
    }
    if (i < 128 * 128) {
        int n = i / 128, k = i - n * 128;
        float v = we2[(size_t)k * 128 + n];
        __nv_bfloat16 h = __float2bfloat16(v);
        g_we2t_hi[i] = h;
        g_we2t_mid[i] = __float2bfloat16(v - __bfloat162float(h));
    }
}

// ---------------- encoder: layer1 scalar fp32 + layer2 on mma.sync bf16x3 ----------------
// 64 edges / CTA, 128 threads. ONLY change vs R13: minBlocksPerMultiprocessor 3
// (caps regs at ~170, natural allocation was 248 padding -> 2 CTAs/SM).
__global__ void __launch_bounds__(128, 3) k_enc(
    const float* __restrict__ feat,
    const float* __restrict__ w1, const float* __restrict__ b1,
    const float* __restrict__ g1, const float* __restrict__ be1,
    const float* __restrict__ b2, const float* __restrict__ g2,
    const float* __restrict__ be2) {
    __shared__ __align__(16) __nv_bfloat16 sAh[8192];  // 2 subtiles x (64 rows x 64 cols)
    __shared__ __align__(16) __nv_bfloat16 sAm[8192];
    __shared__ __align__(16) __nv_bfloat16 sBh[2048];  // phase2 B staging; phase1 fs
    __shared__ __align__(16) __nv_bfloat16 sBm[2048];
    __shared__ __align__(16) float xs[8][24];
    __shared__ float b2s[128], g2s[128], be2s[128];
    __shared__ float g1s[128], be1s[128];

    const u32 Ah = smem_u32(sAh), Am = smem_u32(sAm);
    const u32 Bh = smem_u32(sBh), Bm = smem_u32(sBm);

    int tid = threadIdx.x, lane = tid & 31, warp = tid >> 5;
    long base = (long)blockIdx.x * 64;

    b2s[tid] = b2[tid];
    g2s[tid] = g2[tid];
    be2s[tid] = be2[tid];
    g1s[tid] = g1[tid];
    be1s[tid] = be1[tid];

    // layer1 column cache (thread owns col d = tid)
    int d = tid;
    u64 wp[12];
    #pragma unroll
    for (int k = 0; k < 12; k++)
        wp[k] = pack2(w1[(2 * k) * DD + d], w1[(2 * k + 1) * DD + d]);
    float b1v = b1[d];

    // ---------- phase 1: layer1 + LN1 + gelu -> sA planes (8 edges/iter) ----------
    float* fs = (float*)sBh;   // 4 KB = 1024 floats = 8 edges x 128 cols
    for (int it = 0; it < 8; it++) {
        __syncthreads();   // fs / xs free (covers initial smem fills too)
        for (int i = tid; i < 48; i += 128) {
            int t = i / 6, j = i % 6;
            ((float4*)xs[t])[j] = ((const float4*)(feat + (base + it * 8 + t) * 24))[j];
        }
        __syncthreads();

        float acc[8];
        #pragma unroll
        for (int t = 0; t < 8; t++) {
            u64 a = pack2(b1v, 0.0f);
            #pragma unroll
            for (int j = 0; j < 6; j++) {
                ulonglong2 xv = ((const ulonglong2*)xs[t])[j];
                a = fma2(xv.x, wp[2 * j], a);
                a = fma2(xv.y, wp[2 * j + 1], a);
            }
            acc[t] = sum2(a);
        }
        #pragma unroll
        for (int t = 0; t < 8; t++) fs[t * 128 + d] = acc[t];
        __syncthreads();

        // warp w normalizes edges w*2, w*2+1
        #pragma unroll
        for (int tt = 0; tt < 2; tt++) {
            int t = warp * 2 + tt;
            float v[4];
            #pragma unroll
            for (int r = 0; r < 4; r++) v[r] = fs[t * 128 + lane + 32 * r];
            float s = v[0] + v[1] + v[2] + v[3];
            float q = v[0] * v[0] + v[1] * v[1] + v[2] * v[2] + v[3] * v[3];
            #pragma unroll
            for (int o = 16; o; o >>= 1) {
                s += __shfl_xor_sync(0xffffffffu, s, o);
                q += __shfl_xor_sync(0xffffffffu, q, o);
            }
            float mu = s * (1.0f / DD);
            float rstd = rsqrtf(q * (1.0f / DD) - mu * mu + 1e-5f);
            u32 row = (u32)(it * 8 + t);
            #pragma unroll
            for (int r = 0; r < 4; r++) {
                int c = lane + 32 * r;
                float vv = geluf((v[r] - mu) * rstd * g1s[c] + be1s[c]);
                __nv_bfloat16 h = __float2bfloat16(vv);
                __nv_bfloat16 m = __float2bfloat16(vv - __bfloat162float(h));
                u32 off = ((u32)(c >> 6)) * 8192 + sw128(row * 128 + (u32)(c & 63) * 2);
                STS16(Ah + off, __bfloat16_as_ushort(h));
                STS16(Am + off, __bfloat16_as_ushort(m));
            }
        }
    }
    __syncthreads();   // sA complete; fs reads done before B staging overwrites

    // ---------- phase 2: mma ----------
    int g = lane >> 2, tig = lane & 3;
    int wbase = warp * 16;
    const u32 aRow = (u32)(wbase + (lane & 15));
    const u32 aKH  = (u32)((lane >> 4) & 1) * 16;
    const u32 bRowInPair = (u32)(((lane >> 4) & 1) * 8 + (lane & 7));
    const u32 bKH  = (u32)((lane >> 3) & 1) * 16;
    const int bn = tid >> 2, bu = (tid & 3) * 2;
    const u32 bSts0 = sw128((u32)(bn * 128 + bu * 16));
    const u32 bSts1 = sw128((u32)(bn * 128 + (bu + 1) * 16));

    float dd[64];
    #pragma unroll
    for (int i = 0; i < 64; i++) dd[i] = 0.0f;

    uint4 ph0, ph1, pm0, pm1;
    {
        size_t gi = (size_t)bn * 128 + bu * 8;
        ph0 = *(const uint4*)(g_we2t_hi + gi);
        ph1 = *(const uint4*)(g_we2t_hi + gi + 8);
        pm0 = *(const uint4*)(g_we2t_mid + gi);
        pm1 = *(const uint4*)(g_we2t_mid + gi + 8);
    }

    for (int kc = 0; kc < 2; kc++) {
        u32 af[4][8];
        #pragma unroll
        for (int kk = 0; kk < 4; kk++) {
            u32 aAddr = (u32)kc * 8192 + sw128((u32)(aRow * 128 + kk * 32) + aKH);
            ldsm4(af[kk][0], af[kk][1], af[kk][2], af[kk][3], Ah + aAddr);
            ldsm4(af[kk][4], af[kk][5], af[kk][6], af[kk][7], Am + aAddr);
        }

        #pragma unroll
        for (int ng = 0; ng < 4; ng++) {
            STS128P(Bh + bSts0, ph0);
            STS128P(Bh + bSts1, ph1);
            STS128P(Bm + bSts0, pm0);
            STS128P(Bm + bSts1, pm1);
            {
                int np = kc * 4 + ng + 1;
                if (np > 7) np = 7;
                int nkc = np >> 2, nng = np & 3;
                size_t gi = (size_t)(nng * 32 + bn) * 128 + nkc * 64 + bu * 8;
                ph0 = *(const uint4*)(g_we2t_hi + gi);
                ph1 = *(const uint4*)(g_we2t_hi + gi + 8);
                pm0 = *(const uint4*)(g_we2t_mid + gi);
                pm1 = *(const uint4*)(g_we2t_mid + gi + 8);
            }
            __syncthreads();   // B visible
            #pragma unroll
            for (int kk = 0; kk < 4; kk++) {
                #pragma unroll
                for (int nt = 0; nt < 2; nt++) {
                    u32 bAddr = sw128((u32)((nt * 16 + bRowInPair) * 128 + kk * 32) + bKH);
                    u32 bh0, bh1, bh2, bh3, bm0, bm1, bm2, bm3;
                    ldsm4(bh0, bh1, bh2, bh3, Bh + bAddr);
                    ldsm4(bm0, bm1, bm2, bm3, Bm + bAddr);
                    float* dA = dd + (ng * 4 + nt * 2) * 4;
                    float* dB = dA + 4;
                    mma_bf16(dA, af[kk][0], af[kk][1], af[kk][2], af[kk][3], bh0, bh1);
                    mma_bf16(dA, af[kk][4], af[kk][5], af[kk][6], af[kk][7], bh0, bh1);
                    mma_bf16(dA, af[kk][0], af[kk][1], af[kk][2], af[kk][3], bm0, bm1);
                    mma_bf16(dB, af[kk][0], af[kk][1], af[kk][2], af[kk][3], bh2, bh3);
                    mma_bf16(dB, af[kk][4], af[kk][5], af[kk][6], af[kk][7], bh2, bh3);
                    mma_bf16(dB, af[kk][0], af[kk][1], af[kk][2], af[kk][3], bm2, bm3);
                }
            }
            __syncthreads();   // B reads done before next stores
        }
    }

    // ---------- phase 3: + b2, LN2, store to g_edge_emb ----------
    float s0 = 0.0f, q0 = 0.0f, s1 = 0.0f, q1 = 0.0f;
    #pragma unroll
    for (int ti = 0; ti < 16; ti++) {
        int c0 = ti * 8 + tig * 2;
        float v0 = dd[ti * 4 + 0] + b2s[c0];
        float v1 = dd[ti * 4 + 1] + b2s[c0 + 1];
        float v2 = dd[ti * 4 + 2] + b2s[c0];
        float v3 = dd[ti * 4 + 3] + b2s[c0 + 1];
        dd[ti * 4 + 0] = v0; dd[ti * 4 + 1] = v1;
        dd[ti * 4 + 2] = v2; dd[ti * 4 + 3] = v3;
        s0 += v0 + v1; q0 += v0 * v0 + v1 * v1;
        s1 += v2 + v3; q1 += v2 * v2 + v3 * v3;
    }
    #pragma unroll
    for (int o = 1; o < 4; o <<= 1) {
        s0 += __shfl_xor_sync(0xffffffffu, s0, o, 4);
        q0 += __shfl_xor_sync(0xffffffffu, q0, o, 4);
        s1 += __shfl_xor_sync(0xffffffffu, s1, o, 4);
        q1 += __shfl_xor_sync(0xffffffffu, q1, o, 4);
    }
    float mu0 = s0 * (1.0f / DD), mu1 = s1 * (1.0f / DD);
    float rs0 = rsqrtf(q0 * (1.0f / DD) - mu0 * mu0 + 1e-5f);
    float rs1 = rsqrtf(q1 * (1.0f / DD) - mu1 * mu1 + 1e-5f);
    float* o0 = g_edge_emb + (base + wbase + g) * DD;
    float* o1 = g_edge_emb + (base + wbase + g + 8) * DD;
    #pragma unroll
    for (int ti = 0; ti < 16; ti++) {
        int c0 = ti * 8 + tig * 2;
        float2 a, c;
        a.x = (dd[ti * 4 + 0] - mu0) * rs0 * g2s[c0]     + be2s[c0];
        a.y = (dd[ti * 4 + 1] - mu0) * rs0 * g2s[c0 + 1] + be2s[c0 + 1];
        c.x = (dd[ti * 4 + 2] - mu1) * rs1 * g2s[c0]     + be2s[c0];
        c.y = (dd[ti * 4 + 3] - mu1) * rs1 * g2s[c0 + 1] + be2s[c0 + 1];
        *(float2*)(o0 + c0) = a;
        *(float2*)(o1 + c0) = c;
    }
}

// ---------------- per-edge attention dots for both rounds ----------------
__global__ void __launch_bounds__(256) k_edot(const float* __restrict__ watt1,
                                              const float* __restrict__ watt2) {
    int lane = threadIdx.x & 31;
    long gw = (long)blockIdx.x * 8 + (threadIdx.x >> 5);
    long nwarps = (long)gridDim.x * 8;
    float w1r[4], w2r[4];
    #pragma unroll
    for (int r = 0; r < 4; r++) {
        w1r[r] = watt1[128 + lane + 32 * r];
        w2r[r] = watt2[128 + lane + 32 * r];
    }
    for (long idx = gw; idx < (long)BB * EE; idx += nwarps) {
        const float* row = g_edge_emb + idx * DD;
        float v0 = row[lane], v1 = row[lane + 32], v2 = row[lane + 64], v3 = row[lane + 96];
        float d1 = fmaf(v0, w1r[0], fmaf(v1, w1r[1], fmaf(v2, w1r[2], v3 * w1r[3])));
        float d2 = fmaf(v0, w2r[0], fmaf(v1, w2r[1], fmaf(v2, w2r[2], v3 * w2r[3])));
        #pragma unroll
        for (int o = 16; o; o >>= 1) {
            d1 += __shfl_down_sync(0xffffffffu, d1, o);
            d2 += __shfl_down_sync(0xffffffffu, d2, o);
        }
        if (lane == 0) {
            long b = idx / EE, e = idx - b * EE;
            g_d[(b * 2 + 0) * EE + e] = d1;
            g_d[(b * 2 + 1) * EE + e] = d2;
        }
    }
}

// ---------------- message passing (unchanged) ----------------
__global__ void k_mp(const float* __restrict__ watt, const float* __restrict__ batt, int dir) {
    int n = blockIdx.x;
    int b = blockIdx.y;
    int tid = threadIdx.x;
    const float* nin  = (dir ? g_nodeB : g_nodeA) + (size_t)b * NN * DD;
    float*       nout = (dir ? g_nodeA : g_nodeB) + (size_t)b * NN * DD;
    const float* eemb = g_edge_emb + (size_t)b * EE * DD;
    const float* dvec = g_d + ((size_t)b * 2 + dir) * EE;
    float*       sb   = g_s + (size_t)b * 2 * EE;

    int cnt = g_deg[n];
    int start = g_off[n];
    float hval = nin[n * DD + tid];
    if (cnt == 0) { nout[n * DD + tid] = hval; return; }

    __shared__ float red[4];

    float c = brsum128(hval * watt[tid], red);
    float battv = batt[0];

    float lmax = -INFINITY;
    for (int i = tid; i < cnt; i += 128) {
        int p = g_csr[start + i];
        int e = (p < EE) ? p : p - EE;
        float s = c + dvec[e] + battv;
        s = (s > 0.0f) ? s : 0.2f * s;
        sb[start + i] = s;
        lmax = fmaxf(lmax, s);
    }
    float m = brmax128(lmax, red);

    float den = 0.0f;
    for (int i = tid; i < cnt; i += 128) {
        float ex = __expf(sb[start + i] - m);
        sb[start + i] = ex;
        den += ex;
    }
    den = brsum128(den, red);
    float inv = 1.0f / den;

    float acc0 = 0.0f, acc1 = 0.0f;
    int i = 0;
    for (; i + 1 < cnt; i += 2) {
        int p0 = g_csr[start + i];
        int p1 = g_csr[start + i + 1];
        int ea = (p0 < EE) ? p0 : p0 - EE;
        int eb = (p1 < EE) ? p1 : p1 - EE;
        float wg0 = sb[start + i];
        float wg1 = sb[start + i + 1];
        acc0 = fmaf(wg0, eemb[(size_t)ea * DD + tid], acc0);
        acc1 = fmaf(wg1, eemb[(size_t)eb * DD + tid], acc1);
    }
    if (i < cnt) {
        int p = g_csr[start + i];
        int e = (p < EE) ? p : p - EE;
        acc0 = fmaf(sb[start + i], eemb[(size_t)e * DD + tid], acc0);
    }
    nout[n * DD + tid] = geluf((acc0 + acc1) * inv);
}

// ---------------- decoder stage 1 (EXACT R8 structure) ----------------
__global__ void __launch_bounds__(256, 1) k_dec1(
    const int* __restrict__ src, const int* __restrict__ dst,
    const float* __restrict__ b1) {
    __shared__ __align__(16) __nv_bfloat16 sAh[8192];
    __shared__ __align__(16) __nv_bfloat16 sAm[8192];
    __shared__ __align__(16) __nv_bfloat16 sBh[2048];
    __shared__ __align__(16) __nv_bfloat16 sBm[2048];
    __shared__ float b1s[256];
    __shared__ int sidx[128], didx[128];

    const u32 Ah = smem_u32(sAh), Am = smem_u32(sAm);
    const u32 Bh = smem_u32(sBh), Bm = smem_u32(sBm);

    int tid = threadIdx.x, lane = tid & 31, warp = tid >> 5;
    int g = lane >> 2, tig = lane & 3;
    int wbase = warp * 16;

    long base = (long)blockIdx.x * 128;
    int b = (int)(base / EE);
    int e0 = (int)(base - (long)b * EE);
    size_t bNN = (size_t)b * NN;

    b1s[tid] = b1[tid];
    if (tid < 128) {
        sidx[tid] = src[e0 + tid];
        didx[tid] = dst[e0 + tid];
    }
    __syncthreads();

    const u32 aRow = (u32)(wbase + (lane & 15));
    const u32 aKH  = (u32)((lane >> 4) & 1) * 16;
    const u32 bRowInPair = (u32)(((lane >> 4) & 1) * 8 + (lane & 7));
    const u32 bKH  = (u32)((lane >> 3) & 1) * 16;
    const int bn = tid >> 3, bu = tid & 7;
    const u32 bSts = sw128((u32)(bn * 128 + bu * 16));

    float d1[128];
    #pragma unroll
    for (int i = 0; i < 128; i++) d1[i] = 0.0f;

    uint4 pvh, pvm;
    {
        size_t gidx = (size_t)bn * 384 + bu * 8;
        pvh = *(const uint4*)(g_w1t_hi + gidx);
        pvm = *(const uint4*)(g_w1t_mid + gidx);
    }

    for (int kc = 0; kc < 6; kc++) {
        for (int j = tid; j < 2048; j += 256) {
            int r = j >> 4, q = j & 15;
            const float* rp;
            int f4;
            if (kc < 2)      { rp = g_nodeA + (bNN + sidx[r]) * DD;              f4 = kc * 16 + q; }
            else if (kc < 4) { rp = g_nodeA + (bNN + didx[r]) * DD;              f4 = (kc - 2) * 16 + q; }
            else             { rp = g_edge_emb + ((size_t)b * EE + e0 + r) * DD; f4 = (kc - 4) * 16 + q; }
            float4 v = ((const float4*)rp)[f4];
            __nv_bfloat16 h0 = __float2bfloat16(v.x), h1 = __float2bfloat16(v.y);
            __nv_bfloat16 h2 = __float2bfloat16(v.z), h3 = __float2bfloat16(v.w);
            __nv_bfloat16 m0 = __float2bfloat16(v.x - __bfloat162float(h0));
            __nv_bfloat16 m1 = __float2bfloat16(v.y - __bfloat162float(h1));
            __nv_bfloat16 m2 = __float2bfloat16(v.z - __bfloat162float(h2));
            __nv_bfloat16 m3 = __float2bfloat16(v.w - __bfloat162float(h3));
            u32 off = sw128((u32)(r * 128 + q * 8));
            STS64P(Ah + off, packbf(h0, h1), packbf(h2, h3));
            STS64P(Am + off, packbf(m0, m1), packbf(m2, m3));
        }
        __syncthreads();

        u32 af[4][8];
        #pragma unroll
        for (int kk = 0; kk < 4; kk++) {
            u32 aAddr = sw128((u32)(aRow * 128 + kk * 32) + aKH);
            ldsm4(af[kk][0], af[kk][1], af[kk][2], af[kk][3], Ah + aAddr);
            ldsm4(af[kk][4], af[kk][5], af[kk][6], af[kk][7], Am + aAddr);
        }

        #pragma unroll
        for (int ng = 0; ng < 8; ng++) {
            STS128P(Bh + bSts, pvh);
            STS128P(Bm + bSts, pvm);
            {
                int np = kc * 8 + ng + 1;
                if (np > 47) np = 47;
                int nkc = np >> 3, nng = np & 7;
                size_t gidx = (size_t)(nng * 32 + bn) * 384 + nkc * 64 + bu * 8;
                pvh = *(const uint4*)(g_w1t_hi + gidx);
                pvm = *(const uint4*)(g_w1t_mid + gidx);
            }
            __syncthreads();
            #pragma unroll
            for (int kk = 0; kk < 4; kk++) {
                #pragma unroll
                for (int nt = 0; nt < 2; nt++) {
                    u32 bAddr = sw128((u32)((nt * 16 + bRowInPair) * 128 + kk * 32) + bKH);
                    u32 bh0, bh1, bh2, bh3, bm0, bm1, bm2, bm3;
                    ldsm4(bh0, bh1, bh2, bh3, Bh + bAddr);
                    ldsm4(bm0, bm1, bm2, bm3, Bm + bAddr);
                    float* dA = d1 + (ng * 4 + nt * 2) * 4;
                    float* dB = dA + 4;
                    mma_bf16(dA, af[kk][0], af[kk][1], af[kk][2], af[kk][3], bh0, bh1);
                    mma_bf16(dA, af[kk][4], af[kk][5], af[kk][6], af[kk][7], bh0, bh1);
                    mma_bf16(dA, af[kk][0], af[kk][1], af[kk][2], af[kk][3], bm0, bm1);
                    mma_bf16(dB, af[kk][0], af[kk][1], af[kk][2], af[kk][3], bh2, bh3);
                    mma_bf16(dB, af[kk][4], af[kk][5], af[kk][6], af[kk][7], bh2, bh3);
                    mma_bf16(dB, af[kk][0], af[kk][1], af[kk][2], af[kk][3], bm2, bm3);
                }
            }
            __syncthreads();
        }
    }

    long r0 = base + wbase + g;
    long r1 = r0 + 8;
    #pragma unroll
    for (int ti = 0; ti < 32; ti++) {
        int c0 = ti * 8 + tig * 2;
        float v0 = geluf(d1[ti * 4 + 0] + b1s[c0]);
        float v1 = geluf(d1[ti * 4 + 1] + b1s[c0 + 1]);
        float v2 = geluf(d1[ti * 4 + 2] + b1s[c0]);
        float v3 = geluf(d1[ti * 4 + 3] + b1s[c0 + 1]);
        __nv_bfloat16 h0 = __float2bfloat16(v0), h1 = __float2bfloat16(v1);
        __nv_bfloat16 h2 = __float2bfloat16(v2), h3 = __float2bfloat16(v3);
        __nv_bfloat16 m0 = __float2bfloat16(v0 - __bfloat162float(h0));
        __nv_bfloat16 m1 = __float2bfloat16(v1 - __bfloat162float(h1));
        __nv_bfloat16 m2 = __float2bfloat16(v2 - __bfloat162float(h2));
        __nv_bfloat16 m3 = __float2bfloat16(v3 - __bfloat162float(h3));
        *(u32*)(g_z1_hi  + r0 * 256 + c0) = packbf(h0, h1);
        *(u32*)(g_z1_mid + r0 * 256 + c0) = packbf(m0, m1);
        *(u32*)(g_z1_hi  + r1 * 256 + c0) = packbf(h2, h3);
        *(u32*)(g_z1_mid + r1 * 256 + c0) = packbf(m2, m3);
    }
}

// ---------------- decoder stage 2 (EXACT R8 structure) ----------------
__global__ void __launch_bounds__(256, 1) k_dec2(
    const float* __restrict__ b2, const float* __restrict__ w3,
    const float* __restrict__ b3, float* __restrict__ out) {
    __shared__ __align__(16) __nv_bfloat16 sAh[8192];
    __shared__ __align__(16) __nv_bfloat16 sAm[8192];
    __shared__ __align__(16) __nv_bfloat16 sBh[2048];
    __shared__ __align__(16) __nv_bfloat16 sBm[2048];
    __shared__ float b2s[128], w3s[128];

    const u32 Ah = smem_u32(sAh), Am = smem_u32(sAm);
    const u32 Bh = smem_u32(sBh), Bm = smem_u32(sBm);

    int tid = threadIdx.x, lane = tid & 31, warp = tid >> 5;
    int g = lane >> 2, tig = lane & 3;
    int wbase = warp * 16;
    long base = (long)blockIdx.x * 128;

    if (tid < 128) { b2s[tid] = b2[tid]; w3s[tid] = w3[tid]; }

    const u32 aRow = (u32)(wbase + (lane & 15));
    const u32 aKH  = (u32)((lane >> 4) & 1) * 16;
    const u32 bRowInPair = (u32)(((lane >> 4) & 1) * 8 + (lane & 7));
    const u32 bKH  = (u32)((lane >> 3) & 1) * 16;
    const int bn = tid >> 3, bu = tid & 7;
    const u32 bSts = sw128((u32)(bn * 128 + bu * 16));

    float d2[64];
    #pragma unroll
    for (int i = 0; i < 64; i++) d2[i] = 0.0f;

    uint4 pvh, pvm;
    {
        size_t gidx = (size_t)bn * 256 + bu * 8;
        pvh = *(const uint4*)(g_w2t_hi + gidx);
        pvm = *(const uint4*)(g_w2t_mid + gidx);
    }

    for (int kc = 0; kc < 4; kc++) {
        __syncthreads();
        for (int j = tid; j < 1024; j += 256) {
            int r = j >> 3, u = j & 7;
            size_t gidx = (size_t)(base + r) * 256 + kc * 64 + u * 8;
            uint4 vh = *(const uint4*)(g_z1_hi + gidx);
            uint4 vm = *(const uint4*)(g_z1_mid + gidx);
            u32 off = sw128((u32)(r * 128 + u * 16));
            STS128P(Ah + off, vh);
            STS128P(Am + off, vm);
        }
        __syncthreads();

        u32 af[4][8];
        #pragma unroll
        for (int kk = 0; kk < 4; kk++) {
            u32 aAddr = sw128((u32)(aRow * 128 + kk * 32) + aKH);
            ldsm4(af[kk][0], af[kk][1], af[kk][2], af[kk][3], Ah + aAddr);
            ldsm4(af[kk][4], af[kk][5], af[kk][6], af[kk][7], Am + aAddr);
        }

        #pragma unroll
        for (int ng = 0; ng < 4; ng++) {
            STS128P(Bh + bSts, pvh);
            STS128P(Bm + bSts, pvm);
            {
                int np = kc * 4 + ng + 1;
                if (np > 15) np = 15;
                int nkc = np >> 2, nng = np & 3;
                size_t gidx = (size_t)(nng * 32 + bn) * 256 + nkc * 64 + bu * 8;
                pvh = *(const uint4*)(g_w2t_hi + gidx);
                pvm = *(const uint4*)(g_w2t_mid + gidx);
            }
            __syncthreads();
            #pragma unroll
            for (int kk = 0; kk < 4; kk++) {
                #pragma unroll
                for (int nt = 0; nt < 2; nt++) {
                    u32 bAddr = sw128((u32)((nt * 16 + bRowInPair) * 128 + kk * 32) + bKH);
                    u32 bh0, bh1, bh2, bh3, bm0, bm1, bm2, bm3;
                    ldsm4(bh0, bh1, bh2, bh3, Bh + bAddr);
                    ldsm4(bm0, bm1, bm2, bm3, Bm + bAddr);
                    float* dA = d2 + (ng * 4 + nt * 2) * 4;
                    float* dB = dA + 4;
                    mma_bf16(dA, af[kk][0], af[kk][1], af[kk][2], af[kk][3], bh0, bh1);
                    mma_bf16(dA, af[kk][4], af[kk][5], af[kk][6], af[kk][7], bh0, bh1);
                    mma_bf16(dA, af[kk][0], af[kk][1], af[kk][2], af[kk][3], bm0, bm1);
                    mma_bf16(dB, af[kk][0], af[kk][1], af[kk][2], af[kk][3], bh2, bh3);
                    mma_bf16(dB, af[kk][4], af[kk][5], af[kk][6], af[kk][7], bh2, bh3);
                    mma_bf16(dB, af[kk][0], af[kk][1], af[kk][2], af[kk][3], bm2, bm3);
                }
            }
            __syncthreads();
        }
    }

    float acc0 = 0.0f, acc1 = 0.0f;
    #pragma unroll
    for (int ti = 0; ti < 16; ti++) {
        int c0 = ti * 8 + tig * 2;
        float w0 = w3s[c0], w1v = w3s[c0 + 1];
        float bb0 = b2s[c0], bb1 = b2s[c0 + 1];
        acc0 = fmaf(geluf(d2[ti * 4 + 0] + bb0), w0, acc0);
        acc0 = fmaf(geluf(d2[ti * 4 + 1] + bb1), w1v, acc0);
        acc1 = fmaf(geluf(d2[ti * 4 + 2] + bb0), w0, acc1);
        acc1 = fmaf(geluf(d2[ti * 4 + 3] + bb1), w1v, acc1);
    }
    acc0 += __shfl_down_sync(0xffffffffu, acc0, 2, 4);
    acc0 += __shfl_down_sync(0xffffffffu, acc0, 1, 4);
    acc1 += __shfl_down_sync(0xffffffffu, acc1, 2, 4);
    acc1 += __shfl_down_sync(0xffffffffu, acc1, 1, 4);
    if (tig == 0) {
        float b3v = b3[0];
        out[base + wbase + g] = acc0 + b3v;
        out[base + wbase + g + 8] = acc1 + b3v;
    }
}

// ---------------- launch ----------------
extern "C" void kernel_launch(void* const* d_in, const int* in_sizes, int n_in,
                              void* d_out, int out_size) {
    const float* feat   = (const float*)d_in[0];
    const float* enc_w1 = (const float*)d_in[1];
    const float* enc_b1 = (const float*)d_in[2];
    const float* enc_g1 = (const float*)d_in[3];
    const float* enc_be1= (const float*)d_in[4];
    const float* enc_w2 = (const float*)d_in[5];
    const float* enc_b2 = (const float*)d_in[6];
    const float* enc_g2 = (const float*)d_in[7];
    const float* enc_be2= (const float*)d_in[8];
    const float* watt1  = (const float*)d_in[9];
    const float* batt1  = (const float*)d_in[10];
    const float* watt2  = (const float*)d_in[11];
    const float* batt2  = (const float*)d_in[12];
    const float* dec_w1 = (const float*)d_in[13];
    const float* dec_b1 = (const float*)d_in[14];
    const float* dec_w2 = (const float*)d_in[15];
    const float* dec_b2 = (const float*)d_in[16];
    const float* dec_w3 = (const float*)d_in[17];
    const float* dec_b3 = (const float*)d_in[18];
    const int*   src    = (const int*)d_in[19];
    const int*   dst    = (const int*)d_in[20];
    float* out = (float*)d_out;

    {
        long n = (long)BB * NN * DD;
        int blocks = (int)((n + 255) / 256);
        k_zero_node_and_counts<<<blocks, 256>>>();
    }

    k_prep<<<(256 * 384 + 255) / 256, 256>>>(dec_w1, dec_w2, enc_w2);

    k_count_deg<<<(EE + 255) / 256, 256>>>(src, dst);

    // 4th launch (ncu-profiled): the encoder
    k_enc<<<(BB * EE) / 64, 128>>>(feat, enc_w1, enc_b1, enc_g1, enc_be1,
                                   enc_b2, enc_g2, enc_be2);

    k_scan<<<1, 1024>>>();
    k_scatter<<<(2 * EE + 255) / 256, 256>>>(src, dst);

    k_edot<<<1480, 256>>>(watt1, watt2);

    k_mp<<<dim3(NN, BB), DD>>>(watt1, batt1, 0);
    k_mp<<<dim3(NN, BB), DD>>>(watt2, batt2, 1);

    k_dec1<<<(BB * EE) / 128, 256>>>(src, dst, dec_b1);
    k_dec2<<<(BB * EE) / 128, 256>>>(dec_b2, dec_w3, dec_b3, out);
}

// round 15
// speedup vs baseline: 1.2543x; 1.1799x over previous
#include <cuda_runtime.h>
#include <cuda_bf16.h>
#include <math.h>
#include <stdint.h>

// Problem constants
#define BB 2
#define EE 160000
#define NN 10000
#define DD 128
#define TE 16

typedef unsigned long long u64;
typedef unsigned int u32;

// ---------------- scratch (device globals) ----------------
__device__ float g_edge_emb[(size_t)BB * EE * DD];
__device__ float g_nodeA[(size_t)BB * NN * DD];
__device__ float g_nodeB[(size_t)BB * NN * DD];
__device__ float g_s[(size_t)BB * 2 * EE];
__device__ float g_d[(size_t)BB * 2 * EE];
__device__ int   g_deg[NN];
__device__ int   g_off[NN + 1];
__device__ int   g_cursor[NN];
__device__ int   g_csr[2 * EE];
// decoder weights, transposed to [N,K] row-major, bf16 hi/mid split
__device__ __align__(16) __nv_bfloat16 g_w1t_hi[256 * 384];
__device__ __align__(16) __nv_bfloat16 g_w1t_mid[256 * 384];
__device__ __align__(16) __nv_bfloat16 g_w2t_hi[128 * 256];
__device__ __align__(16) __nv_bfloat16 g_w2t_mid[128 * 256];
// encoder layer-2 weights, transposed [N=128][K=128], bf16 hi/mid split
__device__ __align__(16) __nv_bfloat16 g_we2t_hi[128 * 128];
__device__ __align__(16) __nv_bfloat16 g_we2t_mid[128 * 128];
// z1 activations, pre-split bf16 hi/mid: [B*E][256]
__device__ __align__(16) __nv_bfloat16 g_z1_hi[(size_t)BB * EE * 256];
__device__ __align__(16) __nv_bfloat16 g_z1_mid[(size_t)BB * EE * 256];

// ---------------- generic helpers ----------------
__device__ __forceinline__ float geluf(float x) { return x * normcdff(x); }

__device__ __forceinline__ u64 pack2(float lo, float hi) {
    u64 r; asm("mov.b64 %0, {%1, %2};" : "=l"(r) : "f"(lo), "f"(hi)); return r;
}
__device__ __forceinline__ u64 fma2(u64 a, u64 b, u64 c) {
    u64 d; asm("fma.rn.f32x2 %0, %1, %2, %3;" : "=l"(d) : "l"(a), "l"(b), "l"(c)); return d;
}
__device__ __forceinline__ float sum2(u64 v) {
    float lo, hi; asm("mov.b64 {%0, %1}, %2;" : "=f"(lo), "=f"(hi) : "l"(v)); return lo + hi;
}

__device__ __forceinline__ float brsum128(float v, float* red) {
    int lane = threadIdx.x & 31, w = threadIdx.x >> 5;
    #pragma unroll
    for (int o = 16; o; o >>= 1) v += __shfl_down_sync(0xffffffffu, v, o);
    if (lane == 0) red[w] = v;
    __syncthreads();
    float s = red[0] + red[1] + red[2] + red[3];
    __syncthreads();
    return s;
}
__device__ __forceinline__ float brmax128(float v, float* red) {
    int lane = threadIdx.x & 31, w = threadIdx.x >> 5;
    #pragma unroll
    for (int o = 16; o; o >>= 1) v = fmaxf(v, __shfl_down_sync(0xffffffffu, v, o));
    if (lane == 0) red[w] = v;
    __syncthreads();
    float s = fmaxf(fmaxf(red[0], red[1]), fmaxf(red[2], red[3]));
    __syncthreads();
    return s;
}

// ---------------- mma.sync / ldmatrix helpers ----------------
__device__ __forceinline__ u32 smem_u32(const void* p) {
    u32 a; asm("{ .reg .u64 t; cvta.to.shared.u64 t, %1; cvt.u32.u64 %0, t; }" : "=r"(a) : "l"(p));
    return a;
}
__device__ __forceinline__ void ldsm4(u32& r0, u32& r1, u32& r2, u32& r3, u32 addr) {
    asm volatile("ldmatrix.sync.aligned.m8n8.x4.shared.b16 {%0,%1,%2,%3}, [%4];"
        : "=r"(r0), "=r"(r1), "=r"(r2), "=r"(r3) : "r"(addr));
}
__device__ __forceinline__ void mma_bf16(float* d, u32 a0, u32 a1, u32 a2, u32 a3, u32 b0, u32 b1) {
    asm volatile("mma.sync.aligned.m16n8k16.row.col.f32.bf16.bf16.f32 "
        "{%0,%1,%2,%3}, {%4,%5,%6,%7}, {%8,%9}, {%0,%1,%2,%3};"
        : "+f"(d[0]), "+f"(d[1]), "+f"(d[2]), "+f"(d[3])
        : "r"(a0), "r"(a1), "r"(a2), "r"(a3), "r"(b0), "r"(b1));
}
#define STS16(a, v)     asm volatile("st.shared.u16 [%0], %1;" :: "r"(a), "h"(v) : "memory")
#define STS64P(a, x, y) asm volatile("st.shared.v2.b32 [%0], {%1, %2};" :: "r"(a), "r"(x), "r"(y) : "memory")
#define STS128P(a, v)   asm volatile("st.shared.v4.b32 [%0], {%1, %2, %3, %4};" \
                            :: "r"(a), "r"((v).x), "r"((v).y), "r"((v).z), "r"((v).w) : "memory")
__device__ __forceinline__ u32 sw128(u32 off) { return off ^ ((off >> 3) & 0x70); }
__device__ __forceinline__ u32 packbf(__nv_bfloat16 a, __nv_bfloat16 b) {
    return ((u32)__bfloat16_as_ushort(b) << 16) | (u32)__bfloat16_as_ushort(a);
}

// ---------------- init ----------------
__global__ void k_zero_node_and_counts() {
    long i = (long)blockIdx.x * blockDim.x + threadIdx.x;
    long nNode = (long)BB * NN * DD;
    if (i < nNode) g_nodeA[i] = 0.0f;
    if (i < NN) { g_deg[i] = 0; g_cursor[i] = 0; }
}

// ---------------- CSR build ----------------
__global__ void k_count_deg(const int* __restrict__ src, const int* __restrict__ dst) {
    int i = blockIdx.x * blockDim.x + threadIdx.x;
    if (i < EE) {
        atomicAdd(&g_deg[src[i]], 1);
        atomicAdd(&g_deg[dst[i]], 1);
    }
}

__global__ void k_scan() {
    __shared__ int sums[1024];
    int t = threadIdx.x;
    const int chunk = (NN + 1023) / 1024;
    int start = t * chunk;
    int end = min(start + chunk, NN);
    int s = 0;
    for (int i = start; i < end; i++) s += g_deg[i];
    sums[t] = s;
    __syncthreads();
    for (int d = 1; d < 1024; d <<= 1) {
        int v = (t >= d) ? sums[t - d] : 0;
        __syncthreads();
        sums[t] += v;
        __syncthreads();
    }
    int run = (t > 0) ? sums[t - 1] : 0;
    for (int i = start; i < end; i++) { g_off[i] = run; run += g_deg[i]; }
    if (t == 1023) g_off[NN] = sums[1023];
}

__global__ void k_scatter(const int* __restrict__ src, const int* __restrict__ dst) {
    int p = blockIdx.x * blockDim.x + threadIdx.x;
    if (p < 2 * EE) {
        int node = (p < EE) ? src[p] : dst[p - EE];
        int pos = g_off[node] + atomicAdd(&g_cursor[node], 1);
        g_csr[pos] = p;
    }
}

// ---------------- weight prep: transpose + bf16 hi/mid split ----------------
__global__ void k_prep(const float* __restrict__ w1, const float* __restrict__ w2,
                       const float* __restrict__ we2) {
    int i = blockIdx.x * blockDim.x + threadIdx.x;
    if (i < 256 * 384) {
        int n = i / 384, k = i - n * 384;
        float v = w1[(size_t)k * 256 + n];
        __nv_bfloat16 h = __float2bfloat16(v);
        g_w1t_hi[i] = h;
        g_w1t_mid[i] = __float2bfloat16(v - __bfloat162float(h));
    }
    if (i < 128 * 256) {
        int n = i / 256, k = i - n * 256;
        float v = w2[(size_t)k * 128 + n];
        __nv_bfloat16 h = __float2bfloat16(v);
        g_w2t_hi[i] = h;
        g_w2t_mid[i] = __float2bfloat16(v - __bfloat162float(h));
    }
    if (i < 128 * 128) {
        int n = i / 128, k = i - n * 128;
        float v = we2[(size_t)k * 128 + n];
        __nv_bfloat16 h = __float2bfloat16(v);
        g_we2t_hi[i] = h;
        g_we2t_mid[i] = __float2bfloat16(v - __bfloat162float(h));
    }
}

// ---------------- encoder (unchanged from R14, launch_bounds(128,3)) ----------------
__global__ void __launch_bounds__(128, 3) k_enc(
    const float* __restrict__ feat,
    const float* __restrict__ w1, const float* __restrict__ b1,
    const float* __restrict__ g1, const float* __restrict__ be1,
    const float* __restrict__ b2, const float* __restrict__ g2,
    const float* __restrict__ be2) {
    __shared__ __align__(16) __nv_bfloat16 sAh[8192];
    __shared__ __align__(16) __nv_bfloat16 sAm[8192];
    __shared__ __align__(16) __nv_bfloat16 sBh[2048];
    __shared__ __align__(16) __nv_bfloat16 sBm[2048];
    __shared__ __align__(16) float xs[8][24];
    __shared__ float b2s[128], g2s[128], be2s[128];
    __shared__ float g1s[128], be1s[128];

    const u32 Ah = smem_u32(sAh), Am = smem_u32(sAm);
    const u32 Bh = smem_u32(sBh), Bm = smem_u32(sBm);

    int tid = threadIdx.x, lane = tid & 31, warp = tid >> 5;
    long base = (long)blockIdx.x * 64;

    b2s[tid] = b2[tid];
    g2s[tid] = g2[tid];
    be2s[tid] = be2[tid];
    g1s[tid] = g1[tid];
    be1s[tid] = be1[tid];

    int d = tid;
    u64 wp[12];
    #pragma unroll
    for (int k = 0; k < 12; k++)
        wp[k] = pack2(w1[(2 * k) * DD + d], w1[(2 * k + 1) * DD + d]);
    float b1v = b1[d];

    // ---------- phase 1 ----------
    float* fs = (float*)sBh;
    for (int it = 0; it < 8; it++) {
        __syncthreads();
        for (int i = tid; i < 48; i += 128) {
            int t = i / 6, j = i % 6;
            ((float4*)xs[t])[j] = ((const float4*)(feat + (base + it * 8 + t) * 24))[j];
        }
        __syncthreads();

        float acc[8];
        #pragma unroll
        for (int t = 0; t < 8; t++) {
            u64 a = pack2(b1v, 0.0f);
            #pragma unroll
            for (int j = 0; j < 6; j++) {
                ulonglong2 xv = ((const ulonglong2*)xs[t])[j];
                a = fma2(xv.x, wp[2 * j], a);
                a = fma2(xv.y, wp[2 * j + 1], a);
            }
            acc[t] = sum2(a);
        }
        #pragma unroll
        for (int t = 0; t < 8; t++) fs[t * 128 + d] = acc[t];
        __syncthreads();

        #pragma unroll
        for (int tt = 0; tt < 2; tt++) {
            int t = warp * 2 + tt;
            float v[4];
            #pragma unroll
            for (int r = 0; r < 4; r++) v[r] = fs[t * 128 + lane + 32 * r];
            float s = v[0] + v[1] + v[2] + v[3];
            float q = v[0] * v[0] + v[1] * v[1] + v[2] * v[2] + v[3] * v[3];
            #pragma unroll
            for (int o = 16; o; o >>= 1) {
                s += __shfl_xor_sync(0xffffffffu, s, o);
                q += __shfl_xor_sync(0xffffffffu, q, o);
            }
            float mu = s * (1.0f / DD);
            float rstd = rsqrtf(q * (1.0f / DD) - mu * mu + 1e-5f);
            u32 row = (u32)(it * 8 + t);
            #pragma unroll
            for (int r = 0; r < 4; r++) {
                int c = lane + 32 * r;
                float vv = geluf((v[r] - mu) * rstd * g1s[c] + be1s[c]);
                __nv_bfloat16 h = __float2bfloat16(vv);
                __nv_bfloat16 m = __float2bfloat16(vv - __bfloat162float(h));
                u32 off = ((u32)(c >> 6)) * 8192 + sw128(row * 128 + (u32)(c & 63) * 2);
                STS16(Ah + off, __bfloat16_as_ushort(h));
                STS16(Am + off, __bfloat16_as_ushort(m));
            }
        }
    }
    __syncthreads();

    // ---------- phase 2 ----------
    int g = lane >> 2, tig = lane & 3;
    int wbase = warp * 16;
    const u32 aRow = (u32)(wbase + (lane & 15));
    const u32 aKH  = (u32)((lane >> 4) & 1) * 16;
    const u32 bRowInPair = (u32)(((lane >> 4) & 1) * 8 + (lane & 7));
    const u32 bKH  = (u32)((lane >> 3) & 1) * 16;
    const int bn = tid >> 2, bu = (tid & 3) * 2;
    const u32 bSts0 = sw128((u32)(bn * 128 + bu * 16));
    const u32 bSts1 = sw128((u32)(bn * 128 + (bu + 1) * 16));

    float dd[64];
    #pragma unroll
    for (int i = 0; i < 64; i++) dd[i] = 0.0f;

    uint4 ph0, ph1, pm0, pm1;
    {
        size_t gi = (size_t)bn * 128 + bu * 8;
        ph0 = *(const uint4*)(g_we2t_hi + gi);
        ph1 = *(const uint4*)(g_we2t_hi + gi + 8);
        pm0 = *(const uint4*)(g_we2t_mid + gi);
        pm1 = *(const uint4*)(g_we2t_mid + gi + 8);
    }

    for (int kc = 0; kc < 2; kc++) {
        u32 af[4][8];
        #pragma unroll
        for (int kk = 0; kk < 4; kk++) {
            u32 aAddr = (u32)kc * 8192 + sw128((u32)(aRow * 128 + kk * 32) + aKH);
            ldsm4(af[kk][0], af[kk][1], af[kk][2], af[kk][3], Ah + aAddr);
            ldsm4(af[kk][4], af[kk][5], af[kk][6], af[kk][7], Am + aAddr);
        }

        #pragma unroll
        for (int ng = 0; ng < 4; ng++) {
            STS128P(Bh + bSts0, ph0);
            STS128P(Bh + bSts1, ph1);
            STS128P(Bm + bSts0, pm0);
            STS128P(Bm + bSts1, pm1);
            {
                int np = kc * 4 + ng + 1;
                if (np > 7) np = 7;
                int nkc = np >> 2, nng = np & 3;
                size_t gi = (size_t)(nng * 32 + bn) * 128 + nkc * 64 + bu * 8;
                ph0 = *(const uint4*)(g_we2t_hi + gi);
                ph1 = *(const uint4*)(g_we2t_hi + gi + 8);
                pm0 = *(const uint4*)(g_we2t_mid + gi);
                pm1 = *(const uint4*)(g_we2t_mid + gi + 8);
            }
            __syncthreads();
            #pragma unroll
            for (int kk = 0; kk < 4; kk++) {
                #pragma unroll
                for (int nt = 0; nt < 2; nt++) {
                    u32 bAddr = sw128((u32)((nt * 16 + bRowInPair) * 128 + kk * 32) + bKH);
                    u32 bh0, bh1, bh2, bh3, bm0, bm1, bm2, bm3;
                    ldsm4(bh0, bh1, bh2, bh3, Bh + bAddr);
                    ldsm4(bm0, bm1, bm2, bm3, Bm + bAddr);
                    float* dA = dd + (ng * 4 + nt * 2) * 4;
                    float* dB = dA + 4;
                    mma_bf16(dA, af[kk][0], af[kk][1], af[kk][2], af[kk][3], bh0, bh1);
                    mma_bf16(dA, af[kk][4], af[kk][5], af[kk][6], af[kk][7], bh0, bh1);
                    mma_bf16(dA, af[kk][0], af[kk][1], af[kk][2], af[kk][3], bm0, bm1);
                    mma_bf16(dB, af[kk][0], af[kk][1], af[kk][2], af[kk][3], bh2, bh3);
                    mma_bf16(dB, af[kk][4], af[kk][5], af[kk][6], af[kk][7], bh2, bh3);
                    mma_bf16(dB, af[kk][0], af[kk][1], af[kk][2], af[kk][3], bm2, bm3);
                }
            }
            __syncthreads();
        }
    }

    // ---------- phase 3 ----------
    float s0 = 0.0f, q0 = 0.0f, s1 = 0.0f, q1 = 0.0f;
    #pragma unroll
    for (int ti = 0; ti < 16; ti++) {
        int c0 = ti * 8 + tig * 2;
        float v0 = dd[ti * 4 + 0] + b2s[c0];
        float v1 = dd[ti * 4 + 1] + b2s[c0 + 1];
        float v2 = dd[ti * 4 + 2] + b2s[c0];
        float v3 = dd[ti * 4 + 3] + b2s[c0 + 1];
        dd[ti * 4 + 0] = v0; dd[ti * 4 + 1] = v1;
        dd[ti * 4 + 2] = v2; dd[ti * 4 + 3] = v3;
        s0 += v0 + v1; q0 += v0 * v0 + v1 * v1;
        s1 += v2 + v3; q1 += v2 * v2 + v3 * v3;
    }
    #pragma unroll
    for (int o = 1; o < 4; o <<= 1) {
        s0 += __shfl_xor_sync(0xffffffffu, s0, o, 4);
        q0 += __shfl_xor_sync(0xffffffffu, q0, o, 4);
        s1 += __shfl_xor_sync(0xffffffffu, s1, o, 4);
        q1 += __shfl_xor_sync(0xffffffffu, q1, o, 4);
    }
    float mu0 = s0 * (1.0f / DD), mu1 = s1 * (1.0f / DD);
    float rs0 = rsqrtf(q0 * (1.0f / DD) - mu0 * mu0 + 1e-5f);
    float rs1 = rsqrtf(q1 * (1.0f / DD) - mu1 * mu1 + 1e-5f);
    float* o0 = g_edge_emb + (base + wbase + g) * DD;
    float* o1 = g_edge_emb + (base + wbase + g + 8) * DD;
    #pragma unroll
    for (int ti = 0; ti < 16; ti++) {
        int c0 = ti * 8 + tig * 2;
        float2 a, c;
        a.x = (dd[ti * 4 + 0] - mu0) * rs0 * g2s[c0]     + be2s[c0];
        a.y = (dd[ti * 4 + 1] - mu0) * rs0 * g2s[c0 + 1] + be2s[c0 + 1];
        c.x = (dd[ti * 4 + 2] - mu1) * rs1 * g2s[c0]     + be2s[c0];
        c.y = (dd[ti * 4 + 3] - mu1) * rs1 * g2s[c0 + 1] + be2s[c0 + 1];
        *(float2*)(o0 + c0) = a;
        *(float2*)(o1 + c0) = c;
    }
}

// ---------------- per-edge attention dots ----------------
__global__ void __launch_bounds__(256) k_edot(const float* __restrict__ watt1,
                                              const float* __restrict__ watt2) {
    int lane = threadIdx.x & 31;
    long gw = (long)blockIdx.x * 8 + (threadIdx.x >> 5);
    long nwarps = (long)gridDim.x * 8;
    float w1r[4], w2r[4];
    #pragma unroll
    for (int r = 0; r < 4; r++) {
        w1r[r] = watt1[128 + lane + 32 * r];
        w2r[r] = watt2[128 + lane + 32 * r];
    }
    for (long idx = gw; idx < (long)BB * EE; idx += nwarps) {
        const float* row = g_edge_emb + idx * DD;
        float v0 = row[lane], v1 = row[lane + 32], v2 = row[lane + 64], v3 = row[lane + 96];
        float d1 = fmaf(v0, w1r[0], fmaf(v1, w1r[1], fmaf(v2, w1r[2], v3 * w1r[3])));
        float d2 = fmaf(v0, w2r[0], fmaf(v1, w2r[1], fmaf(v2, w2r[2], v3 * w2r[3])));
        #pragma unroll
        for (int o = 16; o; o >>= 1) {
            d1 += __shfl_down_sync(0xffffffffu, d1, o);
            d2 += __shfl_down_sync(0xffffffffu, d2, o);
        }
        if (lane == 0) {
            long b = idx / EE, e = idx - b * EE;
            g_d[(b * 2 + 0) * EE + e] = d1;
            g_d[(b * 2 + 1) * EE + e] = d2;
        }
    }
}

// ---------------- message passing (unchanged) ----------------
__global__ void k_mp(const float* __restrict__ watt, const float* __restrict__ batt, int dir) {
    int n = blockIdx.x;
    int b = blockIdx.y;
    int tid = threadIdx.x;
    const float* nin  = (dir ? g_nodeB : g_nodeA) + (size_t)b * NN * DD;
    float*       nout = (dir ? g_nodeA : g_nodeB) + (size_t)b * NN * DD;
    const float* eemb = g_edge_emb + (size_t)b * EE * DD;
    const float* dvec = g_d + ((size_t)b * 2 + dir) * EE;
    float*       sb   = g_s + (size_t)b * 2 * EE;

    int cnt = g_deg[n];
    int start = g_off[n];
    float hval = nin[n * DD + tid];
    if (cnt == 0) { nout[n * DD + tid] = hval; return; }

    __shared__ float red[4];

    float c = brsum128(hval * watt[tid], red);
    float battv = batt[0];

    float lmax = -INFINITY;
    for (int i = tid; i < cnt; i += 128) {
        int p = g_csr[start + i];
        int e = (p < EE) ? p : p - EE;
        float s = c + dvec[e] + battv;
        s = (s > 0.0f) ? s : 0.2f * s;
        sb[start + i] = s;
        lmax = fmaxf(lmax, s);
    }
    float m = brmax128(lmax, red);

    float den = 0.0f;
    for (int i = tid; i < cnt; i += 128) {
        float ex = __expf(sb[start + i] - m);
        sb[start + i] = ex;
        den += ex;
    }
    den = brsum128(den, red);
    float inv = 1.0f / den;

    float acc0 = 0.0f, acc1 = 0.0f;
    int i = 0;
    for (; i + 1 < cnt; i += 2) {
        int p0 = g_csr[start + i];
        int p1 = g_csr[start + i + 1];
        int ea = (p0 < EE) ? p0 : p0 - EE;
        int eb = (p1 < EE) ? p1 : p1 - EE;
        float wg0 = sb[start + i];
        float wg1 = sb[start + i + 1];
        acc0 = fmaf(wg0, eemb[(size_t)ea * DD + tid], acc0);
        acc1 = fmaf(wg1, eemb[(size_t)eb * DD + tid], acc1);
    }
    if (i < cnt) {
        int p = g_csr[start + i];
        int e = (p < EE) ? p : p - EE;
        acc0 = fmaf(sb[start + i], eemb[(size_t)e * DD + tid], acc0);
    }
    nout[n * DD + tid] = geluf((acc0 + acc1) * inv);
}

// ---------------- decoder stage 1 (R8 structure + A register prefetch) ----------------
__global__ void __launch_bounds__(256, 1) k_dec1(
    const int* __restrict__ src, const int* __restrict__ dst,
    const float* __restrict__ b1) {
    __shared__ __align__(16) __nv_bfloat16 sAh[8192];
    __shared__ __align__(16) __nv_bfloat16 sAm[8192];
    __shared__ __align__(16) __nv_bfloat16 sBh[2048];
    __shared__ __align__(16) __nv_bfloat16 sBm[2048];
    __shared__ float b1s[256];
    __shared__ int sidx[128], didx[128];

    const u32 Ah = smem_u32(sAh), Am = smem_u32(sAm);
    const u32 Bh = smem_u32(sBh), Bm = smem_u32(sBm);

    int tid = threadIdx.x, lane = tid & 31, warp = tid >> 5;
    int g = lane >> 2, tig = lane & 3;
    int wbase = warp * 16;

    long base = (long)blockIdx.x * 128;
    int b = (int)(base / EE);
    int e0 = (int)(base - (long)b * EE);
    size_t bNN = (size_t)b * NN;

    b1s[tid] = b1[tid];
    if (tid < 128) {
        sidx[tid] = src[e0 + tid];
        didx[tid] = dst[e0 + tid];
    }
    __syncthreads();

    const u32 aRow = (u32)(wbase + (lane & 15));
    const u32 aKH  = (u32)((lane >> 4) & 1) * 16;
    const u32 bRowInPair = (u32)(((lane >> 4) & 1) * 8 + (lane & 7));
    const u32 bKH  = (u32)((lane >> 3) & 1) * 16;
    const int bn = tid >> 3, bu = tid & 7;
    const u32 bSts = sw128((u32)(bn * 128 + bu * 16));

    float d1[128];
    #pragma unroll
    for (int i = 0; i < 128; i++) d1[i] = 0.0f;

    uint4 pvh, pvm;
    {
        size_t gidx = (size_t)bn * 384 + bu * 8;
        pvh = *(const uint4*)(g_w1t_hi + gidx);
        pvm = *(const uint4*)(g_w1t_mid + gidx);
    }

    // A prefetch buffer: 8 float4 per thread (next kc's chunk)
    float4 av[8];
    #pragma unroll
    for (int i = 0; i < 8; i++) {
        int j = tid + 256 * i;
        int r = j >> 4, q = j & 15;
        av[i] = ((const float4*)(g_nodeA + (bNN + sidx[r]) * DD))[q];   // kc=0
    }

    for (int kc = 0; kc < 6; kc++) {
        // store prefetched A chunk (convert + split); prior readers protected
        // by trailing sync of previous kc's ng loop (or initial sync).
        #pragma unroll
        for (int i = 0; i < 8; i++) {
            int j = tid + 256 * i;
            int r = j >> 4, q = j & 15;
            float4 v = av[i];
            __nv_bfloat16 h0 = __float2bfloat16(v.x), h1 = __float2bfloat16(v.y);
            __nv_bfloat16 h2 = __float2bfloat16(v.z), h3 = __float2bfloat16(v.w);
            __nv_bfloat16 m0 = __float2bfloat16(v.x - __bfloat162float(h0));
            __nv_bfloat16 m1 = __float2bfloat16(v.y - __bfloat162float(h1));
            __nv_bfloat16 m2 = __float2bfloat16(v.z - __bfloat162float(h2));
            __nv_bfloat16 m3 = __float2bfloat16(v.w - __bfloat162float(h3));
            u32 off = sw128((u32)(r * 128 + q * 8));
            STS64P(Ah + off, packbf(h0, h1), packbf(h2, h3));
            STS64P(Am + off, packbf(m0, m1), packbf(m2, m3));
        }
        // prefetch next kc's chunk (overlaps this kc's mma phase)
        if (kc < 5) {
            int nk = kc + 1;
            #pragma unroll
            for (int i = 0; i < 8; i++) {
                int j = tid + 256 * i;
                int r = j >> 4, q = j & 15;
                const float* rp;
                int f4;
                if (nk < 2)      { rp = g_nodeA + (bNN + sidx[r]) * DD;              f4 = nk * 16 + q; }
                else if (nk < 4) { rp = g_nodeA + (bNN + didx[r]) * DD;              f4 = (nk - 2) * 16 + q; }
                else             { rp = g_edge_emb + ((size_t)b * EE + e0 + r) * DD; f4 = (nk - 4) * 16 + q; }
                av[i] = ((const float4*)rp)[f4];
            }
        }
        __syncthreads();   // A visible

        u32 af[4][8];
        #pragma unroll
        for (int kk = 0; kk < 4; kk++) {
            u32 aAddr = sw128((u32)(aRow * 128 + kk * 32) + aKH);
            ldsm4(af[kk][0], af[kk][1], af[kk][2], af[kk][3], Ah + aAddr);
            ldsm4(af[kk][4], af[kk][5], af[kk][6], af[kk][7], Am + aAddr);
        }

        #pragma unroll
        for (int ng = 0; ng < 8; ng++) {
            STS128P(Bh + bSts, pvh);
            STS128P(Bm + bSts, pvm);
            {
                int np = kc * 8 + ng + 1;
                if (np > 47) np = 47;
                int nkc = np >> 3, nng = np & 7;
                size_t gidx = (size_t)(nng * 32 + bn) * 384 + nkc * 64 + bu * 8;
                pvh = *(const uint4*)(g_w1t_hi + gidx);
                pvm = *(const uint4*)(g_w1t_mid + gidx);
            }
            __syncthreads();
            #pragma unroll
            for (int kk = 0; kk < 4; kk++) {
                #pragma unroll
                for (int nt = 0; nt < 2; nt++) {
                    u32 bAddr = sw128((u32)((nt * 16 + bRowInPair) * 128 + kk * 32) + bKH);
                    u32 bh0, bh1, bh2, bh3, bm0, bm1, bm2, bm3;
                    ldsm4(bh0, bh1, bh2, bh3, Bh + bAddr);
                    ldsm4(bm0, bm1, bm2, bm3, Bm + bAddr);
                    float* dA = d1 + (ng * 4 + nt * 2) * 4;
                    float* dB = dA + 4;
                    mma_bf16(dA, af[kk][0], af[kk][1], af[kk][2], af[kk][3], bh0, bh1);
                    mma_bf16(dA, af[kk][4], af[kk][5], af[kk][6], af[kk][7], bh0, bh1);
                    mma_bf16(dA, af[kk][0], af[kk][1], af[kk][2], af[kk][3], bm0, bm1);
                    mma_bf16(dB, af[kk][0], af[kk][1], af[kk][2], af[kk][3], bh2, bh3);
                    mma_bf16(dB, af[kk][4], af[kk][5], af[kk][6], af[kk][7], bh2, bh3);
                    mma_bf16(dB, af[kk][0], af[kk][1], af[kk][2], af[kk][3], bm2, bm3);
                }
            }
            __syncthreads();
        }
    }

    long r0 = base + wbase + g;
    long r1 = r0 + 8;
    #pragma unroll
    for (int ti = 0; ti < 32; ti++) {
        int c0 = ti * 8 + tig * 2;
        float v0 = geluf(d1[ti * 4 + 0] + b1s[c0]);
        float v1 = geluf(d1[ti * 4 + 1] + b1s[c0 + 1]);
        float v2 = geluf(d1[ti * 4 + 2] + b1s[c0]);
        float v3 = geluf(d1[ti * 4 + 3] + b1s[c0 + 1]);
        __nv_bfloat16 h0 = __float2bfloat16(v0), h1 = __float2bfloat16(v1);
        __nv_bfloat16 h2 = __float2bfloat16(v2), h3 = __float2bfloat16(v3);
        __nv_bfloat16 m0 = __float2bfloat16(v0 - __bfloat162float(h0));
        __nv_bfloat16 m1 = __float2bfloat16(v1 - __bfloat162float(h1));
        __nv_bfloat16 m2 = __float2bfloat16(v2 - __bfloat162float(h2));
        __nv_bfloat16 m3 = __float2bfloat16(v3 - __bfloat162float(h3));
        *(u32*)(g_z1_hi  + r0 * 256 + c0) = packbf(h0, h1);
        *(u32*)(g_z1_mid + r0 * 256 + c0) = packbf(m0, m1);
        *(u32*)(g_z1_hi  + r1 * 256 + c0) = packbf(h2, h3);
        *(u32*)(g_z1_mid + r1 * 256 + c0) = packbf(m2, m3);
    }
}

// ---------------- decoder stage 2 (R8 structure + A register prefetch) ----------------
__global__ void __launch_bounds__(256, 1) k_dec2(
    const float* __restrict__ b2, const float* __restrict__ w3,
    const float* __restrict__ b3, float* __restrict__ out) {
    __shared__ __align__(16) __nv_bfloat16 sAh[8192];
    __shared__ __align__(16) __nv_bfloat16 sAm[8192];
    __shared__ __align__(16) __nv_bfloat16 sBh[2048];
    __shared__ __align__(16) __nv_bfloat16 sBm[2048];
    __shared__ float b2s[128], w3s[128];

    const u32 Ah = smem_u32(sAh), Am = smem_u32(sAm);
    const u32 Bh = smem_u32(sBh), Bm = smem_u32(sBm);

    int tid = threadIdx.x, lane = tid & 31, warp = tid >> 5;
    int g = lane >> 2, tig = lane & 3;
    int wbase = warp * 16;
    long base = (long)blockIdx.x * 128;

    if (tid < 128) { b2s[tid] = b2[tid]; w3s[tid] = w3[tid]; }

    const u32 aRow = (u32)(wbase + (lane & 15));
    const u32 aKH  = (u32)((lane >> 4) & 1) * 16;
    const u32 bRowInPair = (u32)(((lane >> 4) & 1) * 8 + (lane & 7));
    const u32 bKH  = (u32)((lane >> 3) & 1) * 16;
    const int bn = tid >> 3, bu = tid & 7;
    const u32 bSts = sw128((u32)(bn * 128 + bu * 16));

    float d2[64];
    #pragma unroll
    for (int i = 0; i < 64; i++) d2[i] = 0.0f;

    uint4 pvh, pvm;
    {
        size_t gidx = (size_t)bn * 256 + bu * 8;
        pvh = *(const uint4*)(g_w2t_hi + gidx);
        pvm = *(const uint4*)(g_w2t_mid + gidx);
    }

    // A prefetch: 4 (hi,mid) uint4 pairs per thread
    uint4 avh[4], avm[4];
    #pragma unroll
    for (int i = 0; i < 4; i++) {
        int j = tid + 256 * i;
        int r = j >> 3, u = j & 7;
        size_t gidx = (size_t)(base + r) * 256 + u * 8;    // kc=0
        avh[i] = *(const uint4*)(g_z1_hi + gidx);
        avm[i] = *(const uint4*)(g_z1_mid + gidx);
    }

    for (int kc = 0; kc < 4; kc++) {
        __syncthreads();   // prior readers of sA done
        #pragma unroll
        for (int i = 0; i < 4; i++) {
            int j = tid + 256 * i;
            int r = j >> 3, u = j & 7;
            u32 off = sw128((u32)(r * 128 + u * 16));
            STS128P(Ah + off, avh[i]);
            STS128P(Am + off, avm[i]);
        }
        if (kc < 3) {
            int nk = kc + 1;
            #pragma unroll
            for (int i = 0; i < 4; i++) {
                int j = tid + 256 * i;
                int r = j >> 3, u = j & 7;
                size_t gidx = (size_t)(base + r) * 256 + nk * 64 + u * 8;
                avh[i] = *(const uint4*)(g_z1_hi + gidx);
                avm[i] = *(const uint4*)(g_z1_mid + gidx);
            }
        }
        __syncthreads();

        u32 af[4][8];
        #pragma unroll
        for (int kk = 0; kk < 4; kk++) {
            u32 aAddr = sw128((u32)(aRow * 128 + kk * 32) + aKH);
            ldsm4(af[kk][0], af[kk][1], af[kk][2], af[kk][3], Ah + aAddr);
            ldsm4(af[kk][4], af[kk][5], af[kk][6], af[kk][7], Am + aAddr);
        }

        #pragma unroll
        for (int ng = 0; ng < 4; ng++) {
            STS128P(Bh + bSts, pvh);
            STS128P(Bm + bSts, pvm);
            {
                int np = kc * 4 + ng + 1;
                if (np > 15) np = 15;
                int nkc = np >> 2, nng = np & 3;
                size_t gidx = (size_t)(nng * 32 + bn) * 256 + nkc * 64 + bu * 8;
                pvh = *(const uint4*)(g_w2t_hi + gidx);
                pvm = *(const uint4*)(g_w2t_mid + gidx);
            }
            __syncthreads();
            #pragma unroll
            for (int kk = 0; kk < 4; kk++) {
                #pragma unroll
                for (int nt = 0; nt < 2; nt++) {
                    u32 bAddr = sw128((u32)((nt * 16 + bRowInPair) * 128 + kk * 32) + bKH);
                    u32 bh0, bh1, bh2, bh3, bm0, bm1, bm2, bm3;
                    ldsm4(bh0, bh1, bh2, bh3, Bh + bAddr);
                    ldsm4(bm0, bm1, bm2, bm3, Bm + bAddr);
                    float* dA = d2 + (ng * 4 + nt * 2) * 4;
                    float* dB = dA + 4;
                    mma_bf16(dA, af[kk][0], af[kk][1], af[kk][2], af[kk][3], bh0, bh1);
                    mma_bf16(dA, af[kk][4], af[kk][5], af[kk][6], af[kk][7], bh0, bh1);
                    mma_bf16(dA, af[kk][0], af[kk][1], af[kk][2], af[kk][3], bm0, bm1);
                    mma_bf16(dB, af[kk][0], af[kk][1], af[kk][2], af[kk][3], bh2, bh3);
                    mma_bf16(dB, af[kk][4], af[kk][5], af[kk][6], af[kk][7], bh2, bh3);
                    mma_bf16(dB, af[kk][0], af[kk][1], af[kk][2], af[kk][3], bm2, bm3);
                }
            }
            __syncthreads();
        }
    }

    float acc0 = 0.0f, acc1 = 0.0f;
    #pragma unroll
    for (int ti = 0; ti < 16; ti++) {
        int c0 = ti * 8 + tig * 2;
        float w0 = w3s[c0], w1v = w3s[c0 + 1];
        float bb0 = b2s[c0], bb1 = b2s[c0 + 1];
        acc0 = fmaf(geluf(d2[ti * 4 + 0] + bb0), w0, acc0);
        acc0 = fmaf(geluf(d2[ti * 4 + 1] + bb1), w1v, acc0);
        acc1 = fmaf(geluf(d2[ti * 4 + 2] + bb0), w0, acc1);
        acc1 = fmaf(geluf(d2[ti * 4 + 3] + bb1), w1v, acc1);
    }
    acc0 += __shfl_down_sync(0xffffffffu, acc0, 2, 4);
    acc0 += __shfl_down_sync(0xffffffffu, acc0, 1, 4);
    acc1 += __shfl_down_sync(0xffffffffu, acc1, 2, 4);
    acc1 += __shfl_down_sync(0xffffffffu, acc1, 1, 4);
    if (tig == 0) {
        float b3v = b3[0];
        out[base + wbase + g] = acc0 + b3v;
        out[base + wbase + g + 8] = acc1 + b3v;
    }
}

// ---------------- launch ----------------
extern "C" void kernel_launch(void* const* d_in, const int* in_sizes, int n_in,
                              void* d_out, int out_size) {
    const float* feat   = (const float*)d_in[0];
    const float* enc_w1 = (const float*)d_in[1];
    const float* enc_b1 = (const float*)d_in[2];
    const float* enc_g1 = (const float*)d_in[3];
    const float* enc_be1= (const float*)d_in[4];
    const float* enc_w2 = (const float*)d_in[5];
    const float* enc_b2 = (const float*)d_in[6];
    const float* enc_g2 = (const float*)d_in[7];
    const float* enc_be2= (const float*)d_in[8];
    const float* watt1  = (const float*)d_in[9];
    const float* batt1  = (const float*)d_in[10];
    const float* watt2  = (const float*)d_in[11];
    const float* batt2  = (const float*)d_in[12];
    const float* dec_w1 = (const float*)d_in[13];
    const float* dec_b1 = (const float*)d_in[14];
    const float* dec_w2 = (const float*)d_in[15];
    const float* dec_b2 = (const float*)d_in[16];
    const float* dec_w3 = (const float*)d_in[17];
    const float* dec_b3 = (const float*)d_in[18];
    const int*   src    = (const int*)d_in[19];
    const int*   dst    = (const int*)d_in[20];
    float* out = (float*)d_out;

    {
        long n = (long)BB * NN * DD;
        int blocks = (int)((n + 255) / 256);
        k_zero_node_and_counts<<<blocks, 256>>>();
    }

    k_prep<<<(256 * 384 + 255) / 256, 256>>>(dec_w1, dec_w2, enc_w2);

    k_count_deg<<<(EE + 255) / 256, 256>>>(src, dst);

    k_enc<<<(BB * EE) / 64, 128>>>(feat, enc_w1, enc_b1, enc_g1, enc_be1,
                                   enc_b2, enc_g2, enc_be2);

    k_scan<<<1, 1024>>>();
    k_scatter<<<(2 * EE + 255) / 256, 256>>>(src, dst);

    k_edot<<<1480, 256>>>(watt1, watt2);

    k_mp<<<dim3(NN, BB), DD>>>(watt1, batt1, 0);
    k_mp<<<dim3(NN, BB), DD>>>(watt2, batt2, 1);

    k_dec1<<<(BB * EE) / 128, 256>>>(src, dst, dec_b1);
    k_dec2<<<(BB * EE) / 128, 256>>>(dec_b2, dec_w3, dec_b3, out);
}

// round 17
// speedup vs baseline: 1.3000x; 1.0365x over previous
#include <cuda_runtime.h>
#include <cuda_bf16.h>
#include <math.h>
#include <stdint.h>

// Problem constants
#define BB 2
#define EE 160000
#define NN 10000
#define DD 128
#define TE 16

typedef unsigned long long u64;
typedef unsigned int u32;

// ---------------- scratch (device globals) ----------------
__device__ float g_edge_emb[(size_t)BB * EE * DD];
__device__ float g_nodeA[(size_t)BB * NN * DD];
__device__ float g_nodeB[(size_t)BB * NN * DD];
__device__ float g_s[(size_t)BB * 2 * EE];
__device__ float g_d[(size_t)BB * 2 * EE];
__device__ int   g_deg[NN];
__device__ int   g_off[NN + 1];
__device__ int   g_cursor[NN];
__device__ int   g_csr[2 * EE];
// decoder weights, transposed to [N,K] row-major, bf16 hi/mid split
__device__ __align__(16) __nv_bfloat16 g_w1t_hi[256 * 384];
__device__ __align__(16) __nv_bfloat16 g_w1t_mid[256 * 384];
__device__ __align__(16) __nv_bfloat16 g_w2t_hi[128 * 256];
__device__ __align__(16) __nv_bfloat16 g_w2t_mid[128 * 256];
// encoder layer-2 weights, transposed [N=128][K=128], bf16 hi/mid split
__device__ __align__(16) __nv_bfloat16 g_we2t_hi[128 * 128];
__device__ __align__(16) __nv_bfloat16 g_we2t_mid[128 * 128];
// z1 activations, pre-split bf16 hi/mid: [B*E][256]
__device__ __align__(16) __nv_bfloat16 g_z1_hi[(size_t)BB * EE * 256];
__device__ __align__(16) __nv_bfloat16 g_z1_mid[(size_t)BB * EE * 256];

// ---------------- generic helpers ----------------
__device__ __forceinline__ float geluf(float x) { return x * normcdff(x); }

__device__ __forceinline__ u64 pack2(float lo, float hi) {
    u64 r; asm("mov.b64 %0, {%1, %2};" : "=l"(r) : "f"(lo), "f"(hi)); return r;
}
__device__ __forceinline__ u64 fma2(u64 a, u64 b, u64 c) {
    u64 d; asm("fma.rn.f32x2 %0, %1, %2, %3;" : "=l"(d) : "l"(a), "l"(b), "l"(c)); return d;
}
__device__ __forceinline__ float sum2(u64 v) {
    float lo, hi; asm("mov.b64 {%0, %1}, %2;" : "=f"(lo), "=f"(hi) : "l"(v)); return lo + hi;
}

__device__ __forceinline__ float brsum128(float v, float* red) {
    int lane = threadIdx.x & 31, w = threadIdx.x >> 5;
    #pragma unroll
    for (int o = 16; o; o >>= 1) v += __shfl_down_sync(0xffffffffu, v, o);
    if (lane == 0) red[w] = v;
    __syncthreads();
    float s = red[0] + red[1] + red[2] + red[3];
    __syncthreads();
    return s;
}
__device__ __forceinline__ float brmax128(float v, float* red) {
    int lane = threadIdx.x & 31, w = threadIdx.x >> 5;
    #pragma unroll
    for (int o = 16; o; o >>= 1) v = fmaxf(v, __shfl_down_sync(0xffffffffu, v, o));
    if (lane == 0) red[w] = v;
    __syncthreads();
    float s = fmaxf(fmaxf(red[0], red[1]), fmaxf(red[2], red[3]));
    __syncthreads();
    return s;
}

// ---------------- mma.sync / ldmatrix helpers ----------------
__device__ __forceinline__ u32 smem_u32(const void* p) {
    u32 a; asm("{ .reg .u64 t; cvta.to.shared.u64 t, %1; cvt.u32.u64 %0, t; }" : "=r"(a) : "l"(p));
    return a;
}
__device__ __forceinline__ void ldsm4(u32& r0, u32& r1, u32& r2, u32& r3, u32 addr) {
    asm volatile("ldmatrix.sync.aligned.m8n8.x4.shared.b16 {%0,%1,%2,%3}, [%4];"
        : "=r"(r0), "=r"(r1), "=r"(r2), "=r"(r3) : "r"(addr));
}
__device__ __forceinline__ void mma_bf16(float* d, u32 a0, u32 a1, u32 a2, u32 a3, u32 b0, u32 b1) {
    asm volatile("mma.sync.aligned.m16n8k16.row.col.f32.bf16.bf16.f32 "
        "{%0,%1,%2,%3}, {%4,%5,%6,%7}, {%8,%9}, {%0,%1,%2,%3};"
        : "+f"(d[0]), "+f"(d[1]), "+f"(d[2]), "+f"(d[3])
        : "r"(a0), "r"(a1), "r"(a2), "r"(a3), "r"(b0), "r"(b1));
}
#define STS16(a, v)     asm volatile("st.shared.u16 [%0], %1;" :: "r"(a), "h"(v) : "memory")
#define STS64P(a, x, y) asm volatile("st.shared.v2.b32 [%0], {%1, %2};" :: "r"(a), "r"(x), "r"(y) : "memory")
#define STS128P(a, v)   asm volatile("st.shared.v4.b32 [%0], {%1, %2, %3, %4};" \
                            :: "r"(a), "r"((v).x), "r"((v).y), "r"((v).z), "r"((v).w) : "memory")
__device__ __forceinline__ u32 sw128(u32 off) { return off ^ ((off >> 3) & 0x70); }
__device__ __forceinline__ u32 packbf(__nv_bfloat16 a, __nv_bfloat16 b) {
    return ((u32)__bfloat16_as_ushort(b) << 16) | (u32)__bfloat16_as_ushort(a);
}

// ---------------- init ----------------
__global__ void k_zero_node_and_counts() {
    long i = (long)blockIdx.x * blockDim.x + threadIdx.x;
    long nNode = (long)BB * NN * DD;
    if (i < nNode) g_nodeA[i] = 0.0f;
    if (i < NN) { g_deg[i] = 0; g_cursor[i] = 0; }
}

// ---------------- CSR build ----------------
__global__ void k_count_deg(const int* __restrict__ src, const int* __restrict__ dst) {
    int i = blockIdx.x * blockDim.x + threadIdx.x;
    if (i < EE) {
        atomicAdd(&g_deg[src[i]], 1);
        atomicAdd(&g_deg[dst[i]], 1);
    }
}

__global__ void k_scan() {
    __shared__ int sums[1024];
    int t = threadIdx.x;
    const int chunk = (NN + 1023) / 1024;
    int start = t * chunk;
    int end = min(start + chunk, NN);
    int s = 0;
    for (int i = start; i < end; i++) s += g_deg[i];
    sums[t] = s;
    __syncthreads();
    for (int d = 1; d < 1024; d <<= 1) {
        int v = (t >= d) ? sums[t - d] : 0;
        __syncthreads();
        sums[t] += v;
        __syncthreads();
    }
    int run = (t > 0) ? sums[t - 1] : 0;
    for (int i = start; i < end; i++) { g_off[i] = run; run += g_deg[i]; }
    if (t == 1023) g_off[NN] = sums[1023];
}

__global__ void k_scatter(const int* __restrict__ src, const int* __restrict__ dst) {
    int p = blockIdx.x * blockDim.x + threadIdx.x;
    if (p < 2 * EE) {
        int node = (p < EE) ? src[p] : dst[p - EE];
        int pos = g_off[node] + atomicAdd(&g_cursor[node], 1);
        g_csr[pos] = p;
    }
}

// ---------------- weight prep: transpose + bf16 hi/mid split ----------------
__global__ void k_prep(const float* __restrict__ w1, const float* __restrict__ w2,
                       const float* __restrict__ we2) {
    int i = blockIdx.x * blockDim.x + threadIdx.x;
    if (i < 256 * 384) {
        int n = i / 384, k = i - n * 384;
        float v = w1[(size_t)k * 256 + n];
        __nv_bfloat16 h = __float2bfloat16(v);
        g_w1t_hi[i] = h;
        g_w1t_mid[i] = __float2bfloat16(v - __bfloat162float(h));
    }
    if (i < 128 * 256) {
        int n = i / 256, k = i - n * 256;
        float v = w2[(size_t)k * 128 + n];
        __nv_bfloat16 h = __float2bfloat16(v);
        g_w2t_hi[i] = h;
        g_w2t_mid[i] = __float2bfloat16(v - __bfloat162float(h));
    }
    if (i < 128 * 128) {
        int n = i / 128, k = i - n * 128;
        float v = we2[(size_t)k * 128 + n];
        __nv_bfloat16 h = __float2bfloat16(v);
        g_we2t_hi[i] = h;
        g_we2t_mid[i] = __float2bfloat16(v - __bfloat162float(h));
    }
}

// ---------------- encoder (EXACT R14/R15: launch_bounds(128,3), no prefetch, no edot) ----------------
__global__ void __launch_bounds__(128, 3) k_enc(
    const float* __restrict__ feat,
    const float* __restrict__ w1, const float* __restrict__ b1,
    const float* __restrict__ g1, const float* __restrict__ be1,
    const float* __restrict__ b2, const float* __restrict__ g2,
    const float* __restrict__ be2) {
    __shared__ __align__(16) __nv_bfloat16 sAh[8192];
    __shared__ __align__(16) __nv_bfloat16 sAm[8192];
    __shared__ __align__(16) __nv_bfloat16 sBh[2048];
    __shared__ __align__(16) __nv_bfloat16 sBm[2048];
    __shared__ __align__(16) float xs[8][24];
    __shared__ float b2s[128], g2s[128], be2s[128];
    __shared__ float g1s[128], be1s[128];

    const u32 Ah = smem_u32(sAh), Am = smem_u32(sAm);
    const u32 Bh = smem_u32(sBh), Bm = smem_u32(sBm);

    int tid = threadIdx.x, lane = tid & 31, warp = tid >> 5;
    long base = (long)blockIdx.x * 64;

    b2s[tid] = b2[tid];
    g2s[tid] = g2[tid];
    be2s[tid] = be2[tid];
    g1s[tid] = g1[tid];
    be1s[tid] = be1[tid];

    int d = tid;
    u64 wp[12];
    #pragma unroll
    for (int k = 0; k < 12; k++)
        wp[k] = pack2(w1[(2 * k) * DD + d], w1[(2 * k + 1) * DD + d]);
    float b1v = b1[d];

    // ---------- phase 1 ----------
    float* fs = (float*)sBh;
    for (int it = 0; it < 8; it++) {
        __syncthreads();
        for (int i = tid; i < 48; i += 128) {
            int t = i / 6, j = i % 6;
            ((float4*)xs[t])[j] = ((const float4*)(feat + (base + it * 8 + t) * 24))[j];
        }
        __syncthreads();

        float acc[8];
        #pragma unroll
        for (int t = 0; t < 8; t++) {
            u64 a = pack2(b1v, 0.0f);
            #pragma unroll
            for (int j = 0; j < 6; j++) {
                ulonglong2 xv = ((const ulonglong2*)xs[t])[j];
                a = fma2(xv.x, wp[2 * j], a);
                a = fma2(xv.y, wp[2 * j + 1], a);
            }
            acc[t] = sum2(a);
        }
        #pragma unroll
        for (int t = 0; t < 8; t++) fs[t * 128 + d] = acc[t];
        __syncthreads();

        #pragma unroll
        for (int tt = 0; tt < 2; tt++) {
            int t = warp * 2 + tt;
            float v[4];
            #pragma unroll
            for (int r = 0; r < 4; r++) v[r] = fs[t * 128 + lane + 32 * r];
            float s = v[0] + v[1] + v[2] + v[3];
            float q = v[0] * v[0] + v[1] * v[1] + v[2] * v[2] + v[3] * v[3];
            #pragma unroll
            for (int o = 16; o; o >>= 1) {
                s += __shfl_xor_sync(0xffffffffu, s, o);
                q += __shfl_xor_sync(0xffffffffu, q, o);
            }
            float mu = s * (1.0f / DD);
            float rstd = rsqrtf(q * (1.0f / DD) - mu * mu + 1e-5f);
            u32 row = (u32)(it * 8 + t);
            #pragma unroll
            for (int r = 0; r < 4; r++) {
                int c = lane + 32 * r;
                float vv = geluf((v[r] - mu) * rstd * g1s[c] + be1s[c]);
                __nv_bfloat16 h = __float2bfloat16(vv);
                __nv_bfloat16 m = __float2bfloat16(vv - __bfloat162float(h));
                u32 off = ((u32)(c >> 6)) * 8192 + sw128(row * 128 + (u32)(c & 63) * 2);
                STS16(Ah + off, __bfloat16_as_ushort(h));
                STS16(Am + off, __bfloat16_as_ushort(m));
            }
        }
    }
    __syncthreads();

    // ---------- phase 2 ----------
    int g = lane >> 2, tig = lane & 3;
    int wbase = warp * 16;
    const u32 aRow = (u32)(wbase + (lane & 15));
    const u32 aKH  = (u32)((lane >> 4) & 1) * 16;
    const u32 bRowInPair = (u32)(((lane >> 4) & 1) * 8 + (lane & 7));
    const u32 bKH  = (u32)((lane >> 3) & 1) * 16;
    const int bn = tid >> 2, bu = (tid & 3) * 2;
    const u32 bSts0 = sw128((u32)(bn * 128 + bu * 16));
    const u32 bSts1 = sw128((u32)(bn * 128 + (bu + 1) * 16));

    float dd[64];
    #pragma unroll
    for (int i = 0; i < 64; i++) dd[i] = 0.0f;

    uint4 ph0, ph1, pm0, pm1;
    {
        size_t gi = (size_t)bn * 128 + bu * 8;
        ph0 = *(const uint4*)(g_we2t_hi + gi);
        ph1 = *(const uint4*)(g_we2t_hi + gi + 8);
        pm0 = *(const uint4*)(g_we2t_mid + gi);
        pm1 = *(const uint4*)(g_we2t_mid + gi + 8);
    }

    for (int kc = 0; kc < 2; kc++) {
        u32 af[4][8];
        #pragma unroll
        for (int kk = 0; kk < 4; kk++) {
            u32 aAddr = (u32)kc * 8192 + sw128((u32)(aRow * 128 + kk * 32) + aKH);
            ldsm4(af[kk][0], af[kk][1], af[kk][2], af[kk][3], Ah + aAddr);
            ldsm4(af[kk][4], af[kk][5], af[kk][6], af[kk][7], Am + aAddr);
        }

        #pragma unroll
        for (int ng = 0; ng < 4; ng++) {
            STS128P(Bh + bSts0, ph0);
            STS128P(Bh + bSts1, ph1);
            STS128P(Bm + bSts0, pm0);
            STS128P(Bm + bSts1, pm1);
            {
                int np = kc * 4 + ng + 1;
                if (np > 7) np = 7;
                int nkc = np >> 2, nng = np & 3;
                size_t gi = (size_t)(nng * 32 + bn) * 128 + nkc * 64 + bu * 8;
                ph0 = *(const uint4*)(g_we2t_hi + gi);
                ph1 = *(const uint4*)(g_we2t_hi + gi + 8);
                pm0 = *(const uint4*)(g_we2t_mid + gi);
                pm1 = *(const uint4*)(g_we2t_mid + gi + 8);
            }
            __syncthreads();
            #pragma unroll
            for (int kk = 0; kk < 4; kk++) {
                #pragma unroll
                for (int nt = 0; nt < 2; nt++) {
                    u32 bAddr = sw128((u32)((nt * 16 + bRowInPair) * 128 + kk * 32) + bKH);
                    u32 bh0, bh1, bh2, bh3, bm0, bm1, bm2, bm3;
                    ldsm4(bh0, bh1, bh2, bh3, Bh + bAddr);
                    ldsm4(bm0, bm1, bm2, bm3, Bm + bAddr);
                    float* dA = dd + (ng * 4 + nt * 2) * 4;
                    float* dB = dA + 4;
                    mma_bf16(dA, af[kk][0], af[kk][1], af[kk][2], af[kk][3], bh0, bh1);
                    mma_bf16(dA, af[kk][4], af[kk][5], af[kk][6], af[kk][7], bh0, bh1);
                    mma_bf16(dA, af[kk][0], af[kk][1], af[kk][2], af[kk][3], bm0, bm1);
                    mma_bf16(dB, af[kk][0], af[kk][1], af[kk][2], af[kk][3], bh2, bh3);
                    mma_bf16(dB, af[kk][4], af[kk][5], af[kk][6], af[kk][7], bh2, bh3);
                    mma_bf16(dB, af[kk][0], af[kk][1], af[kk][2], af[kk][3], bm2, bm3);
                }
            }
            __syncthreads();
        }
    }

    // ---------- phase 3 ----------
    float s0 = 0.0f, q0 = 0.0f, s1 = 0.0f, q1 = 0.0f;
    #pragma unroll
    for (int ti = 0; ti < 16; ti++) {
        int c0 = ti * 8 + tig * 2;
        float v0 = dd[ti * 4 + 0] + b2s[c0];
        float v1 = dd[ti * 4 + 1] + b2s[c0 + 1];
        float v2 = dd[ti * 4 + 2] + b2s[c0];
        float v3 = dd[ti * 4 + 3] + b2s[c0 + 1];
        dd[ti * 4 + 0] = v0; dd[ti * 4 + 1] = v1;
        dd[ti * 4 + 2] = v2; dd[ti * 4 + 3] = v3;
        s0 += v0 + v1; q0 += v0 * v0 + v1 * v1;
        s1 += v2 + v3; q1 += v2 * v2 + v3 * v3;
    }
    #pragma unroll
    for (int o = 1; o < 4; o <<= 1) {
        s0 += __shfl_xor_sync(0xffffffffu, s0, o, 4);
        q0 += __shfl_xor_sync(0xffffffffu, q0, o, 4);
        s1 += __shfl_xor_sync(0xffffffffu, s1, o, 4);
        q1 += __shfl_xor_sync(0xffffffffu, q1, o, 4);
    }
    float mu0 = s0 * (1.0f / DD), mu1 = s1 * (1.0f / DD);
    float rs0 = rsqrtf(q0 * (1.0f / DD) - mu0 * mu0 + 1e-5f);
    float rs1 = rsqrtf(q1 * (1.0f / DD) - mu1 * mu1 + 1e-5f);
    float* o0 = g_edge_emb + (base + wbase + g) * DD;
    float* o1 = g_edge_emb + (base + wbase + g + 8) * DD;
    #pragma unroll
    for (int ti = 0; ti < 16; ti++) {
        int c0 = ti * 8 + tig * 2;
        float2 a, c;
        a.x = (dd[ti * 4 + 0] - mu0) * rs0 * g2s[c0]     + be2s[c0];
        a.y = (dd[ti * 4 + 1] - mu0) * rs0 * g2s[c0 + 1] + be2s[c0 + 1];
        c.x = (dd[ti * 4 + 2] - mu1) * rs1 * g2s[c0]     + be2s[c0];
        c.y = (dd[ti * 4 + 3] - mu1) * rs1 * g2s[c0 + 1] + be2s[c0 + 1];
        *(float2*)(o0 + c0) = a;
        *(float2*)(o1 + c0) = c;
    }
}

// ---------------- per-edge attention dots (separate kernel, as in R15) ----------------
__global__ void __launch_bounds__(256) k_edot(const float* __restrict__ watt1,
                                              const float* __restrict__ watt2) {
    int lane = threadIdx.x & 31;
    long gw = (long)blockIdx.x * 8 + (threadIdx.x >> 5);
    long nwarps = (long)gridDim.x * 8;
    float w1r[4], w2r[4];
    #pragma unroll
    for (int r = 0; r < 4; r++) {
        w1r[r] = watt1[128 + lane + 32 * r];
        w2r[r] = watt2[128 + lane + 32 * r];
    }
    for (long idx = gw; idx < (long)BB * EE; idx += nwarps) {
        const float* row = g_edge_emb + idx * DD;
        float v0 = row[lane], v1 = row[lane + 32], v2 = row[lane + 64], v3 = row[lane + 96];
        float d1 = fmaf(v0, w1r[0], fmaf(v1, w1r[1], fmaf(v2, w1r[2], v3 * w1r[3])));
        float d2 = fmaf(v0, w2r[0], fmaf(v1, w2r[1], fmaf(v2, w2r[2], v3 * w2r[3])));
        #pragma unroll
        for (int o = 16; o; o >>= 1) {
            d1 += __shfl_down_sync(0xffffffffu, d1, o);
            d2 += __shfl_down_sync(0xffffffffu, d2, o);
        }
        if (lane == 0) {
            long b = idx / EE, e = idx - b * EE;
            g_d[(b * 2 + 0) * EE + e] = d1;
            g_d[(b * 2 + 1) * EE + e] = d2;
        }
    }
}

// ---------------- message passing: smem-staged softmax, 4-way aggregation ----------------
#define MP_CAP 1024
__global__ void k_mp(const float* __restrict__ watt, const float* __restrict__ batt, int dir) {
    int n = blockIdx.x;
    int b = blockIdx.y;
    int tid = threadIdx.x;
    const float* nin  = (dir ? g_nodeB : g_nodeA) + (size_t)b * NN * DD;
    float*       nout = (dir ? g_nodeA : g_nodeB) + (size_t)b * NN * DD;
    const float* eemb = g_edge_emb + (size_t)b * EE * DD;
    const float* dvec = g_d + ((size_t)b * 2 + dir) * EE;
    float*       sb   = g_s + (size_t)b * 2 * EE;

    int cnt = g_deg[n];
    int start = g_off[n];
    float hval = nin[n * DD + tid];
    if (cnt == 0) { nout[n * DD + tid] = hval; return; }

    __shared__ float red[4];
    __shared__ int   se[MP_CAP];
    __shared__ float swt[MP_CAP];

    float c = brsum128(hval * watt[tid], red);
    float battv = batt[0];

    if (cnt <= MP_CAP) {
        // pass 1: edge index + score into smem
        float lmax = -INFINITY;
        for (int i = tid; i < cnt; i += 128) {
            int p = g_csr[start + i];
            int e = (p < EE) ? p : p - EE;
            se[i] = e;
            float s = c + dvec[e] + battv;
            s = (s > 0.0f) ? s : 0.2f * s;
            swt[i] = s;
            lmax = fmaxf(lmax, s);
        }
        float m = brmax128(lmax, red);       // barrier => se/swt visible

        float den = 0.0f;
        for (int i = tid; i < cnt; i += 128) {
            float ex = __expf(swt[i] - m);
            swt[i] = ex;
            den += ex;
        }
        den = brsum128(den, red);            // barrier => ex visible
        float inv = 1.0f / den;

        // pass 3: 4-way unrolled aggregation, all indices/weights from smem
        float acc0 = 0.0f, acc1 = 0.0f, acc2 = 0.0f, acc3 = 0.0f;
        int i = 0;
        for (; i + 3 < cnt; i += 4) {
            int ea = se[i], eb = se[i + 1], ec = se[i + 2], ed = se[i + 3];
            float w0 = swt[i], w1v = swt[i + 1], w2v = swt[i + 2], w3v = swt[i + 3];
            acc0 = fmaf(w0,  eemb[(size_t)ea * DD + tid], acc0);
            acc1 = fmaf(w1v, eemb[(size_t)eb * DD + tid], acc1);
            acc2 = fmaf(w2v, eemb[(size_t)ec * DD + tid], acc2);
            acc3 = fmaf(w3v, eemb[(size_t)ed * DD + tid], acc3);
        }
        for (; i < cnt; i++)
            acc0 = fmaf(swt[i], eemb[(size_t)se[i] * DD + tid], acc0);
        nout[n * DD + tid] = geluf(((acc0 + acc1) + (acc2 + acc3)) * inv);
    } else {
        // fallback: original global-memory path
        float lmax = -INFINITY;
        for (int i = tid; i < cnt; i += 128) {
            int p = g_csr[start + i];
            int e = (p < EE) ? p : p - EE;
            float s = c + dvec[e] + battv;
            s = (s > 0.0f) ? s : 0.2f * s;
            sb[start + i] = s;
            lmax = fmaxf(lmax, s);
        }
        float m = brmax128(lmax, red);

        float den = 0.0f;
        for (int i = tid; i < cnt; i += 128) {
            float ex = __expf(sb[start + i] - m);
            sb[start + i] = ex;
            den += ex;
        }
        den = brsum128(den, red);
        float inv = 1.0f / den;

        float acc0 = 0.0f, acc1 = 0.0f;
        int i = 0;
        for (; i + 1 < cnt; i += 2) {
            int p0 = g_csr[start + i];
            int p1 = g_csr[start + i + 1];
            int ea = (p0 < EE) ? p0 : p0 - EE;
            int eb = (p1 < EE) ? p1 : p1 - EE;
            acc0 = fmaf(sb[start + i],     eemb[(size_t)ea * DD + tid], acc0);
            acc1 = fmaf(sb[start + i + 1], eemb[(size_t)eb * DD + tid], acc1);
        }
        if (i < cnt) {
            int p = g_csr[start + i];
            int e = (p < EE) ? p : p - EE;
            acc0 = fmaf(sb[start + i], eemb[(size_t)e * DD + tid], acc0);
        }
        nout[n * DD + tid] = geluf((acc0 + acc1) * inv);
    }
}

// ---------------- decoder stage 1 (unchanged from R15) ----------------
__global__ void __launch_bounds__(256, 1) k_dec1(
    const int* __restrict__ src, const int* __restrict__ dst,
    const float* __restrict__ b1) {
    __shared__ __align__(16) __nv_bfloat16 sAh[8192];
    __shared__ __align__(16) __nv_bfloat16 sAm[8192];
    __shared__ __align__(16) __nv_bfloat16 sBh[2048];
    __shared__ __align__(16) __nv_bfloat16 sBm[2048];
    __shared__ float b1s[256];
    __shared__ int sidx[128], didx[128];

    const u32 Ah = smem_u32(sAh), Am = smem_u32(sAm);
    const u32 Bh = smem_u32(sBh), Bm = smem_u32(sBm);

    int tid = threadIdx.x, lane = tid & 31, warp = tid >> 5;
    int g = lane >> 2, tig = lane & 3;
    int wbase = warp * 16;

    long base = (long)blockIdx.x * 128;
    int b = (int)(base / EE);
    int e0 = (int)(base - (long)b * EE);
    size_t bNN = (size_t)b * NN;

    b1s[tid] = b1[tid];
    if (tid < 128) {
        sidx[tid] = src[e0 + tid];
        didx[tid] = dst[e0 + tid];
    }
    __syncthreads();

    const u32 aRow = (u32)(wbase + (lane & 15));
    const u32 aKH  = (u32)((lane >> 4) & 1) * 16;
    const u32 bRowInPair = (u32)(((lane >> 4) & 1) * 8 + (lane & 7));
    const u32 bKH  = (u32)((lane >> 3) & 1) * 16;
    const int bn = tid >> 3, bu = tid & 7;
    const u32 bSts = sw128((u32)(bn * 128 + bu * 16));

    float d1[128];
    #pragma unroll
    for (int i = 0; i < 128; i++) d1[i] = 0.0f;

    uint4 pvh, pvm;
    {
        size_t gidx = (size_t)bn * 384 + bu * 8;
        pvh = *(const uint4*)(g_w1t_hi + gidx);
        pvm = *(const uint4*)(g_w1t_mid + gidx);
    }

    float4 av[8];
    #pragma unroll
    for (int i = 0; i < 8; i++) {
        int j = tid + 256 * i;
        int r = j >> 4, q = j & 15;
        av[i] = ((const float4*)(g_nodeA + (bNN + sidx[r]) * DD))[q];
    }

    for (int kc = 0; kc < 6; kc++) {
        #pragma unroll
        for (int i = 0; i < 8; i++) {
            int j = tid + 256 * i;
            int r = j >> 4, q = j & 15;
            float4 v = av[i];
            __nv_bfloat16 h0 = __float2bfloat16(v.x), h1 = __float2bfloat16(v.y);
            __nv_bfloat16 h2 = __float2bfloat16(v.z), h3 = __float2bfloat16(v.w);
            __nv_bfloat16 m0 = __float2bfloat16(v.x - __bfloat162float(h0));
            __nv_bfloat16 m1 = __float2bfloat16(v.y - __bfloat162float(h1));
            __nv_bfloat16 m2 = __float2bfloat16(v.z - __bfloat162float(h2));
            __nv_bfloat16 m3 = __float2bfloat16(v.w - __bfloat162float(h3));
            u32 off = sw128((u32)(r * 128 + q * 8));
            STS64P(Ah + off, packbf(h0, h1), packbf(h2, h3));
            STS64P(Am + off, packbf(m0, m1), packbf(m2, m3));
        }
        if (kc < 5) {
            int nk = kc + 1;
            #pragma unroll
            for (int i = 0; i < 8; i++) {
                int j = tid + 256 * i;
                int r = j >> 4, q = j & 15;
                const float* rp;
                int f4;
                if (nk < 2)      { rp = g_nodeA + (bNN + sidx[r]) * DD;              f4 = nk * 16 + q; }
                else if (nk < 4) { rp = g_nodeA + (bNN + didx[r]) * DD;              f4 = (nk - 2) * 16 + q; }
                else             { rp = g_edge_emb + ((size_t)b * EE + e0 + r) * DD; f4 = (nk - 4) * 16 + q; }
                av[i] = ((const float4*)rp)[f4];
            }
        }
        __syncthreads();

        u32 af[4][8];
        #pragma unroll
        for (int kk = 0; kk < 4; kk++) {
            u32 aAddr = sw128((u32)(aRow * 128 + kk * 32) + aKH);
            ldsm4(af[kk][0], af[kk][1], af[kk][2], af[kk][3], Ah + aAddr);
            ldsm4(af[kk][4], af[kk][5], af[kk][6], af[kk][7], Am + aAddr);
        }

        #pragma unroll
        for (int ng = 0; ng < 8; ng++) {
            STS128P(Bh + bSts, pvh);
            STS128P(Bm + bSts, pvm);
            {
                int np = kc * 8 + ng + 1;
                if (np > 47) np = 47;
                int nkc = np >> 3, nng = np & 7;
                size_t gidx = (size_t)(nng * 32 + bn) * 384 + nkc * 64 + bu * 8;
                pvh = *(const uint4*)(g_w1t_hi + gidx);
                pvm = *(const uint4*)(g_w1t_mid + gidx);
            }
            __syncthreads();
            #pragma unroll
            for (int kk = 0; kk < 4; kk++) {
                #pragma unroll
                for (int nt = 0; nt < 2; nt++) {
                    u32 bAddr = sw128((u32)((nt * 16 + bRowInPair) * 128 + kk * 32) + bKH);
                    u32 bh0, bh1, bh2, bh3, bm0, bm1, bm2, bm3;
                    ldsm4(bh0, bh1, bh2, bh3, Bh + bAddr);
                    ldsm4(bm0, bm1, bm2, bm3, Bm + bAddr);
                    float* dA = d1 + (ng * 4 + nt * 2) * 4;
                    float* dB = dA + 4;
                    mma_bf16(dA, af[kk][0], af[kk][1], af[kk][2], af[kk][3], bh0, bh1);
                    mma_bf16(dA, af[kk][4], af[kk][5], af[kk][6], af[kk][7], bh0, bh1);
                    mma_bf16(dA, af[kk][0], af[kk][1], af[kk][2], af[kk][3], bm0, bm1);
                    mma_bf16(dB, af[kk][0], af[kk][1], af[kk][2], af[kk][3], bh2, bh3);
                    mma_bf16(dB, af[kk][4], af[kk][5], af[kk][6], af[kk][7], bh2, bh3);
                    mma_bf16(dB, af[kk][0], af[kk][1], af[kk][2], af[kk][3], bm2, bm3);
                }
            }
            __syncthreads();
        }
    }

    long r0 = base + wbase + g;
    long r1 = r0 + 8;
    #pragma unroll
    for (int ti = 0; ti < 32; ti++) {
        int c0 = ti * 8 + tig * 2;
        float v0 = geluf(d1[ti * 4 + 0] + b1s[c0]);
        float v1 = geluf(d1[ti * 4 + 1] + b1s[c0 + 1]);
        float v2 = geluf(d1[ti * 4 + 2] + b1s[c0]);
        float v3 = geluf(d1[ti * 4 + 3] + b1s[c0 + 1]);
        __nv_bfloat16 h0 = __float2bfloat16(v0), h1 = __float2bfloat16(v1);
        __nv_bfloat16 h2 = __float2bfloat16(v2), h3 = __float2bfloat16(v3);
        __nv_bfloat16 m0 = __float2bfloat16(v0 - __bfloat162float(h0));
        __nv_bfloat16 m1 = __float2bfloat16(v1 - __bfloat162float(h1));
        __nv_bfloat16 m2 = __float2bfloat16(v2 - __bfloat162float(h2));
        __nv_bfloat16 m3 = __float2bfloat16(v3 - __bfloat162float(h3));
        *(u32*)(g_z1_hi  + r0 * 256 + c0) = packbf(h0, h1);
        *(u32*)(g_z1_mid + r0 * 256 + c0) = packbf(m0, m1);
        *(u32*)(g_z1_hi  + r1 * 256 + c0) = packbf(h2, h3);
        *(u32*)(g_z1_mid + r1 * 256 + c0) = packbf(m2, m3);
    }
}

// ---------------- decoder stage 2 (unchanged from R15) ----------------
__global__ void __launch_bounds__(256, 1) k_dec2(
    const float* __restrict__ b2, const float* __restrict__ w3,
    const float* __restrict__ b3, float* __restrict__ out) {
    __shared__ __align__(16) __nv_bfloat16 sAh[8192];
    __shared__ __align__(16) __nv_bfloat16 sAm[8192];
    __shared__ __align__(16) __nv_bfloat16 sBh[2048];
    __shared__ __align__(16) __nv_bfloat16 sBm[2048];
    __shared__ float b2s[128], w3s[128];

    const u32 Ah = smem_u32(sAh), Am = smem_u32(sAm);
    const u32 Bh = smem_u32(sBh), Bm = smem_u32(sBm);

    int tid = threadIdx.x, lane = tid & 31, warp = tid >> 5;
    int g = lane >> 2, tig = lane & 3;
    int wbase = warp * 16;
    long base = (long)blockIdx.x * 128;

    if (tid < 128) { b2s[tid] = b2[tid]; w3s[tid] = w3[tid]; }

    const u32 aRow = (u32)(wbase + (lane & 15));
    const u32 aKH  = (u32)((lane >> 4) & 1) * 16;
    const u32 bRowInPair = (u32)(((lane >> 4) & 1) * 8 + (lane & 7));
    const u32 bKH  = (u32)((lane >> 3) & 1) * 16;
    const int bn = tid >> 3, bu = tid & 7;
    const u32 bSts = sw128((u32)(bn * 128 + bu * 16));

    float d2[64];
    #pragma unroll
    for (int i = 0; i < 64; i++) d2[i] = 0.0f;

    uint4 pvh, pvm;
    {
        size_t gidx = (size_t)bn * 256 + bu * 8;
        pvh = *(const uint4*)(g_w2t_hi + gidx);
        pvm = *(const uint4*)(g_w2t_mid + gidx);
    }

    uint4 avh[4], avm[4];
    #pragma unroll
    for (int i = 0; i < 4; i++) {
        int j = tid + 256 * i;
        int r = j >> 3, u = j & 7;
        size_t gidx = (size_t)(base + r) * 256 + u * 8;
        avh[i] = *(const uint4*)(g_z1_hi + gidx);
        avm[i] = *(const uint4*)(g_z1_mid + gidx);
    }

    for (int kc = 0; kc < 4; kc++) {
        __syncthreads();
        #pragma unroll
        for (int i = 0; i < 4; i++) {
            int j = tid + 256 * i;
            int r = j >> 3, u = j & 7;
            u32 off = sw128((u32)(r * 128 + u * 16));
            STS128P(Ah + off, avh[i]);
            STS128P(Am + off, avm[i]);
        }
        if (kc < 3) {
            int nk = kc + 1;
            #pragma unroll
            for (int i = 0; i < 4; i++) {
                int j = tid + 256 * i;
                int r = j >> 3, u = j & 7;
                size_t gidx = (size_t)(base + r) * 256 + nk * 64 + u * 8;
                avh[i] = *(const uint4*)(g_z1_hi + gidx);
                avm[i] = *(const uint4*)(g_z1_mid + gidx);
            }
        }
        __syncthreads();

        u32 af[4][8];
        #pragma unroll
        for (int kk = 0; kk < 4; kk++) {
            u32 aAddr = sw128((u32)(aRow * 128 + kk * 32) + aKH);
            ldsm4(af[kk][0], af[kk][1], af[kk][2], af[kk][3], Ah + aAddr);
            ldsm4(af[kk][4], af[kk][5], af[kk][6], af[kk][7], Am + aAddr);
        }

        #pragma unroll
        for (int ng = 0; ng < 4; ng++) {
            STS128P(Bh + bSts, pvh);
            STS128P(Bm + bSts, pvm);
            {
                int np = kc * 4 + ng + 1;
                if (np > 15) np = 15;
                int nkc = np >> 2, nng = np & 3;
                size_t gidx = (size_t)(nng * 32 + bn) * 256 + nkc * 64 + bu * 8;
                pvh = *(const uint4*)(g_w2t_hi + gidx);
                pvm = *(const uint4*)(g_w2t_mid + gidx);
            }
            __syncthreads();
            #pragma unroll
            for (int kk = 0; kk < 4; kk++) {
                #pragma unroll
                for (int nt = 0; nt < 2; nt++) {
                    u32 bAddr = sw128((u32)((nt * 16 + bRowInPair) * 128 + kk * 32) + bKH);
                    u32 bh0, bh1, bh2, bh3, bm0, bm1, bm2, bm3;
                    ldsm4(bh0, bh1, bh2, bh3, Bh + bAddr);
                    ldsm4(bm0, bm1, bm2, bm3, Bm + bAddr);
                    float* dA = d2 + (ng * 4 + nt * 2) * 4;
                    float* dB = dA + 4;
                    mma_bf16(dA, af[kk][0], af[kk][1], af[kk][2], af[kk][3], bh0, bh1);
                    mma_bf16(dA, af[kk][4], af[kk][5], af[kk][6], af[kk][7], bh0, bh1);
                    mma_bf16(dA, af[kk][0], af[kk][1], af[kk][2], af[kk][3], bm0, bm1);
                    mma_bf16(dB, af[kk][0], af[kk][1], af[kk][2], af[kk][3], bh2, bh3);
                    mma_bf16(dB, af[kk][4], af[kk][5], af[kk][6], af[kk][7], bh2, bh3);
                    mma_bf16(dB, af[kk][0], af[kk][1], af[kk][2], af[kk][3], bm2, bm3);
                }
            }
            __syncthreads();
        }
    }

    float acc0 = 0.0f, acc1 = 0.0f;
    #pragma unroll
    for (int ti = 0; ti < 16; ti++) {
        int c0 = ti * 8 + tig * 2;
        float w0 = w3s[c0], w1v = w3s[c0 + 1];
        float bb0 = b2s[c0], bb1 = b2s[c0 + 1];
        acc0 = fmaf(geluf(d2[ti * 4 + 0] + bb0), w0, acc0);
        acc0 = fmaf(geluf(d2[ti * 4 + 1] + bb1), w1v, acc0);
        acc1 = fmaf(geluf(d2[ti * 4 + 2] + bb0), w0, acc1);
        acc1 = fmaf(geluf(d2[ti * 4 + 3] + bb1), w1v, acc1);
    }
    acc0 += __shfl_down_sync(0xffffffffu, acc0, 2, 4);
    acc0 += __shfl_down_sync(0xffffffffu, acc0, 1, 4);
    acc1 += __shfl_down_sync(0xffffffffu, acc1, 2, 4);
    acc1 += __shfl_down_sync(0xffffffffu, acc1, 1, 4);
    if (tig == 0) {
        float b3v = b3[0];
        out[base + wbase + g] = acc0 + b3v;
        out[base + wbase + g + 8] = acc1 + b3v;
    }
}

// ---------------- launch ----------------
extern "C" void kernel_launch(void* const* d_in, const int* in_sizes, int n_in,
                              void* d_out, int out_size) {
    const float* feat   = (const float*)d_in[0];
    const float* enc_w1 = (const float*)d_in[1];
    const float* enc_b1 = (const float*)d_in[2];
    const float* enc_g1 = (const float*)d_in[3];
    const float* enc_be1= (const float*)d_in[4];
    const float* enc_w2 = (const float*)d_in[5];
    const float* enc_b2 = (const float*)d_in[6];
    const float* enc_g2 = (const float*)d_in[7];
    const float* enc_be2= (const float*)d_in[8];
    const float* watt1  = (const float*)d_in[9];
    const float* batt1  = (const float*)d_in[10];
    const float* watt2  = (const float*)d_in[11];
    const float* batt2  = (const float*)d_in[12];
    const float* dec_w1 = (const float*)d_in[13];
    const float* dec_b1 = (const float*)d_in[14];
    const float* dec_w2 = (const float*)d_in[15];
    const float* dec_b2 = (const float*)d_in[16];
    const float* dec_w3 = (const float*)d_in[17];
    const float* dec_b3 = (const float*)d_in[18];
    const int*   src    = (const int*)d_in[19];
    const int*   dst    = (const int*)d_in[20];
    float* out = (float*)d_out;

    {
        long n = (long)BB * NN * DD;
        int blocks = (int)((n + 255) / 256);
        k_zero_node_and_counts<<<blocks, 256>>>();
    }

    k_prep<<<(256 * 384 + 255) / 256, 256>>>(dec_w1, dec_w2, enc_w2);

    k_count_deg<<<(EE + 255) / 256, 256>>>(src, dst);

    k_enc<<<(BB * EE) / 64, 128>>>(feat, enc_w1, enc_b1, enc_g1, enc_be1,
                                   enc_b2, enc_g2, enc_be2);

    k_scan<<<1, 1024>>>();
    k_scatter<<<(2 * EE + 255) / 256, 256>>>(src, dst);

    k_edot<<<1480, 256>>>(watt1, watt2);

    k_mp<<<dim3(NN, BB), DD>>>(watt1, batt1, 0);
    k_mp<<<dim3(NN, BB), DD>>>(watt2, batt2, 1);

    k_dec1<<<(BB * EE) / 128, 256>>>(src, dst, dec_b1);
    k_dec2<<<(BB * EE) / 128, 256>>>(dec_b2, dec_w3, dec_b3, out);
}